// round 3
// baseline (speedup 1.0000x reference)
#include <cuda_runtime.h>
#include <math.h>

#define BATCH 2048
#define NEXP 8
#define NCLS 100
#define HID 1024
#define GATEH 2048
#define FEAT 2048

typedef unsigned long long u64;

// ---------------- scratch (device globals; no allocation allowed) -------------
__device__ float g_convout[134217728];            // max conv output: [2048,64,32,32]
__device__ float g_poolA[33554432];
__device__ float g_poolB[16777216];               // final f [2048,512,2,2]
__device__ float g_hid[BATCH * GATEH];
__device__ float g_clean[BATCH * NEXP];
__device__ float g_rawstd[BATCH * NEXP];
__device__ float g_gates[BATCH * NEXP];
__device__ float g_prob[BATCH * NEXP];
__device__ float g_eh[(size_t)NEXP * BATCH * HID];
__device__ float g_eh2[(size_t)NEXP * BATCH * (HID / 2)];
__device__ float g_eo[(size_t)NEXP * BATCH * NCLS];
__device__ float g_imp[NEXP];
__device__ float g_load[NEXP];
__device__ int   g_rowlist[NEXP * BATCH];
__device__ int   g_cnt[NEXP];
__device__ int   g_rowslot[BATCH * 2];
__device__ float g_slotgate[NEXP * BATCH];

// ---------------- f32x2 helpers (packed dual-FMA, full-rate fp32) -------------
__device__ __forceinline__ u64 dupf(float v) {
  u64 r; asm("mov.b64 %0, {%1, %1};" : "=l"(r) : "f"(v)); return r;
}
__device__ __forceinline__ void fma2(u64& d, u64 a, u64 b) {
  asm("fma.rn.f32x2 %0, %1, %2, %0;" : "+l"(d) : "l"(a), "l"(b));
}
__device__ __forceinline__ float2 unp(u64 v) {
  float2 f; asm("mov.b64 {%0, %1}, %2;" : "=f"(f.x), "=f"(f.y) : "l"(v)); return f;
}

// =================== dense GEMM 128x64x16, f32x2 inner loop ===================
// C[m,n] = act(A[m,:] @ B[:,n] + bias[n]); optional row gather + per-z count.
#define DBM 128
#define DBN 64
#define DBK 16

__global__ __launch_bounds__(256) void gemm_f2(
    const float* __restrict__ A, const float* __restrict__ B,
    const float* __restrict__ bias, float* __restrict__ C,
    int M, int N, int K, int relu,
    long long sA, long long sB, long long sBias, long long sC,
    const int* __restrict__ rowlist, const int* __restrict__ cnt) {
  const int z = blockIdx.z;
  const int Mz = cnt ? cnt[z] : M;
  const int m0 = blockIdx.y * DBM;
  if (m0 >= Mz) return;
  const int n0 = blockIdx.x * DBN;

  const float* Ab = A + (long long)z * sA;
  const float* Bb = B + (long long)z * sB;
  const float* biasb = bias + (long long)z * sBias;
  float* Cb = C + (long long)z * sC;
  const int* rl = rowlist ? rowlist + z * BATCH : (const int*)0;

  __shared__ float As[DBK][DBM + 2];   // stride 130 floats (8B-multiple)
  __shared__ float Bs[DBK][DBN + 4];   // stride 68 floats (16B-multiple)

  u64 acc[4][4];
#pragma unroll
  for (int p = 0; p < 4; p++)
#pragma unroll
    for (int j = 0; j < 4; j++) acc[p][j] = 0ull;

  const int tid = threadIdx.x;
  const int tx = tid & 15, ty = tid >> 4;

  // A loader: 2 float4 per thread
  int rowA[2], kqA[2];
  size_t abase[2];
#pragma unroll
  for (int i = 0; i < 2; i++) {
    int v = tid + i * 256;
    rowA[i] = v >> 2;
    kqA[i] = v & 3;
    int gm = m0 + rowA[i];
    int ridx = rl ? ((gm < Mz) ? rl[gm] : 0) : gm;
    abase[i] = (size_t)ridx * K + kqA[i] * 4;
  }
  const int kb = tid >> 4, nb = (tid & 15) * 4;

  for (int k0 = 0; k0 < K; k0 += DBK) {
#pragma unroll
    for (int i = 0; i < 2; i++) {
      float4 a4 = *(const float4*)&Ab[abase[i] + k0];
      int kk = kqA[i] * 4;
      As[kk + 0][rowA[i]] = a4.x;
      As[kk + 1][rowA[i]] = a4.y;
      As[kk + 2][rowA[i]] = a4.z;
      As[kk + 3][rowA[i]] = a4.w;
    }
    {
      float4 b4;
      size_t bo = (size_t)(k0 + kb) * N + n0 + nb;
      if (n0 + nb + 3 < N) {
        b4 = *(const float4*)&Bb[bo];
      } else {
        b4.x = (n0 + nb + 0 < N) ? Bb[bo + 0] : 0.f;
        b4.y = (n0 + nb + 1 < N) ? Bb[bo + 1] : 0.f;
        b4.z = (n0 + nb + 2 < N) ? Bb[bo + 2] : 0.f;
        b4.w = (n0 + nb + 3 < N) ? Bb[bo + 3] : 0.f;
      }
      *(float4*)&Bs[kb][nb] = b4;
    }
    __syncthreads();
#pragma unroll
    for (int kk = 0; kk < DBK; kk++) {
      const u64* arow = (const u64*)&As[kk][0];
      u64 a0 = arow[ty * 4 + 0], a1 = arow[ty * 4 + 1];
      u64 a2 = arow[ty * 4 + 2], a3 = arow[ty * 4 + 3];
      float4 b4 = *(const float4*)&Bs[kk][tx * 4];
      u64 b0 = dupf(b4.x), b1 = dupf(b4.y), b2 = dupf(b4.z), b3 = dupf(b4.w);
      fma2(acc[0][0], a0, b0); fma2(acc[0][1], a0, b1);
      fma2(acc[0][2], a0, b2); fma2(acc[0][3], a0, b3);
      fma2(acc[1][0], a1, b0); fma2(acc[1][1], a1, b1);
      fma2(acc[1][2], a1, b2); fma2(acc[1][3], a1, b3);
      fma2(acc[2][0], a2, b0); fma2(acc[2][1], a2, b1);
      fma2(acc[2][2], a2, b2); fma2(acc[2][3], a2, b3);
      fma2(acc[3][0], a3, b0); fma2(acc[3][1], a3, b1);
      fma2(acc[3][2], a3, b2); fma2(acc[3][3], a3, b3);
    }
    __syncthreads();
  }

#pragma unroll
  for (int p = 0; p < 4; p++) {
    int mlo = m0 + ty * 8 + 2 * p;
#pragma unroll
    for (int j = 0; j < 4; j++) {
      int n = n0 + tx * 4 + j;
      if (n >= N) continue;
      float2 v = unp(acc[p][j]);
      float bsv = biasb[n];
      if (mlo < Mz) {
        float r = v.x + bsv;
        if (relu) r = fmaxf(r, 0.f);
        Cb[(size_t)mlo * N + n] = r;
      }
      if (mlo + 1 < Mz) {
        float r = v.y + bsv;
        if (relu) r = fmaxf(r, 0.f);
        Cb[(size_t)(mlo + 1) * N + n] = r;
      }
    }
  }
}

// ============ implicit-im2col conv 64x128x16 + bias/BN/ReLU, f32x2 ============
#define CBM 64
#define CBN 128
#define CBK 16

__global__ __launch_bounds__(256) void conv_f2(
    const float* __restrict__ in, const float* __restrict__ w,
    const float* __restrict__ cb, const float* __restrict__ gam,
    const float* __restrict__ bet, float* __restrict__ out,
    int Cin, int Cout, int H, int logW, int logHW) {
  const int HW = 1 << logHW;
  const int W = 1 << logW;
  const int Ktot = Cin * 9;
  const int n0 = blockIdx.x * CBN;
  const int m0 = blockIdx.y * CBM;

  __shared__ float As[CBK][CBM + 2];   // stride 66 floats (8B-mult)
  __shared__ float Bs[CBK][CBN + 4];

  u64 acc[4][4];
#pragma unroll
  for (int p = 0; p < 4; p++)
#pragma unroll
    for (int j = 0; j < 4; j++) acc[p][j] = 0ull;

  const int tid = threadIdx.x;
  const int tx = tid & 31, ty = tid >> 5;
  const int kB = tid >> 4, nb8 = (tid & 15) * 8;

  for (int k0 = 0; k0 < Ktot; k0 += CBK) {
    // A (weights): 4 scalar guarded loads per thread
#pragma unroll
    for (int i = 0; i < 4; i++) {
      int l = tid + i * 256;
      int k = l & 15, m = l >> 4;
      int gk = k0 + k;
      As[k][m] = (gk < Ktot) ? w[(m0 + m) * Ktot + gk] : 0.f;
    }
    // B (im2col gather): one k per thread, 8 consecutive n
    {
      int gk = k0 + kB;
      int ci = 0, ky = 0, kx = 0;
      bool kvalid = gk < Ktot;
      if (kvalid) {
        ci = gk / 9;
        int r = gk - ci * 9;
        ky = r / 3;
        kx = r - ky * 3;
      }
      const float* inp = in + (size_t)ci * HW;  // offset within image
#pragma unroll
      for (int jj = 0; jj < 8; jj++) {
        int gn = n0 + nb8 + jj;
        float v = 0.f;
        if (kvalid) {
          int b = gn >> logHW;
          int pos = gn & (HW - 1);
          int y = pos >> logW, x = pos & (W - 1);
          int iy = y + ky - 1, ix = x + kx - 1;
          if ((unsigned)iy < (unsigned)H && (unsigned)ix < (unsigned)H)
            v = inp[((size_t)b * Cin << logHW) + (iy << logW) + ix];
        }
        Bs[kB][nb8 + jj] = v;
      }
    }
    __syncthreads();
#pragma unroll
    for (int kk = 0; kk < CBK; kk++) {
      const u64* arow = (const u64*)&As[kk][0];
      u64 a0 = arow[ty * 4 + 0], a1 = arow[ty * 4 + 1];
      u64 a2 = arow[ty * 4 + 2], a3 = arow[ty * 4 + 3];
      float4 b4 = *(const float4*)&Bs[kk][tx * 4];
      u64 b0 = dupf(b4.x), b1 = dupf(b4.y), b2 = dupf(b4.z), b3 = dupf(b4.w);
      fma2(acc[0][0], a0, b0); fma2(acc[0][1], a0, b1);
      fma2(acc[0][2], a0, b2); fma2(acc[0][3], a0, b3);
      fma2(acc[1][0], a1, b0); fma2(acc[1][1], a1, b1);
      fma2(acc[1][2], a1, b2); fma2(acc[1][3], a1, b3);
      fma2(acc[2][0], a2, b0); fma2(acc[2][1], a2, b1);
      fma2(acc[2][2], a2, b2); fma2(acc[2][3], a2, b3);
      fma2(acc[3][0], a3, b0); fma2(acc[3][1], a3, b1);
      fma2(acc[3][2], a3, b2); fma2(acc[3][3], a3, b3);
    }
    __syncthreads();
  }

  const float rs = rsqrtf(1.00001f);
#pragma unroll
  for (int p = 0; p < 4; p++) {
    int mlo = m0 + ty * 8 + 2 * p;
    float sc0 = gam[mlo] * rs, cb0 = cb[mlo], be0 = bet[mlo];
    float sc1 = gam[mlo + 1] * rs, cb1v = cb[mlo + 1], be1v = bet[mlo + 1];
#pragma unroll
    for (int j = 0; j < 4; j++) {
      int gn = n0 + tx * 4 + j;
      int b = gn >> logHW;
      int pos = gn & (HW - 1);
      float2 v = unp(acc[p][j]);
      float r0 = fmaxf((v.x + cb0) * sc0 + be0, 0.f);
      float r1 = fmaxf((v.y + cb1v) * sc1 + be1v, 0.f);
      out[((size_t)(b * Cout + mlo) << logHW) + pos] = r0;
      out[((size_t)(b * Cout + mlo + 1) << logHW) + pos] = r1;
    }
  }
}

// ---------------- 2x2 max pool (stride 2) ----------------
__global__ void pool_kernel(const float* __restrict__ in, float* __restrict__ out,
                            int C, int H) {
  int Hp = H >> 1;
  int total = BATCH * C * Hp * Hp;
  int idx = blockIdx.x * blockDim.x + threadIdx.x;
  if (idx >= total) return;
  int px = idx % Hp;
  int t = idx / Hp;
  int py = t % Hp; t /= Hp;
  int c = t % C;
  int b = t / C;
  const float* p = in + ((size_t)(b * C + c) * H + py * 2) * H + px * 2;
  out[idx] = fmaxf(fmaxf(p[0], p[1]), fmaxf(p[H], p[H + 1]));
}

// ---------------- noisy top-k gating (per row) ----------------
__global__ void gating_kernel(const float* __restrict__ clean,
                              const float* __restrict__ rawstd,
                              const float* __restrict__ noise,
                              float* __restrict__ gates, float* __restrict__ prob) {
  int b = blockIdx.x * blockDim.x + threadIdx.x;
  if (b >= BATCH) return;
  float c[NEXP], sd[NEXP], nz[NEXP];
#pragma unroll
  for (int e = 0; e < NEXP; e++) {
    c[e] = clean[b * NEXP + e];
    float rsv = rawstd[b * NEXP + e];
    float sp = (rsv > 20.f) ? rsv : log1pf(expf(rsv));
    sd[e] = sp + 0.01f;
    nz[e] = c[e] + noise[b * NEXP + e] * sd[e];
  }
  int i0 = 0; float v0 = nz[0];
#pragma unroll
  for (int e = 1; e < NEXP; e++) if (nz[e] > v0) { v0 = nz[e]; i0 = e; }
  int i1 = -1; float v1 = -1e30f;
#pragma unroll
  for (int e = 0; e < NEXP; e++) if (e != i0 && nz[e] > v1) { v1 = nz[e]; i1 = e; }
  float v2 = -1e30f;
#pragma unroll
  for (int e = 0; e < NEXP; e++) if (e != i0 && e != i1 && nz[e] > v2) v2 = nz[e];

  float e1 = expf(v1 - v0);
  float inv = 1.f / (1.f + e1);
  const float kInvSqrt2 = 0.70710678118654752440f;
#pragma unroll
  for (int e = 0; e < NEXP; e++) {
    float g = (e == i0) ? inv : ((e == i1) ? e1 * inv : 0.f);
    gates[b * NEXP + e] = g;
    float th = (nz[e] > v2) ? v2 : v1;
    float z = (c[e] - th) / sd[e];
    prob[b * NEXP + e] = 0.5f * (1.f + erff(z * kInvSqrt2));
  }
}

// -------- deterministic dispatch build (1 block, warp per expert) --------
__global__ void build_dispatch(const float* __restrict__ gates,
                               int* __restrict__ rowlist, int* __restrict__ cnt,
                               int* __restrict__ rowslot,
                               float* __restrict__ slotgate) {
  int w = threadIdx.x >> 5;
  int lane = threadIdx.x & 31;
  int c = 0;
  for (int base = 0; base < BATCH; base += 32) {
    int b = base + lane;
    float g = gates[b * NEXP + w];
    unsigned mask = __ballot_sync(0xffffffffu, g > 0.f);
    if (g > 0.f) {
      int pos = c + __popc(mask & ((1u << lane) - 1u));
      int slot = w * BATCH + pos;
      rowlist[slot] = b;
      slotgate[slot] = g;
      int m8 = 0;
#pragma unroll
      for (int e = 0; e < NEXP; e++) m8 |= (gates[b * NEXP + e] > 0.f) ? (1 << e) : 0;
      int j = __popc(m8 & ((1 << w) - 1));
      rowslot[b * 2 + j] = slot;
    }
    c += __popc(mask);
  }
  if (lane == 0) cnt[w] = c;
}

// ---------------- deterministic per-expert reductions ----------------
__global__ void moe_reduce_kernel(const float* __restrict__ gates,
                                  const float* __restrict__ prob,
                                  float* __restrict__ imp, float* __restrict__ loadv) {
  int e = blockIdx.x;
  int t = threadIdx.x;
  __shared__ float s1[256], s2[256];
  float a = 0.f, b = 0.f;
  for (int i = t; i < BATCH; i += 256) {
    a += gates[i * NEXP + e];
    b += prob[i * NEXP + e];
  }
  s1[t] = a; s2[t] = b;
  __syncthreads();
  for (int s = 128; s > 0; s >>= 1) {
    if (t < s) { s1[t] += s1[t + s]; s2[t] += s2[t + s]; }
    __syncthreads();
  }
  if (t == 0) { imp[e] = s1[0]; loadv[e] = s2[0]; }
}

__global__ void loss_kernel(const float* __restrict__ imp,
                            const float* __restrict__ loadv,
                            float* __restrict__ out) {
  float m1 = 0.f, m2 = 0.f;
  for (int e = 0; e < NEXP; e++) { m1 += imp[e]; m2 += loadv[e]; }
  m1 *= 0.125f; m2 *= 0.125f;
  float v1 = 0.f, v2 = 0.f;
  for (int e = 0; e < NEXP; e++) {
    float d1 = imp[e] - m1; v1 += d1 * d1;
    float d2 = loadv[e] - m2; v2 += d2 * d2;
  }
  v1 /= 7.f; v2 /= 7.f;
  out[0] = v1 / (m1 * m1 + 1e-10f) + v2 / (m2 * m2 + 1e-10f);
}

// ------------- slot-based combine: y[b,c] = g0*eo[s0,c]+g1*eo[s1,c] ----------
__global__ void combine2_kernel(const int* __restrict__ rowslot,
                                const float* __restrict__ slotgate,
                                const float* __restrict__ eo,
                                float* __restrict__ y) {
  int idx = blockIdx.x * blockDim.x + threadIdx.x;
  if (idx >= BATCH * NCLS) return;
  int b = idx / NCLS;
  int c = idx - b * NCLS;
  int s0 = rowslot[b * 2 + 0], s1 = rowslot[b * 2 + 1];
  y[idx] = slotgate[s0] * eo[(size_t)s0 * NCLS + c] +
           slotgate[s1] * eo[(size_t)s1 * NCLS + c];
}

// ================================ launch ======================================
extern "C" void kernel_launch(void* const* d_in, const int* in_sizes, int n_in,
                              void* d_out, int out_size) {
  const float* x    = (const float*)d_in[0];
  const float* noise= (const float*)d_in[1];
  const float* cw1 = (const float*)d_in[2],  *cb1 = (const float*)d_in[3];
  const float* g1  = (const float*)d_in[4],  *be1 = (const float*)d_in[5];
  const float* cw2 = (const float*)d_in[6],  *cb2 = (const float*)d_in[7];
  const float* g2  = (const float*)d_in[8],  *be2 = (const float*)d_in[9];
  const float* cw3 = (const float*)d_in[10], *cb3 = (const float*)d_in[11];
  const float* g3  = (const float*)d_in[12], *be3 = (const float*)d_in[13];
  const float* cw4 = (const float*)d_in[14], *cb4 = (const float*)d_in[15];
  const float* g4  = (const float*)d_in[16], *be4 = (const float*)d_in[17];
  const float* wg1 = (const float*)d_in[18], *wg1b= (const float*)d_in[19];
  const float* wg2 = (const float*)d_in[20], *wg2b= (const float*)d_in[21];
  const float* wn1 = (const float*)d_in[22], *wn1b= (const float*)d_in[23];
  const float* wn2 = (const float*)d_in[24], *wn2b= (const float*)d_in[25];
  const float* eW1 = (const float*)d_in[26], *eb1 = (const float*)d_in[27];
  const float* eW2 = (const float*)d_in[28], *eb2 = (const float*)d_in[29];
  const float* eW3 = (const float*)d_in[30], *eb3 = (const float*)d_in[31];

  float *convout, *poolA, *poolB, *hid, *clean, *rawstd, *gates, *prob;
  float *eh, *eh2, *eo, *imp, *loadv, *slotgate;
  int *rowlist, *cnt, *rowslot;
  cudaGetSymbolAddress((void**)&convout, g_convout);
  cudaGetSymbolAddress((void**)&poolA, g_poolA);
  cudaGetSymbolAddress((void**)&poolB, g_poolB);
  cudaGetSymbolAddress((void**)&hid, g_hid);
  cudaGetSymbolAddress((void**)&clean, g_clean);
  cudaGetSymbolAddress((void**)&rawstd, g_rawstd);
  cudaGetSymbolAddress((void**)&gates, g_gates);
  cudaGetSymbolAddress((void**)&prob, g_prob);
  cudaGetSymbolAddress((void**)&eh, g_eh);
  cudaGetSymbolAddress((void**)&eh2, g_eh2);
  cudaGetSymbolAddress((void**)&eo, g_eo);
  cudaGetSymbolAddress((void**)&imp, g_imp);
  cudaGetSymbolAddress((void**)&loadv, g_load);
  cudaGetSymbolAddress((void**)&rowlist, g_rowlist);
  cudaGetSymbolAddress((void**)&cnt, g_cnt);
  cudaGetSymbolAddress((void**)&rowslot, g_rowslot);
  cudaGetSymbolAddress((void**)&slotgate, g_slotgate);

  float* out = (float*)d_out;

  // ---- conv stack ----
  conv_f2<<<dim3(BATCH * 1024 / CBN, 1), 256>>>(x, cw1, cb1, g1, be1, convout, 3, 64, 32, 5, 10);
  pool_kernel<<<(BATCH * 64 * 256 + 255) / 256, 256>>>(convout, poolA, 64, 32);

  conv_f2<<<dim3(BATCH * 256 / CBN, 2), 256>>>(poolA, cw2, cb2, g2, be2, convout, 64, 128, 16, 4, 8);
  pool_kernel<<<(BATCH * 128 * 64 + 255) / 256, 256>>>(convout, poolB, 128, 16);

  conv_f2<<<dim3(BATCH * 64 / CBN, 4), 256>>>(poolB, cw3, cb3, g3, be3, convout, 128, 256, 8, 3, 6);
  pool_kernel<<<(BATCH * 256 * 16 + 255) / 256, 256>>>(convout, poolA, 256, 8);

  conv_f2<<<dim3(BATCH * 16 / CBN, 8), 256>>>(poolA, cw4, cb4, g4, be4, convout, 256, 512, 4, 2, 4);
  pool_kernel<<<(BATCH * 512 * 4 + 255) / 256, 256>>>(convout, poolB, 512, 4);

  const float* f = poolB;  // [2048, 2048]

  // ---- gating nets ----
  gemm_f2<<<dim3(GATEH / DBN, BATCH / DBM, 1), 256>>>(
      f, wg1, wg1b, hid, BATCH, GATEH, FEAT, 1, 0, 0, 0, 0, 0, 0);
  gemm_f2<<<dim3(1, BATCH / DBM, 1), 256>>>(
      hid, wg2, wg2b, clean, BATCH, NEXP, GATEH, 0, 0, 0, 0, 0, 0, 0);
  gemm_f2<<<dim3(GATEH / DBN, BATCH / DBM, 1), 256>>>(
      f, wn1, wn1b, hid, BATCH, GATEH, FEAT, 1, 0, 0, 0, 0, 0, 0);
  gemm_f2<<<dim3(1, BATCH / DBM, 1), 256>>>(
      hid, wn2, wn2b, rawstd, BATCH, NEXP, GATEH, 0, 0, 0, 0, 0, 0, 0);

  gating_kernel<<<BATCH / 256, 256>>>(clean, rawstd, noise, gates, prob);
  build_dispatch<<<1, 256>>>(gates, rowlist, cnt, rowslot, slotgate);
  moe_reduce_kernel<<<NEXP, 256>>>(gates, prob, imp, loadv);

  // ---- sparse experts (capacity grid, early-exit on cnt) ----
  gemm_f2<<<dim3(HID / DBN, BATCH / DBM, NEXP), 256>>>(
      f, eW1, eb1, eh, BATCH, HID, FEAT, 1,
      0, (long long)FEAT * HID, HID, (long long)BATCH * HID, rowlist, cnt);
  gemm_f2<<<dim3((HID / 2) / DBN, BATCH / DBM, NEXP), 256>>>(
      eh, eW2, eb2, eh2, BATCH, HID / 2, HID, 1,
      (long long)BATCH * HID, (long long)HID * (HID / 2), HID / 2,
      (long long)BATCH * (HID / 2), 0, cnt);
  gemm_f2<<<dim3((NCLS + DBN - 1) / DBN, BATCH / DBM, NEXP), 256>>>(
      eh2, eW3, eb3, eo, BATCH, NCLS, HID / 2, 0,
      (long long)BATCH * (HID / 2), (long long)(HID / 2) * NCLS, NCLS,
      (long long)BATCH * NCLS, 0, cnt);

  // ---- outputs ----
  combine2_kernel<<<(BATCH * NCLS + 255) / 256, 256>>>(rowslot, slotgate, eo, out);
  if (out_size >= BATCH * NCLS + 1)
    loss_kernel<<<1, 1>>>(imp, loadv, out + BATCH * NCLS);
}

// round 5
// speedup vs baseline: 1.2992x; 1.2992x over previous
#include <cuda_runtime.h>
#include <math.h>
#include <stdint.h>

#define BATCH 2048
#define NEXP 8
#define NCLS 100
#define HID 1024
#define GATEH 2048
#define FEAT 2048

typedef unsigned long long u64;

// Does this compilation pass have sm_10x accelerated features (tcgen05)?
#if defined(__CUDA_ARCH_FEAT_SM103_ALL) || defined(__CUDA_ARCH_FEAT_SM100_ALL) || \
    defined(__CUDA_ARCH_FEAT_SM101_ALL) ||                                        \
    (defined(__CUDA_ARCH_SPECIFIC__) && (__CUDA_ARCH_SPECIFIC__ > 0))
#define HAS_TC 1
#else
#define HAS_TC 0
#endif

// ---------------- scratch (device globals; no allocation allowed) -------------
__device__ float g_convout[134217728];
__device__ float g_poolA[33554432];
__device__ float g_poolB[16777216];
__device__ float g_hid[BATCH * GATEH];
__device__ float g_clean[BATCH * NEXP];
__device__ float g_rawstd[BATCH * NEXP];
__device__ float g_gates[BATCH * NEXP];
__device__ float g_prob[BATCH * NEXP];
__device__ float g_eh[(size_t)NEXP * BATCH * HID];
__device__ float g_eh2[(size_t)NEXP * BATCH * (HID / 2)];
__device__ float g_eo[(size_t)NEXP * BATCH * NCLS];
__device__ float g_imp[NEXP];
__device__ float g_load[NEXP];
__device__ int   g_rowlist[NEXP * BATCH];
__device__ int   g_cnt[NEXP];
__device__ int   g_rowslot[BATCH * 2];
__device__ float g_slotgate[NEXP * BATCH];

// ========================== common helpers ====================================
__device__ __forceinline__ uint32_t smem_u32(const void* p) {
  uint32_t a;
  asm("{ .reg .u64 t; cvta.to.shared.u64 t, %1; cvt.u32.u64 %0, t; }"
      : "=r"(a) : "l"(p));
  return a;
}

#define SW128(o) ((o) ^ (((o) >> 3) & 0x70))

__device__ __forceinline__ u64 dupf(float v) {
  u64 r; asm("mov.b64 %0, {%1, %1};" : "=l"(r) : "f"(v)); return r;
}
__device__ __forceinline__ void fma2(u64& d, u64 a, u64 b) {
  asm("fma.rn.f32x2 %0, %1, %2, %0;" : "+l"(d) : "l"(a), "l"(b));
}
__device__ __forceinline__ float2 unp(u64 v) {
  float2 f; asm("mov.b64 {%0, %1}, %2;" : "=f"(f.x), "=f"(f.y) : "l"(v)); return f;
}

#if HAS_TC
// ---- tcgen05 PTX wrappers (only in accelerated pass) ----
#define TC_ALLOC(sa, n) \
  asm volatile("tcgen05.alloc.cta_group::1.sync.aligned.shared::cta.b32 [%0], %1;" \
               :: "r"(sa), "r"(n) : "memory")
#define TC_DEALLOC(t, n) \
  asm volatile("tcgen05.dealloc.cta_group::1.sync.aligned.b32 %0, %1;" :: "r"(t), "r"(n))
#define TC_RELINQ() \
  asm volatile("tcgen05.relinquish_alloc_permit.cta_group::1.sync.aligned;")
#define TC_COMMIT(mb) \
  asm volatile("tcgen05.commit.cta_group::1.mbarrier::arrive::one.shared::cluster.b64 [%0];" \
               :: "r"(mb) : "memory")
#define TC_FENCE_AFTER()  asm volatile("tcgen05.fence::after_thread_sync;" ::: "memory")
#define TC_FENCE_BEFORE() asm volatile("tcgen05.fence::before_thread_sync;" ::: "memory")
#define TC_WAIT_LD()      asm volatile("tcgen05.wait::ld.sync.aligned;" ::: "memory")
#define FENCE_ASYNC()     asm volatile("fence.proxy.async.shared::cta;" ::: "memory")
#define MB_INIT(mb, n) \
  asm volatile("mbarrier.init.shared.b64 [%0], %1;" :: "r"(mb), "r"(n) : "memory")

#define MB_WAIT(mbar_addr, ph) do { \
  uint32_t _mb = (uint32_t)(mbar_addr); \
  uint32_t _p = (uint32_t)(ph); \
  asm volatile( \
      "{\n\t.reg .pred P1;\n\t" \
      "WAIT_LOOP_%=:\n\t" \
      "mbarrier.try_wait.parity.acquire.cta.shared::cta.b64 P1, [%0], %1, 0x989680;\n\t" \
      "@P1 bra.uni WAIT_DONE_%=;\n\t" \
      "bra.uni WAIT_LOOP_%=;\n\t" \
      "WAIT_DONE_%=:\n\t}" \
      :: "r"(_mb), "r"(_p) : "memory"); \
} while (0)

#define TC_LD_X32(r, ta) \
  asm volatile( \
      "tcgen05.ld.sync.aligned.32x32b.x32.b32 " \
      "{%0, %1, %2, %3, %4, %5, %6, %7, " \
      " %8, %9, %10, %11, %12, %13, %14, %15, " \
      " %16, %17, %18, %19, %20, %21, %22, %23, " \
      " %24, %25, %26, %27, %28, %29, %30, %31}, [%32];" \
      : "=r"((r)[0]),  "=r"((r)[1]),  "=r"((r)[2]),  "=r"((r)[3]), \
        "=r"((r)[4]),  "=r"((r)[5]),  "=r"((r)[6]),  "=r"((r)[7]), \
        "=r"((r)[8]),  "=r"((r)[9]),  "=r"((r)[10]), "=r"((r)[11]), \
        "=r"((r)[12]), "=r"((r)[13]), "=r"((r)[14]), "=r"((r)[15]), \
        "=r"((r)[16]), "=r"((r)[17]), "=r"((r)[18]), "=r"((r)[19]), \
        "=r"((r)[20]), "=r"((r)[21]), "=r"((r)[22]), "=r"((r)[23]), \
        "=r"((r)[24]), "=r"((r)[25]), "=r"((r)[26]), "=r"((r)[27]), \
        "=r"((r)[28]), "=r"((r)[29]), "=r"((r)[30]), "=r"((r)[31]) \
      : "r"(ta))

__device__ __forceinline__ uint64_t mkdesc(uint32_t addr) {
  return ((uint64_t)2 << 61) | ((uint64_t)1 << 46) | ((uint64_t)64 << 32) |
         ((uint64_t)1 << 16) | ((addr >> 4) & 0x3FFF);
}

__device__ __forceinline__ void mma_tf32(uint32_t d, uint64_t ad, uint64_t bd,
                                         uint32_t idesc, uint32_t en) {
  asm volatile(
      "{\n\t.reg .pred p;\n\tsetp.ne.u32 p, %5, 0;\n\t"
      "tcgen05.mma.cta_group::1.kind::tf32 [%0], %1, %2, %3, {%4, %4, %4, %4}, p;\n\t}"
      :: "r"(d), "l"(ad), "l"(bd), "r"(idesc), "r"(0u), "r"(en) : "memory");
}
#endif  // HAS_TC

__device__ __forceinline__ void tf32split(float x, uint32_t& h, uint32_t& l) {
  uint32_t hb;
  asm("cvt.rna.tf32.f32 %0, %1;" : "=r"(hb) : "f"(x));
  float lf = x - __uint_as_float(hb);
  uint32_t lb;
  asm("cvt.rna.tf32.f32 %0, %1;" : "=r"(lb) : "f"(lf));
  h = hb; l = lb;
}

__device__ __forceinline__ void sts128u(uint32_t addr, uint32_t a, uint32_t b,
                                        uint32_t c, uint32_t d) {
  asm volatile("st.shared.v4.b32 [%0], {%1, %2, %3, %4};"
               :: "r"(addr), "r"(a), "r"(b), "r"(c), "r"(d) : "memory");
}
__device__ __forceinline__ void sts32u(uint32_t addr, uint32_t v) {
  asm volatile("st.shared.b32 [%0], %1;" :: "r"(addr), "r"(v) : "memory");
}

// ================= unified GEMM (128x128 tile), tcgen05 or f32x2 fallback =====
#define TCM 128
#define TCN 128
#define TCK 32
#define TC_TILE 16384
#define TC_STAGE (4 * TC_TILE)
#define SOFF_MBAR 16
#define SOFF_TILES 1024
#define SMEM_TC (SOFF_TILES + 2 * TC_STAGE)

__global__ void __launch_bounds__(256, 1) tc_gemm(
    const float* __restrict__ A, const float* __restrict__ Bm,
    const float* __restrict__ bias, float* __restrict__ C,
    int M, int N, int K, int relu,
    long long sA, long long sB, long long sBias, long long sC,
    const int* __restrict__ rowlist, const int* __restrict__ cnt,
    int conv_mode, int Cin, int Himg, int logW, int logHW,
    const float* __restrict__ gam, const float* __restrict__ bet) {
  extern __shared__ char smem[];
  const int z = blockIdx.z;
  const int Mz = cnt ? cnt[z] : M;
  const int m0 = blockIdx.y * TCM;
  if (m0 >= Mz) return;
  const int n0 = blockIdx.x * TCN;

  const float* Ab = A + (long long)z * sA;
  const float* Bb = Bm + (long long)z * sB;
  const float* biasb = bias + (long long)z * sBias;
  float* Cb = C + (long long)z * sC;
  const int* rl = rowlist ? rowlist + z * BATCH : (const int*)0;

  const int tid = threadIdx.x;
  const int wid = tid >> 5, lane = tid & 31;

  // A staging assignment: thread -> (row, k-half)
  const int arow = tid >> 1;
  const int ahalf = (tid & 1) * 16;
  long long aidx;
  {
    int gm = m0 + arow;
    int r_ = (gm < Mz) ? gm : 0;
    if (rl) r_ = (gm < Mz) ? rl[gm] : 0;
    aidx = (long long)r_ * K + ahalf;
  }

  // conv pixel coords (B staging: thread -> (pixel, k-half))
  int pb = 0, py = 0, px = 0;
  if (conv_mode) {
    int gn = n0 + (tid >> 1);
    pb = gn >> logHW;
    int pos = gn & ((1 << logHW) - 1);
    py = pos >> logW;
    px = pos & ((1 << logW) - 1);
  }

#if HAS_TC
  // ======================= tcgen05 tf32x3 path ================================
  const uint32_t sbase = smem_u32(smem);
  if (wid == 0) TC_ALLOC(sbase, 128);
  if (tid == 0) { MB_INIT(sbase + SOFF_MBAR, 1); MB_INIT(sbase + SOFF_MBAR + 8, 1); }
  __syncthreads();
  uint32_t tmem;
  asm volatile("ld.shared.b32 %0, [%1];" : "=r"(tmem) : "r"(sbase));

  const int nchunks = K / TCK;
  int phase0 = 0, phase1 = 0;
  const uint32_t idesc =
      (1u << 4) | (2u << 7) | (2u << 10) | ((TCN / 8) << 17) | ((TCM / 16) << 24);

  for (int c = 0; c < nchunks; c++) {
    const int s = c & 1;
    const uint32_t stg = sbase + SOFF_TILES + s * TC_STAGE;
    const uint32_t sAhi = stg, sAlo = stg + TC_TILE;
    const uint32_t sBhi = stg + 2 * TC_TILE, sBlo = stg + 3 * TC_TILE;
    if (c >= 2) {
      if (s == 0) { MB_WAIT(sbase + SOFF_MBAR, phase0); phase0 ^= 1; }
      else        { MB_WAIT(sbase + SOFF_MBAR + 8, phase1); phase1 ^= 1; }
    }
    const int k0 = c * TCK;

    // ---- stage A (128 x 32): hi/lo split, SW128 K-major ----
    {
      const float* ap = Ab + aidx + k0;
      uint32_t ha[16], la[16];
#pragma unroll
      for (int q = 0; q < 4; q++) {
        float4 t = *(const float4*)(ap + q * 4);
        tf32split(t.x, ha[q * 4 + 0], la[q * 4 + 0]);
        tf32split(t.y, ha[q * 4 + 1], la[q * 4 + 1]);
        tf32split(t.z, ha[q * 4 + 2], la[q * 4 + 2]);
        tf32split(t.w, ha[q * 4 + 3], la[q * 4 + 3]);
      }
      const uint32_t ro = arow * 128 + ahalf * 4;
#pragma unroll
      for (int q = 0; q < 4; q++) {
        uint32_t off = SW128(ro + q * 16);
        sts128u(sAhi + off, ha[q * 4], ha[q * 4 + 1], ha[q * 4 + 2], ha[q * 4 + 3]);
        sts128u(sAlo + off, la[q * 4], la[q * 4 + 1], la[q * 4 + 2], la[q * 4 + 3]);
      }
    }

    // ---- stage B (128 x 32) ----
    if (!conv_mode) {
      const int kk_ = lane;
      const int nb_ = wid * 16;
      const float* bp = Bb + (long long)(k0 + kk_) * N + n0 + nb_;
      float vv[16];
#pragma unroll
      for (int q = 0; q < 4; q++) {
        int nn = n0 + nb_ + q * 4;
        if (nn + 3 < N) {
          float4 t = *(const float4*)(bp + q * 4);
          vv[q * 4 + 0] = t.x; vv[q * 4 + 1] = t.y;
          vv[q * 4 + 2] = t.z; vv[q * 4 + 3] = t.w;
        } else {
#pragma unroll
          for (int j = 0; j < 4; j++)
            vv[q * 4 + j] = (nn + j < N) ? bp[q * 4 + j] : 0.f;
        }
      }
#pragma unroll
      for (int j = 0; j < 16; j++) {
        uint32_t h, l;
        tf32split(vv[j], h, l);
        uint32_t off = SW128((uint32_t)(nb_ + j) * 128 + kk_ * 4);
        sts32u(sBhi + off, h);
        sts32u(sBlo + off, l);
      }
    } else {
      const int khalf = (tid & 1) * 16;
      const int nl = tid >> 1;
      uint32_t hb[16], lb[16];
#pragma unroll
      for (int i = 0; i < 16; i++) {
        int k = k0 + khalf + i;
        int ci = k / 9;
        int rr = k - ci * 9;
        int ky = rr / 3;
        int kx = rr - ky * 3;
        int iy = py + ky - 1, ix = px + kx - 1;
        float v = 0.f;
        if ((unsigned)iy < (unsigned)Himg && (unsigned)ix < (unsigned)Himg)
          v = Bb[(((long long)pb * Cin + ci) << logHW) + (iy << logW) + ix];
        tf32split(v, hb[i], lb[i]);
      }
      const uint32_t ro = nl * 128 + khalf * 4;
#pragma unroll
      for (int q = 0; q < 4; q++) {
        uint32_t off = SW128(ro + q * 16);
        sts128u(sBhi + off, hb[q * 4], hb[q * 4 + 1], hb[q * 4 + 2], hb[q * 4 + 3]);
        sts128u(sBlo + off, lb[q * 4], lb[q * 4 + 1], lb[q * 4 + 2], lb[q * 4 + 3]);
      }
    }

    FENCE_ASYNC();
    __syncthreads();

    if (tid == 0) {
      uint64_t dAh = mkdesc(sAhi), dAl = mkdesc(sAlo);
      uint64_t dBh = mkdesc(sBhi), dBl = mkdesc(sBlo);
#pragma unroll
      for (int i = 0; i < 4; i++)
        mma_tf32(tmem, dAh + 2 * i, dBh + 2 * i, idesc, (c > 0) | (i > 0));
#pragma unroll
      for (int i = 0; i < 4; i++)
        mma_tf32(tmem, dAh + 2 * i, dBl + 2 * i, idesc, 1u);
#pragma unroll
      for (int i = 0; i < 4; i++)
        mma_tf32(tmem, dAl + 2 * i, dBh + 2 * i, idesc, 1u);
      TC_COMMIT(sbase + SOFF_MBAR + 8 * s);
    }
  }

  MB_WAIT(sbase + SOFF_MBAR, phase0);
  if (nchunks > 1) MB_WAIT(sbase + SOFF_MBAR + 8, phase1);
  TC_FENCE_AFTER();

  if (wid < 4) {
    const int m = m0 + wid * 32 + lane;
    if (!conv_mode) {
      const bool mok = (m < Mz);
#pragma unroll 1
      for (int g = 0; g < 4; g++) {
        uint32_t r[32];
        TC_LD_X32(r, tmem + g * 32);
        TC_WAIT_LD();
        if (mok) {
#pragma unroll
          for (int j = 0; j < 32; j++) {
            int n = n0 + g * 32 + j;
            if (n < N) {
              float v = __uint_as_float(r[j]) + biasb[n];
              if (relu) v = fmaxf(v, 0.f);
              Cb[(long long)m * N + n] = v;
            }
          }
        }
      }
    } else {
      const float sc = gam[m] * rsqrtf(1.00001f);
      const float cbv = biasb[m], bev = bet[m];
      const int HWm1 = (1 << logHW) - 1;
#pragma unroll 1
      for (int g = 0; g < 4; g++) {
        uint32_t r[32];
        TC_LD_X32(r, tmem + g * 32);
        TC_WAIT_LD();
#pragma unroll
        for (int j = 0; j < 32; j++) {
          int pix = n0 + g * 32 + j;
          int b = pix >> logHW;
          int pos = pix & HWm1;
          float v = fmaxf((__uint_as_float(r[j]) + cbv) * sc + bev, 0.f);
          Cb[(((long long)b * M + m) << logHW) + pos] = v;
        }
      }
    }
    TC_FENCE_BEFORE();
  }
  __syncthreads();
  if (wid == 0) { TC_RELINQ(); TC_DEALLOC(tmem, 128); }

#else
  // ================== fallback: f32x2 scalar GEMM (same semantics) ===========
  float* Af = (float*)(smem + SOFF_TILES);     // [32][130]
  float* Bf = Af + 32 * 130;                   // [32][132]

  u64 acc[4][8];
#pragma unroll
  for (int p = 0; p < 4; p++)
#pragma unroll
    for (int j = 0; j < 8; j++) acc[p][j] = 0ull;

  const int tx = tid & 15, ty = tid >> 4;
  const int m8 = ty * 8, n8 = tx * 8;

  for (int k0 = 0; k0 < K; k0 += TCK) {
    // stage A [k][m]
    {
      const float* ap = Ab + aidx + k0;
#pragma unroll
      for (int q = 0; q < 4; q++) {
        float4 t = *(const float4*)(ap + q * 4);
        Af[(ahalf + q * 4 + 0) * 130 + arow] = t.x;
        Af[(ahalf + q * 4 + 1) * 130 + arow] = t.y;
        Af[(ahalf + q * 4 + 2) * 130 + arow] = t.z;
        Af[(ahalf + q * 4 + 3) * 130 + arow] = t.w;
      }
    }
    // stage B [k][n]
    if (!conv_mode) {
      const int kk_ = lane;
      const int nb_ = wid * 16;
      const float* bp = Bb + (long long)(k0 + kk_) * N + n0 + nb_;
#pragma unroll
      for (int q = 0; q < 4; q++) {
        int nn = n0 + nb_ + q * 4;
        float4 t;
        if (nn + 3 < N) {
          t = *(const float4*)(bp + q * 4);
        } else {
          t.x = (nn + 0 < N) ? bp[q * 4 + 0] : 0.f;
          t.y = (nn + 1 < N) ? bp[q * 4 + 1] : 0.f;
          t.z = (nn + 2 < N) ? bp[q * 4 + 2] : 0.f;
          t.w = (nn + 3 < N) ? bp[q * 4 + 3] : 0.f;
        }
        *(float4*)&Bf[kk_ * 132 + nb_ + q * 4] = t;
      }
    } else {
      const int khalf = (tid & 1) * 16;
      const int nl = tid >> 1;
#pragma unroll
      for (int i = 0; i < 16; i++) {
        int k = k0 + khalf + i;
        int ci = k / 9;
        int rr = k - ci * 9;
        int ky = rr / 3;
        int kx = rr - ky * 3;
        int iy = py + ky - 1, ix = px + kx - 1;
        float v = 0.f;
        if ((unsigned)iy < (unsigned)Himg && (unsigned)ix < (unsigned)Himg)
          v = Bb[(((long long)pb * Cin + ci) << logHW) + (iy << logW) + ix];
        Bf[(khalf + i) * 132 + nl] = v;
      }
    }
    __syncthreads();
#pragma unroll 4
    for (int kk = 0; kk < TCK; kk++) {
      const u64* ar = (const u64*)&Af[kk * 130 + m8];
      u64 a0 = ar[0], a1 = ar[1], a2 = ar[2], a3 = ar[3];
      float4 b40 = *(const float4*)&Bf[kk * 132 + n8];
      float4 b41 = *(const float4*)&Bf[kk * 132 + n8 + 4];
      u64 b[8];
      b[0] = dupf(b40.x); b[1] = dupf(b40.y); b[2] = dupf(b40.z); b[3] = dupf(b40.w);
      b[4] = dupf(b41.x); b[5] = dupf(b41.y); b[6] = dupf(b41.z); b[7] = dupf(b41.w);
#pragma unroll
      for (int j = 0; j < 8; j++) {
        fma2(acc[0][j], a0, b[j]);
        fma2(acc[1][j], a1, b[j]);
        fma2(acc[2][j], a2, b[j]);
        fma2(acc[3][j], a3, b[j]);
      }
    }
    __syncthreads();
  }

  if (!conv_mode) {
#pragma unroll
    for (int p = 0; p < 4; p++) {
      int mlo = m0 + m8 + 2 * p;
#pragma unroll
      for (int j = 0; j < 8; j++) {
        int n = n0 + n8 + j;
        if (n >= N) continue;
        float2 v = unp(acc[p][j]);
        float bsv = biasb[n];
        if (mlo < Mz) {
          float r = v.x + bsv;
          if (relu) r = fmaxf(r, 0.f);
          Cb[(long long)mlo * N + n] = r;
        }
        if (mlo + 1 < Mz) {
          float r = v.y + bsv;
          if (relu) r = fmaxf(r, 0.f);
          Cb[(long long)(mlo + 1) * N + n] = r;
        }
      }
    }
  } else {
    const float rs = rsqrtf(1.00001f);
    const int HWm1 = (1 << logHW) - 1;
#pragma unroll
    for (int p = 0; p < 4; p++) {
      int mlo = m0 + m8 + 2 * p;
      float sc0 = gam[mlo] * rs, cb0 = biasb[mlo], be0 = bet[mlo];
      float sc1 = gam[mlo + 1] * rs, cb1v = biasb[mlo + 1], be1v = bet[mlo + 1];
#pragma unroll
      for (int j = 0; j < 8; j++) {
        int pix = n0 + n8 + j;
        int b = pix >> logHW;
        int pos = pix & HWm1;
        float2 v = unp(acc[p][j]);
        float r0 = fmaxf((v.x + cb0) * sc0 + be0, 0.f);
        float r1 = fmaxf((v.y + cb1v) * sc1 + be1v, 0.f);
        Cb[(((long long)b * M + mlo) << logHW) + pos] = r0;
        Cb[(((long long)b * M + mlo + 1) << logHW) + pos] = r1;
      }
    }
  }
#endif
}

// =================== dense GEMM 128x64x16, f32x2 (small N only) ===============
#define DBM 128
#define DBN 64
#define DBK 16

__global__ __launch_bounds__(256) void gemm_f2(
    const float* __restrict__ A, const float* __restrict__ B,
    const float* __restrict__ bias, float* __restrict__ C,
    int M, int N, int K, int relu) {
  const int n0 = blockIdx.x * DBN;
  const int m0 = blockIdx.y * DBM;

  __shared__ float As[DBK][DBM + 2];
  __shared__ float Bs[DBK][DBN + 4];

  u64 acc[4][4];
#pragma unroll
  for (int p = 0; p < 4; p++)
#pragma unroll
    for (int j = 0; j < 4; j++) acc[p][j] = 0ull;

  const int tid = threadIdx.x;
  const int tx = tid & 15, ty = tid >> 4;

  int rowA[2], kqA[2];
  size_t abase[2];
#pragma unroll
  for (int i = 0; i < 2; i++) {
    int v = tid + i * 256;
    rowA[i] = v >> 2;
    kqA[i] = v & 3;
    abase[i] = (size_t)(m0 + rowA[i]) * K + kqA[i] * 4;
  }
  const int kb = tid >> 4, nb = (tid & 15) * 4;

  for (int k0 = 0; k0 < K; k0 += DBK) {
#pragma unroll
    for (int i = 0; i < 2; i++) {
      float4 a4 = *(const float4*)&A[abase[i] + k0];
      int kk = kqA[i] * 4;
      As[kk + 0][rowA[i]] = a4.x;
      As[kk + 1][rowA[i]] = a4.y;
      As[kk + 2][rowA[i]] = a4.z;
      As[kk + 3][rowA[i]] = a4.w;
    }
    {
      float4 b4;
      size_t bo = (size_t)(k0 + kb) * N + n0 + nb;
      if (n0 + nb + 3 < N) {
        b4 = *(const float4*)&B[bo];
      } else {
        b4.x = (n0 + nb + 0 < N) ? B[bo + 0] : 0.f;
        b4.y = (n0 + nb + 1 < N) ? B[bo + 1] : 0.f;
        b4.z = (n0 + nb + 2 < N) ? B[bo + 2] : 0.f;
        b4.w = (n0 + nb + 3 < N) ? B[bo + 3] : 0.f;
      }
      *(float4*)&Bs[kb][nb] = b4;
    }
    __syncthreads();
#pragma unroll
    for (int kk = 0; kk < DBK; kk++) {
      const u64* arow = (const u64*)&As[kk][0];
      u64 a0 = arow[ty * 4 + 0], a1 = arow[ty * 4 + 1];
      u64 a2 = arow[ty * 4 + 2], a3 = arow[ty * 4 + 3];
      float4 b4 = *(const float4*)&Bs[kk][tx * 4];
      u64 b0 = dupf(b4.x), b1 = dupf(b4.y), b2 = dupf(b4.z), b3 = dupf(b4.w);
      fma2(acc[0][0], a0, b0); fma2(acc[0][1], a0, b1);
      fma2(acc[0][2], a0, b2); fma2(acc[0][3], a0, b3);
      fma2(acc[1][0], a1, b0); fma2(acc[1][1], a1, b1);
      fma2(acc[1][2], a1, b2); fma2(acc[1][3], a1, b3);
      fma2(acc[2][0], a2, b0); fma2(acc[2][1], a2, b1);
      fma2(acc[2][2], a2, b2); fma2(acc[2][3], a2, b3);
      fma2(acc[3][0], a3, b0); fma2(acc[3][1], a3, b1);
      fma2(acc[3][2], a3, b2); fma2(acc[3][3], a3, b3);
    }
    __syncthreads();
  }

#pragma unroll
  for (int p = 0; p < 4; p++) {
    int mlo = m0 + ty * 8 + 2 * p;
#pragma unroll
    for (int j = 0; j < 4; j++) {
      int n = n0 + tx * 4 + j;
      if (n >= N) continue;
      float2 v = unp(acc[p][j]);
      float bsv = bias[n];
      if (mlo < M) {
        float r = v.x + bsv;
        if (relu) r = fmaxf(r, 0.f);
        C[(size_t)mlo * N + n] = r;
      }
      if (mlo + 1 < M) {
        float r = v.y + bsv;
        if (relu) r = fmaxf(r, 0.f);
        C[(size_t)(mlo + 1) * N + n] = r;
      }
    }
  }
}

// ============ implicit-im2col conv 64x128x16 + bias/BN/ReLU (conv1) ===========
#define CBM 64
#define CBN 128
#define CBK 16

__global__ __launch_bounds__(256) void conv_f2(
    const float* __restrict__ in, const float* __restrict__ w,
    const float* __restrict__ cb, const float* __restrict__ gam,
    const float* __restrict__ bet, float* __restrict__ out,
    int Cin, int Cout, int H, int logW, int logHW) {
  const int HW = 1 << logHW;
  const int W = 1 << logW;
  const int Ktot = Cin * 9;
  const int n0 = blockIdx.x * CBN;
  const int m0 = blockIdx.y * CBM;

  __shared__ float As[CBK][CBM + 2];
  __shared__ float Bs[CBK][CBN + 4];

  u64 acc[4][4];
#pragma unroll
  for (int p = 0; p < 4; p++)
#pragma unroll
    for (int j = 0; j < 4; j++) acc[p][j] = 0ull;

  const int tid = threadIdx.x;
  const int tx = tid & 31, ty = tid >> 5;
  const int kB = tid >> 4, nb8 = (tid & 15) * 8;

  for (int k0 = 0; k0 < Ktot; k0 += CBK) {
#pragma unroll
    for (int i = 0; i < 4; i++) {
      int l = tid + i * 256;
      int k = l & 15, m = l >> 4;
      int gk = k0 + k;
      As[k][m] = (gk < Ktot) ? w[(m0 + m) * Ktot + gk] : 0.f;
    }
    {
      int gk = k0 + kB;
      int ci = 0, ky = 0, kx = 0;
      bool kvalid = gk < Ktot;
      if (kvalid) {
        ci = gk / 9;
        int r = gk - ci * 9;
        ky = r / 3;
        kx = r - ky * 3;
      }
      const float* inp = in + (size_t)ci * HW;
#pragma unroll
      for (int jj = 0; jj < 8; jj++) {
        int gn = n0 + nb8 + jj;
        float v = 0.f;
        if (kvalid) {
          int b = gn >> logHW;
          int pos = gn & (HW - 1);
          int y = pos >> logW, x = pos & (W - 1);
          int iy = y + ky - 1, ix = x + kx - 1;
          if ((unsigned)iy < (unsigned)H && (unsigned)ix < (unsigned)H)
            v = inp[((size_t)b * Cin << logHW) + (iy << logW) + ix];
        }
        Bs[kB][nb8 + jj] = v;
      }
    }
    __syncthreads();
#pragma unroll
    for (int kk = 0; kk < CBK; kk++) {
      const u64* arow = (const u64*)&As[kk][0];
      u64 a0 = arow[ty * 4 + 0], a1 = arow[ty * 4 + 1];
      u64 a2 = arow[ty * 4 + 2], a3 = arow[ty * 4 + 3];
      float4 b4 = *(const float4*)&Bs[kk][tx * 4];
      u64 b0 = dupf(b4.x), b1 = dupf(b4.y), b2 = dupf(b4.z), b3 = dupf(b4.w);
      fma2(acc[0][0], a0, b0); fma2(acc[0][1], a0, b1);
      fma2(acc[0][2], a0, b2); fma2(acc[0][3], a0, b3);
      fma2(acc[1][0], a1, b0); fma2(acc[1][1], a1, b1);
      fma2(acc[1][2], a1, b2); fma2(acc[1][3], a1, b3);
      fma2(acc[2][0], a2, b0); fma2(acc[2][1], a2, b1);
      fma2(acc[2][2], a2, b2); fma2(acc[2][3], a2, b3);
      fma2(acc[3][0], a3, b0); fma2(acc[3][1], a3, b1);
      fma2(acc[3][2], a3, b2); fma2(acc[3][3], a3, b3);
    }
    __syncthreads();
  }

  const float rs = rsqrtf(1.00001f);
#pragma unroll
  for (int p = 0; p < 4; p++) {
    int mlo = m0 + ty * 8 + 2 * p;
    float sc0 = gam[mlo] * rs, cb0 = cb[mlo], be0 = bet[mlo];
    float sc1 = gam[mlo + 1] * rs, cb1v = cb[mlo + 1], be1v = bet[mlo + 1];
#pragma unroll
    for (int j = 0; j < 4; j++) {
      int gn = n0 + tx * 4 + j;
      int b = gn >> logHW;
      int pos = gn & (HW - 1);
      float2 v = unp(acc[p][j]);
      float r0 = fmaxf((v.x + cb0) * sc0 + be0, 0.f);
      float r1 = fmaxf((v.y + cb1v) * sc1 + be1v, 0.f);
      out[((size_t)(b * Cout + mlo) << logHW) + pos] = r0;
      out[((size_t)(b * Cout + mlo + 1) << logHW) + pos] = r1;
    }
  }
}

// ---------------- 2x2 max pool (stride 2) ----------------
__global__ void pool_kernel(const float* __restrict__ in, float* __restrict__ out,
                            int C, int H) {
  int Hp = H >> 1;
  int total = BATCH * C * Hp * Hp;
  int idx = blockIdx.x * blockDim.x + threadIdx.x;
  if (idx >= total) return;
  int px = idx % Hp;
  int t = idx / Hp;
  int py = t % Hp; t /= Hp;
  int c = t % C;
  int b = t / C;
  const float* p = in + ((size_t)(b * C + c) * H + py * 2) * H + px * 2;
  out[idx] = fmaxf(fmaxf(p[0], p[1]), fmaxf(p[H], p[H + 1]));
}

// ---------------- noisy top-k gating (per row) ----------------
__global__ void gating_kernel(const float* __restrict__ clean,
                              const float* __restrict__ rawstd,
                              const float* __restrict__ noise,
                              float* __restrict__ gates, float* __restrict__ prob) {
  int b = blockIdx.x * blockDim.x + threadIdx.x;
  if (b >= BATCH) return;
  float c[NEXP], sd[NEXP], nz[NEXP];
#pragma unroll
  for (int e = 0; e < NEXP; e++) {
    c[e] = clean[b * NEXP + e];
    float rsv = rawstd[b * NEXP + e];
    float sp = (rsv > 20.f) ? rsv : log1pf(expf(rsv));
    sd[e] = sp + 0.01f;
    nz[e] = c[e] + noise[b * NEXP + e] * sd[e];
  }
  int i0 = 0; float v0 = nz[0];
#pragma unroll
  for (int e = 1; e < NEXP; e++) if (nz[e] > v0) { v0 = nz[e]; i0 = e; }
  int i1 = -1; float v1 = -1e30f;
#pragma unroll
  for (int e = 0; e < NEXP; e++) if (e != i0 && nz[e] > v1) { v1 = nz[e]; i1 = e; }
  float v2 = -1e30f;
#pragma unroll
  for (int e = 0; e < NEXP; e++) if (e != i0 && e != i1 && nz[e] > v2) v2 = nz[e];

  float e1 = expf(v1 - v0);
  float inv = 1.f / (1.f + e1);
  const float kInvSqrt2 = 0.70710678118654752440f;
#pragma unroll
  for (int e = 0; e < NEXP; e++) {
    float g = (e == i0) ? inv : ((e == i1) ? e1 * inv : 0.f);
    gates[b * NEXP + e] = g;
    float th = (nz[e] > v2) ? v2 : v1;
    float zz = (c[e] - th) / sd[e];
    prob[b * NEXP + e] = 0.5f * (1.f + erff(zz * kInvSqrt2));
  }
}

// -------- deterministic dispatch build (1 block, warp per expert) --------
__global__ void build_dispatch(const float* __restrict__ gates,
                               int* __restrict__ rowlist, int* __restrict__ cnt,
                               int* __restrict__ rowslot,
                               float* __restrict__ slotgate) {
  int w = threadIdx.x >> 5;
  int lane = threadIdx.x & 31;
  int c = 0;
  for (int base = 0; base < BATCH; base += 32) {
    int b = base + lane;
    float g = gates[b * NEXP + w];
    unsigned mask = __ballot_sync(0xffffffffu, g > 0.f);
    if (g > 0.f) {
      int pos = c + __popc(mask & ((1u << lane) - 1u));
      int slot = w * BATCH + pos;
      rowlist[slot] = b;
      slotgate[slot] = g;
      int m8 = 0;
#pragma unroll
      for (int e = 0; e < NEXP; e++) m8 |= (gates[b * NEXP + e] > 0.f) ? (1 << e) : 0;
      int j = __popc(m8 & ((1 << w) - 1));
      rowslot[b * 2 + j] = slot;
    }
    c += __popc(mask);
  }
  if (lane == 0) cnt[w] = c;
}

// ---------------- deterministic per-expert reductions ----------------
__global__ void moe_reduce_kernel(const float* __restrict__ gates,
                                  const float* __restrict__ prob,
                                  float* __restrict__ imp, float* __restrict__ loadv) {
  int e = blockIdx.x;
  int t = threadIdx.x;
  __shared__ float s1[256], s2[256];
  float a = 0.f, b = 0.f;
  for (int i = t; i < BATCH; i += 256) {
    a += gates[i * NEXP + e];
    b += prob[i * NEXP + e];
  }
  s1[t] = a; s2[t] = b;
  __syncthreads();
  for (int s = 128; s > 0; s >>= 1) {
    if (t < s) { s1[t] += s1[t + s]; s2[t] += s2[t + s]; }
    __syncthreads();
  }
  if (t == 0) { imp[e] = s1[0]; loadv[e] = s2[0]; }
}

__global__ void loss_kernel(const float* __restrict__ imp,
                            const float* __restrict__ loadv,
                            float* __restrict__ out) {
  float m1 = 0.f, m2 = 0.f;
  for (int e = 0; e < NEXP; e++) { m1 += imp[e]; m2 += loadv[e]; }
  m1 *= 0.125f; m2 *= 0.125f;
  float v1 = 0.f, v2 = 0.f;
  for (int e = 0; e < NEXP; e++) {
    float d1 = imp[e] - m1; v1 += d1 * d1;
    float d2 = loadv[e] - m2; v2 += d2 * d2;
  }
  v1 /= 7.f; v2 /= 7.f;
  out[0] = v1 / (m1 * m1 + 1e-10f) + v2 / (m2 * m2 + 1e-10f);
}

// ------------- slot-based combine: y[b,c] = g0*eo[s0,c]+g1*eo[s1,c] ----------
__global__ void combine2_kernel(const int* __restrict__ rowslot,
                                const float* __restrict__ slotgate,
                                const float* __restrict__ eo,
                                float* __restrict__ y) {
  int idx = blockIdx.x * blockDim.x + threadIdx.x;
  if (idx >= BATCH * NCLS) return;
  int b = idx / NCLS;
  int c = idx - b * NCLS;
  int s0 = rowslot[b * 2 + 0], s1 = rowslot[b * 2 + 1];
  y[idx] = slotgate[s0] * eo[(size_t)s0 * NCLS + c] +
           slotgate[s1] * eo[(size_t)s1 * NCLS + c];
}

// ================================ launch ======================================
extern "C" void kernel_launch(void* const* d_in, const int* in_sizes, int n_in,
                              void* d_out, int out_size) {
  const float* x    = (const float*)d_in[0];
  const float* noise= (const float*)d_in[1];
  const float* cw1 = (const float*)d_in[2],  *cb1 = (const float*)d_in[3];
  const float* g1  = (const float*)d_in[4],  *be1 = (const float*)d_in[5];
  const float* cw2 = (const float*)d_in[6],  *cb2 = (const float*)d_in[7];
  const float* g2  = (const float*)d_in[8],  *be2 = (const float*)d_in[9];
  const float* cw3 = (const float*)d_in[10], *cb3 = (const float*)d_in[11];
  const float* g3  = (const float*)d_in[12], *be3 = (const float*)d_in[13];
  const float* cw4 = (const float*)d_in[14], *cb4 = (const float*)d_in[15];
  const float* g4  = (const float*)d_in[16], *be4 = (const float*)d_in[17];
  const float* wg1 = (const float*)d_in[18], *wg1b= (const float*)d_in[19];
  const float* wg2 = (const float*)d_in[20], *wg2b= (const float*)d_in[21];
  const float* wn1 = (const float*)d_in[22], *wn1b= (const float*)d_in[23];
  const float* wn2 = (const float*)d_in[24], *wn2b= (const float*)d_in[25];
  const float* eW1 = (const float*)d_in[26], *eb1 = (const float*)d_in[27];
  const float* eW2 = (const float*)d_in[28], *eb2 = (const float*)d_in[29];
  const float* eW3 = (const float*)d_in[30], *eb3 = (const float*)d_in[31];

  float *convout, *poolA, *poolB, *hid, *clean, *rawstd, *gates, *prob;
  float *eh, *eh2, *eo, *imp, *loadv, *slotgate;
  int *rowlist, *cnt, *rowslot;
  cudaGetSymbolAddress((void**)&convout, g_convout);
  cudaGetSymbolAddress((void**)&poolA, g_poolA);
  cudaGetSymbolAddress((void**)&poolB, g_poolB);
  cudaGetSymbolAddress((void**)&hid, g_hid);
  cudaGetSymbolAddress((void**)&clean, g_clean);
  cudaGetSymbolAddress((void**)&rawstd, g_rawstd);
  cudaGetSymbolAddress((void**)&gates, g_gates);
  cudaGetSymbolAddress((void**)&prob, g_prob);
  cudaGetSymbolAddress((void**)&eh, g_eh);
  cudaGetSymbolAddress((void**)&eh2, g_eh2);
  cudaGetSymbolAddress((void**)&eo, g_eo);
  cudaGetSymbolAddress((void**)&imp, g_imp);
  cudaGetSymbolAddress((void**)&loadv, g_load);
  cudaGetSymbolAddress((void**)&rowlist, g_rowlist);
  cudaGetSymbolAddress((void**)&cnt, g_cnt);
  cudaGetSymbolAddress((void**)&rowslot, g_rowslot);
  cudaGetSymbolAddress((void**)&slotgate, g_slotgate);

  float* out = (float*)d_out;

  cudaFuncSetAttribute(tc_gemm, cudaFuncAttributeMaxDynamicSharedMemorySize, SMEM_TC);

  // ---- conv1 (scalar) + pool ----
  conv_f2<<<dim3(BATCH * 1024 / CBN, 1), 256>>>(x, cw1, cb1, g1, be1, convout, 3, 64, 32, 5, 10);
  pool_kernel<<<(BATCH * 64 * 256 + 255) / 256, 256>>>(convout, poolA, 64, 32);

  // ---- conv2-4 (tc_gemm) + pools ----
  tc_gemm<<<dim3(BATCH * 256 / TCN, 1, 1), 256, SMEM_TC>>>(
      cw2, poolA, cb2, convout, 128, BATCH * 256, 576, 1,
      0, 0, 0, 0, 0, 0, 1, 64, 16, 4, 8, g2, be2);
  pool_kernel<<<(BATCH * 128 * 64 + 255) / 256, 256>>>(convout, poolB, 128, 16);

  tc_gemm<<<dim3(BATCH * 64 / TCN, 2, 1), 256, SMEM_TC>>>(
      cw3, poolB, cb3, convout, 256, BATCH * 64, 1152, 1,
      0, 0, 0, 0, 0, 0, 1, 128, 8, 3, 6, g3, be3);
  pool_kernel<<<(BATCH * 256 * 16 + 255) / 256, 256>>>(convout, poolA, 256, 8);

  tc_gemm<<<dim3(BATCH * 16 / TCN, 4, 1), 256, SMEM_TC>>>(
      cw4, poolA, cb4, convout, 512, BATCH * 16, 2304, 1,
      0, 0, 0, 0, 0, 0, 1, 256, 4, 2, 4, g4, be4);
  pool_kernel<<<(BATCH * 512 * 4 + 255) / 256, 256>>>(convout, poolB, 512, 4);

  const float* f = poolB;  // [2048, 2048]

  // ---- gating nets (big GEMMs via tc_gemm, tiny N=8 scalar) ----
  tc_gemm<<<dim3(GATEH / TCN, BATCH / TCM, 1), 256, SMEM_TC>>>(
      f, wg1, wg1b, hid, BATCH, GATEH, FEAT, 1,
      0, 0, 0, 0, 0, 0, 0, 0, 0, 0, 0, 0, 0);
  gemm_f2<<<dim3(1, BATCH / DBM, 1), 256>>>(hid, wg2, wg2b, clean, BATCH, NEXP, GATEH, 0);
  tc_gemm<<<dim3(GATEH / TCN, BATCH / TCM, 1), 256, SMEM_TC>>>(
      f, wn1, wn1b, hid, BATCH, GATEH, FEAT, 1,
      0, 0, 0, 0, 0, 0, 0, 0, 0, 0, 0, 0, 0);
  gemm_f2<<<dim3(1, BATCH / DBM, 1), 256>>>(hid, wn2, wn2b, rawstd, BATCH, NEXP, GATEH, 0);

  gating_kernel<<<BATCH / 256, 256>>>(clean, rawstd, noise, gates, prob);
  build_dispatch<<<1, 256>>>(gates, rowlist, cnt, rowslot, slotgate);
  moe_reduce_kernel<<<NEXP, 256>>>(gates, prob, imp, loadv);

  // ---- sparse experts (capacity grid + early-exit) ----
  tc_gemm<<<dim3(HID / TCN, BATCH / TCM, NEXP), 256, SMEM_TC>>>(
      f, eW1, eb1, eh, BATCH, HID, FEAT, 1,
      0, (long long)FEAT * HID, HID, (long long)BATCH * HID,
      rowlist, cnt, 0, 0, 0, 0, 0, 0, 0);
  tc_gemm<<<dim3((HID / 2) / TCN, BATCH / TCM, NEXP), 256, SMEM_TC>>>(
      eh, eW2, eb2, eh2, BATCH, HID / 2, HID, 1,
      (long long)BATCH * HID, (long long)HID * (HID / 2), HID / 2,
      (long long)BATCH * (HID / 2), 0, cnt, 0, 0, 0, 0, 0, 0, 0);
  tc_gemm<<<dim3(1, BATCH / TCM, NEXP), 256, SMEM_TC>>>(
      eh2, eW3, eb3, eo, BATCH, NCLS, HID / 2, 0,
      (long long)BATCH * (HID / 2), (long long)(HID / 2) * NCLS, NCLS,
      (long long)BATCH * NCLS, 0, cnt, 0, 0, 0, 0, 0, 0, 0);

  // ---- outputs ----
  combine2_kernel<<<(BATCH * NCLS + 255) / 256, 256>>>(rowslot, slotgate, eo, out);
  if (out_size >= BATCH * NCLS + 1)
    loss_kernel<<<1, 1>>>(imp, loadv, out + BATCH * NCLS);
}

// round 6
// speedup vs baseline: 1.5735x; 1.2111x over previous
#include <cuda_runtime.h>
#include <cuda_bf16.h>
#include <math.h>
#include <stdint.h>

#define BATCH 2048
#define NEXP 8
#define NCLS 100
#define HID 1024
#define GATEH 2048
#define FEAT 2048

typedef unsigned long long u64;

// Does this compilation pass have sm_10x accelerated features (tcgen05)?
#if defined(__CUDA_ARCH_FEAT_SM103_ALL) || defined(__CUDA_ARCH_FEAT_SM100_ALL) || \
    defined(__CUDA_ARCH_FEAT_SM101_ALL) ||                                        \
    (defined(__CUDA_ARCH_SPECIFIC__) && (__CUDA_ARCH_SPECIFIC__ > 0))
#define HAS_TC 1
#else
#define HAS_TC 0
#endif

// ---------------- scratch (device globals; no allocation allowed) -------------
__device__ float g_convout[134217728];
__device__ float g_poolA[33554432];
__device__ float g_poolB[16777216];
__device__ float g_hid[BATCH * GATEH];
__device__ float g_clean[BATCH * NEXP];
__device__ float g_rawstd[BATCH * NEXP];
__device__ float g_gates[BATCH * NEXP];
__device__ float g_prob[BATCH * NEXP];
__device__ float g_eh[(size_t)NEXP * BATCH * HID];
__device__ float g_eh2[(size_t)NEXP * BATCH * (HID / 2)];
__device__ float g_eo[(size_t)NEXP * BATCH * NCLS];
__device__ float g_imp[NEXP];
__device__ float g_load[NEXP];
__device__ int   g_rowlist[NEXP * BATCH];
__device__ int   g_cnt[NEXP];
__device__ int   g_rowslot[BATCH * 2];
__device__ float g_slotgate[NEXP * BATCH];

// ========================== common helpers ====================================
__device__ __forceinline__ uint32_t smem_u32(const void* p) {
  uint32_t a;
  asm("{ .reg .u64 t; cvta.to.shared.u64 t, %1; cvt.u32.u64 %0, t; }"
      : "=r"(a) : "l"(p));
  return a;
}

#define SW128(o) ((o) ^ (((o) >> 3) & 0x70))

__device__ __forceinline__ u64 dupf(float v) {
  u64 r; asm("mov.b64 %0, {%1, %1};" : "=l"(r) : "f"(v)); return r;
}
__device__ __forceinline__ void fma2(u64& d, u64 a, u64 b) {
  asm("fma.rn.f32x2 %0, %1, %2, %0;" : "+l"(d) : "l"(a), "l"(b));
}
__device__ __forceinline__ float2 unp(u64 v) {
  float2 f; asm("mov.b64 {%0, %1}, %2;" : "=f"(f.x), "=f"(f.y) : "l"(v)); return f;
}

// bf16 2-way split of two consecutive values, packed k-contiguous into u32
__device__ __forceinline__ void bsplit2(float x0, float x1, uint32_t& hi, uint32_t& lo) {
  __nv_bfloat16 h0 = __float2bfloat16_rn(x0);
  __nv_bfloat16 h1 = __float2bfloat16_rn(x1);
  __nv_bfloat16 l0 = __float2bfloat16_rn(x0 - __bfloat162float(h0));
  __nv_bfloat16 l1 = __float2bfloat16_rn(x1 - __bfloat162float(h1));
  __nv_bfloat162 H; H.x = h0; H.y = h1;
  __nv_bfloat162 L; L.x = l0; L.y = l1;
  hi = *(uint32_t*)&H;
  lo = *(uint32_t*)&L;
}

#if HAS_TC
// ---- tcgen05 PTX wrappers (only in accelerated pass) ----
#define TC_ALLOC(sa, n) \
  asm volatile("tcgen05.alloc.cta_group::1.sync.aligned.shared::cta.b32 [%0], %1;" \
               :: "r"(sa), "r"(n) : "memory")
#define TC_DEALLOC(t, n) \
  asm volatile("tcgen05.dealloc.cta_group::1.sync.aligned.b32 %0, %1;" :: "r"(t), "r"(n))
#define TC_RELINQ() \
  asm volatile("tcgen05.relinquish_alloc_permit.cta_group::1.sync.aligned;")
#define TC_COMMIT(mb) \
  asm volatile("tcgen05.commit.cta_group::1.mbarrier::arrive::one.shared::cluster.b64 [%0];" \
               :: "r"(mb) : "memory")
#define TC_FENCE_AFTER()  asm volatile("tcgen05.fence::after_thread_sync;" ::: "memory")
#define TC_FENCE_BEFORE() asm volatile("tcgen05.fence::before_thread_sync;" ::: "memory")
#define TC_WAIT_LD()      asm volatile("tcgen05.wait::ld.sync.aligned;" ::: "memory")
#define FENCE_ASYNC()     asm volatile("fence.proxy.async.shared::cta;" ::: "memory")
#define MB_INIT(mb, n) \
  asm volatile("mbarrier.init.shared.b64 [%0], %1;" :: "r"(mb), "r"(n) : "memory")

#define MB_WAIT(mbar_addr, ph) do { \
  uint32_t _mb = (uint32_t)(mbar_addr); \
  uint32_t _p = (uint32_t)(ph); \
  asm volatile( \
      "{\n\t.reg .pred P1;\n\t" \
      "WAIT_LOOP_%=:\n\t" \
      "mbarrier.try_wait.parity.acquire.cta.shared::cta.b64 P1, [%0], %1, 0x989680;\n\t" \
      "@P1 bra.uni WAIT_DONE_%=;\n\t" \
      "bra.uni WAIT_LOOP_%=;\n\t" \
      "WAIT_DONE_%=:\n\t}" \
      :: "r"(_mb), "r"(_p) : "memory"); \
} while (0)

#define TC_LD_X32(r, ta) \
  asm volatile( \
      "tcgen05.ld.sync.aligned.32x32b.x32.b32 " \
      "{%0, %1, %2, %3, %4, %5, %6, %7, " \
      " %8, %9, %10, %11, %12, %13, %14, %15, " \
      " %16, %17, %18, %19, %20, %21, %22, %23, " \
      " %24, %25, %26, %27, %28, %29, %30, %31}, [%32];" \
      : "=r"((r)[0]),  "=r"((r)[1]),  "=r"((r)[2]),  "=r"((r)[3]), \
        "=r"((r)[4]),  "=r"((r)[5]),  "=r"((r)[6]),  "=r"((r)[7]), \
        "=r"((r)[8]),  "=r"((r)[9]),  "=r"((r)[10]), "=r"((r)[11]), \
        "=r"((r)[12]), "=r"((r)[13]), "=r"((r)[14]), "=r"((r)[15]), \
        "=r"((r)[16]), "=r"((r)[17]), "=r"((r)[18]), "=r"((r)[19]), \
        "=r"((r)[20]), "=r"((r)[21]), "=r"((r)[22]), "=r"((r)[23]), \
        "=r"((r)[24]), "=r"((r)[25]), "=r"((r)[26]), "=r"((r)[27]), \
        "=r"((r)[28]), "=r"((r)[29]), "=r"((r)[30]), "=r"((r)[31]) \
      : "r"(ta))

__device__ __forceinline__ uint64_t mkdesc(uint32_t addr) {
  return ((uint64_t)2 << 61) | ((uint64_t)1 << 46) | ((uint64_t)64 << 32) |
         ((uint64_t)1 << 16) | ((addr >> 4) & 0x3FFF);
}

// kind::f16 (bf16 inputs, fp32 accum), cg1, disable-mask = 4 zeros
__device__ __forceinline__ void mma_bf16(uint32_t d, uint64_t ad, uint64_t bd,
                                         uint32_t idesc, uint32_t en) {
  asm volatile(
      "{\n\t.reg .pred p;\n\tsetp.ne.u32 p, %5, 0;\n\t"
      "tcgen05.mma.cta_group::1.kind::f16 [%0], %1, %2, %3, {%4, %4, %4, %4}, p;\n\t}"
      :: "r"(d), "l"(ad), "l"(bd), "r"(idesc), "r"(0u), "r"(en) : "memory");
}
#endif  // HAS_TC

__device__ __forceinline__ void sts128u(uint32_t addr, uint32_t a, uint32_t b,
                                        uint32_t c, uint32_t d) {
  asm volatile("st.shared.v4.b32 [%0], {%1, %2, %3, %4};"
               :: "r"(addr), "r"(a), "r"(b), "r"(c), "r"(d) : "memory");
}
__device__ __forceinline__ void sts32u(uint32_t addr, uint32_t v) {
  asm volatile("st.shared.b32 [%0], %1;" :: "r"(addr), "r"(v) : "memory");
}

// ================= unified GEMM (128x128 tile, bf16x3, Kc=64) =================
#define TCM 128
#define TCN 128
#define TCK 64
#define TC_TILE 16384                      // 128 rows x 128B (64 bf16 k)
#define TC_STAGE (4 * TC_TILE)
#define SOFF_MBAR 16
#define SOFF_TILES 1024
#define SMEM_TC (SOFF_TILES + 2 * TC_STAGE)

__global__ void __launch_bounds__(256, 1) tc_gemm(
    const float* __restrict__ A, const float* __restrict__ Bm,
    const float* __restrict__ bias, float* __restrict__ C,
    int M, int N, int K, int relu,
    long long sA, long long sB, long long sBias, long long sC,
    const int* __restrict__ rowlist, const int* __restrict__ cnt,
    int conv_mode, int Cin, int Himg, int logW, int logHW,
    const float* __restrict__ gam, const float* __restrict__ bet) {
  extern __shared__ char smem[];
  const int z = blockIdx.z;
  const int Mz = cnt ? cnt[z] : M;
  const int m0 = blockIdx.y * TCM;
  if (m0 >= Mz) return;
  const int n0 = blockIdx.x * TCN;

  const float* Ab = A + (long long)z * sA;
  const float* Bb = Bm + (long long)z * sB;
  const float* biasb = bias + (long long)z * sBias;
  float* Cb = C + (long long)z * sC;
  const int* rl = rowlist ? rowlist + z * BATCH : (const int*)0;

  const int tid = threadIdx.x;
  const int wid = tid >> 5, lane = tid & 31;

  // A staging: thread -> (row, 32-k half)
  const int arow = tid >> 1;
  const int ahalf = (tid & 1) * 32;
  long long aidx;
  {
    int gm = m0 + arow;
    int r_ = (gm < Mz) ? gm : 0;
    if (rl) r_ = (gm < Mz) ? rl[gm] : 0;
    aidx = (long long)r_ * K + ahalf;
  }

  // conv pixel coords (B staging: thread -> (pixel, 32-k half))
  int pb = 0, py = 0, px = 0;
  if (conv_mode) {
    int gn = n0 + (tid >> 1);
    pb = gn >> logHW;
    int pos = gn & ((1 << logHW) - 1);
    py = pos >> logW;
    px = pos & ((1 << logW) - 1);
  }

#if HAS_TC
  // ======================= tcgen05 bf16x3 path ================================
  const uint32_t sbase = smem_u32(smem);
  if (wid == 0) TC_ALLOC(sbase, 128);
  if (tid == 0) { MB_INIT(sbase + SOFF_MBAR, 1); MB_INIT(sbase + SOFF_MBAR + 8, 1); }
  __syncthreads();
  uint32_t tmem;
  asm volatile("ld.shared.b32 %0, [%1];" : "=r"(tmem) : "r"(sbase));

  const int nchunks = K / TCK;
  int phase0 = 0, phase1 = 0;
  const uint32_t idesc =
      (1u << 4) | (1u << 7) | (1u << 10) | ((TCN / 8) << 17) | ((TCM / 16) << 24);

  for (int c = 0; c < nchunks; c++) {
    const int s = c & 1;
    const uint32_t stg = sbase + SOFF_TILES + s * TC_STAGE;
    const uint32_t sAhi = stg, sAlo = stg + TC_TILE;
    const uint32_t sBhi = stg + 2 * TC_TILE, sBlo = stg + 3 * TC_TILE;
    if (c >= 2) {
      if (s == 0) { MB_WAIT(sbase + SOFF_MBAR, phase0); phase0 ^= 1; }
      else        { MB_WAIT(sbase + SOFF_MBAR + 8, phase1); phase1 ^= 1; }
    }
    const int k0 = c * TCK;

    // ---- stage A (128 x 64 k): bf16 hi/lo, SW128 K-major ----
    {
      const float* ap = Ab + aidx + k0;
      uint32_t ha[16], la[16];
#pragma unroll
      for (int q = 0; q < 8; q++) {
        float4 t = *(const float4*)(ap + q * 4);
        bsplit2(t.x, t.y, ha[q * 2 + 0], la[q * 2 + 0]);
        bsplit2(t.z, t.w, ha[q * 2 + 1], la[q * 2 + 1]);
      }
      const uint32_t ro = arow * 128 + ahalf * 2;
#pragma unroll
      for (int q = 0; q < 4; q++) {
        uint32_t off = SW128(ro + q * 16);
        sts128u(sAhi + off, ha[q * 4], ha[q * 4 + 1], ha[q * 4 + 2], ha[q * 4 + 3]);
        sts128u(sAlo + off, la[q * 4], la[q * 4 + 1], la[q * 4 + 2], la[q * 4 + 3]);
      }
    }

    // ---- stage B (128 n x 64 k) ----
    if (!conv_mode) {
      // dense weights [K][N]: thread -> k-pair p (0..31), n-group ng (16 n)
      const int p = tid >> 3;
      const int ng = tid & 7;
      const float* bp0 = Bb + (long long)(k0 + 2 * p) * N + n0 + ng * 16;
      const float* bp1 = bp0 + N;
      float va[16], vb[16];
#pragma unroll
      for (int q = 0; q < 4; q++) {
        int nn = n0 + ng * 16 + q * 4;
        if (nn + 3 < N) {
          float4 t0 = *(const float4*)(bp0 + q * 4);
          float4 t1 = *(const float4*)(bp1 + q * 4);
          va[q * 4 + 0] = t0.x; va[q * 4 + 1] = t0.y; va[q * 4 + 2] = t0.z; va[q * 4 + 3] = t0.w;
          vb[q * 4 + 0] = t1.x; vb[q * 4 + 1] = t1.y; vb[q * 4 + 2] = t1.z; vb[q * 4 + 3] = t1.w;
        } else {
#pragma unroll
          for (int j = 0; j < 4; j++) {
            va[q * 4 + j] = (nn + j < N) ? bp0[q * 4 + j] : 0.f;
            vb[q * 4 + j] = (nn + j < N) ? bp1[q * 4 + j] : 0.f;
          }
        }
      }
#pragma unroll
      for (int j = 0; j < 16; j++) {
        uint32_t h, l;
        bsplit2(va[j], vb[j], h, l);   // pair across k (2p, 2p+1), same n
        uint32_t off = SW128((uint32_t)(ng * 16 + j) * 128 + p * 4);
        sts32u(sBhi + off, h);
        sts32u(sBlo + off, l);
      }
    } else {
      // im2col gather: row = pixel, 32 k per thread
      const int khalf = (tid & 1) * 32;
      const int nl = tid >> 1;
      uint32_t hb[16], lb[16];
#pragma unroll
      for (int i = 0; i < 32; i += 2) {
        float v[2];
#pragma unroll
        for (int d = 0; d < 2; d++) {
          int k = k0 + khalf + i + d;
          int ci = k / 9;
          int rr = k - ci * 9;
          int ky = rr / 3;
          int kx = rr - ky * 3;
          int iy = py + ky - 1, ix = px + kx - 1;
          v[d] = 0.f;
          if ((unsigned)iy < (unsigned)Himg && (unsigned)ix < (unsigned)Himg)
            v[d] = Bb[(((long long)pb * Cin + ci) << logHW) + (iy << logW) + ix];
        }
        bsplit2(v[0], v[1], hb[i / 2], lb[i / 2]);
      }
      const uint32_t ro = nl * 128 + khalf * 2;
#pragma unroll
      for (int q = 0; q < 4; q++) {
        uint32_t off = SW128(ro + q * 16);
        sts128u(sBhi + off, hb[q * 4], hb[q * 4 + 1], hb[q * 4 + 2], hb[q * 4 + 3]);
        sts128u(sBlo + off, lb[q * 4], lb[q * 4 + 1], lb[q * 4 + 2], lb[q * 4 + 3]);
      }
    }

    FENCE_ASYNC();
    __syncthreads();

    if (tid == 0) {
      uint64_t dAh = mkdesc(sAhi), dAl = mkdesc(sAlo);
      uint64_t dBh = mkdesc(sBhi), dBl = mkdesc(sBlo);
#pragma unroll
      for (int i = 0; i < 4; i++)   // K=16 per step -> +32B = +2 units
        mma_bf16(tmem, dAh + 2 * i, dBh + 2 * i, idesc, (c > 0) | (i > 0));
#pragma unroll
      for (int i = 0; i < 4; i++)
        mma_bf16(tmem, dAh + 2 * i, dBl + 2 * i, idesc, 1u);
#pragma unroll
      for (int i = 0; i < 4; i++)
        mma_bf16(tmem, dAl + 2 * i, dBh + 2 * i, idesc, 1u);
      TC_COMMIT(sbase + SOFF_MBAR + 8 * s);
    }
  }

  MB_WAIT(sbase + SOFF_MBAR, phase0);
  if (nchunks > 1) MB_WAIT(sbase + SOFF_MBAR + 8, phase1);
  TC_FENCE_AFTER();

  if (wid < 4) {
    const int m = m0 + wid * 32 + lane;
    if (!conv_mode) {
      const bool mok = (m < Mz);
#pragma unroll 1
      for (int g = 0; g < 4; g++) {
        uint32_t r[32];
        TC_LD_X32(r, tmem + g * 32);
        TC_WAIT_LD();
        if (mok) {
#pragma unroll
          for (int j = 0; j < 32; j++) {
            int n = n0 + g * 32 + j;
            if (n < N) {
              float v = __uint_as_float(r[j]) + biasb[n];
              if (relu) v = fmaxf(v, 0.f);
              Cb[(long long)m * N + n] = v;
            }
          }
        }
      }
    } else {
      const float sc = gam[m] * rsqrtf(1.00001f);
      const float cbv = biasb[m], bev = bet[m];
      const int HWm1 = (1 << logHW) - 1;
#pragma unroll 1
      for (int g = 0; g < 4; g++) {
        uint32_t r[32];
        TC_LD_X32(r, tmem + g * 32);
        TC_WAIT_LD();
#pragma unroll
        for (int j = 0; j < 32; j++) {
          int pix = n0 + g * 32 + j;
          int b = pix >> logHW;
          int pos = pix & HWm1;
          float v = fmaxf((__uint_as_float(r[j]) + cbv) * sc + bev, 0.f);
          Cb[(((long long)b * M + m) << logHW) + pos] = v;
        }
      }
    }
    TC_FENCE_BEFORE();
  }
  __syncthreads();
  if (wid == 0) { TC_RELINQ(); TC_DEALLOC(tmem, 128); }

#else
  // ================== fallback: f32x2 scalar GEMM (same semantics) ===========
  float* Af = (float*)(smem + SOFF_TILES);     // [64][130]
  float* Bf = Af + 64 * 130;                   // [64][132]

  u64 acc[4][8];
#pragma unroll
  for (int p = 0; p < 4; p++)
#pragma unroll
    for (int j = 0; j < 8; j++) acc[p][j] = 0ull;

  const int tx = tid & 15, ty = tid >> 4;
  const int m8 = ty * 8, n8 = tx * 8;

  for (int k0 = 0; k0 < K; k0 += TCK) {
    {
      const float* ap = Ab + aidx + k0;
#pragma unroll
      for (int q = 0; q < 8; q++) {
        float4 t = *(const float4*)(ap + q * 4);
        Af[(ahalf + q * 4 + 0) * 130 + arow] = t.x;
        Af[(ahalf + q * 4 + 1) * 130 + arow] = t.y;
        Af[(ahalf + q * 4 + 2) * 130 + arow] = t.z;
        Af[(ahalf + q * 4 + 3) * 130 + arow] = t.w;
      }
    }
    if (!conv_mode) {
      const int p = tid >> 3;
      const int ng = tid & 7;
      const float* bp0 = Bb + (long long)(k0 + 2 * p) * N + n0 + ng * 16;
      const float* bp1 = bp0 + N;
#pragma unroll
      for (int q = 0; q < 4; q++) {
#pragma unroll
        for (int j = 0; j < 4; j++) {
          int nn = n0 + ng * 16 + q * 4 + j;
          Bf[(2 * p) * 132 + ng * 16 + q * 4 + j] = (nn < N) ? bp0[q * 4 + j] : 0.f;
          Bf[(2 * p + 1) * 132 + ng * 16 + q * 4 + j] = (nn < N) ? bp1[q * 4 + j] : 0.f;
        }
      }
    } else {
      const int khalf = (tid & 1) * 32;
      const int nl = tid >> 1;
#pragma unroll
      for (int i = 0; i < 32; i++) {
        int k = k0 + khalf + i;
        int ci = k / 9;
        int rr = k - ci * 9;
        int ky = rr / 3;
        int kx = rr - ky * 3;
        int iy = py + ky - 1, ix = px + kx - 1;
        float v = 0.f;
        if ((unsigned)iy < (unsigned)Himg && (unsigned)ix < (unsigned)Himg)
          v = Bb[(((long long)pb * Cin + ci) << logHW) + (iy << logW) + ix];
        Bf[(khalf + i) * 132 + nl] = v;
      }
    }
    __syncthreads();
#pragma unroll 4
    for (int kk = 0; kk < TCK; kk++) {
      const u64* ar = (const u64*)&Af[kk * 130 + m8];
      u64 a0 = ar[0], a1 = ar[1], a2 = ar[2], a3 = ar[3];
      float4 b40 = *(const float4*)&Bf[kk * 132 + n8];
      float4 b41 = *(const float4*)&Bf[kk * 132 + n8 + 4];
      u64 b[8];
      b[0] = dupf(b40.x); b[1] = dupf(b40.y); b[2] = dupf(b40.z); b[3] = dupf(b40.w);
      b[4] = dupf(b41.x); b[5] = dupf(b41.y); b[6] = dupf(b41.z); b[7] = dupf(b41.w);
#pragma unroll
      for (int j = 0; j < 8; j++) {
        fma2(acc[0][j], a0, b[j]);
        fma2(acc[1][j], a1, b[j]);
        fma2(acc[2][j], a2, b[j]);
        fma2(acc[3][j], a3, b[j]);
      }
    }
    __syncthreads();
  }

  if (!conv_mode) {
#pragma unroll
    for (int p = 0; p < 4; p++) {
      int mlo = m0 + m8 + 2 * p;
#pragma unroll
      for (int j = 0; j < 8; j++) {
        int n = n0 + n8 + j;
        if (n >= N) continue;
        float2 v = unp(acc[p][j]);
        float bsv = biasb[n];
        if (mlo < Mz) {
          float r = v.x + bsv;
          if (relu) r = fmaxf(r, 0.f);
          Cb[(long long)mlo * N + n] = r;
        }
        if (mlo + 1 < Mz) {
          float r = v.y + bsv;
          if (relu) r = fmaxf(r, 0.f);
          Cb[(long long)(mlo + 1) * N + n] = r;
        }
      }
    }
  } else {
    const float rs = rsqrtf(1.00001f);
    const int HWm1 = (1 << logHW) - 1;
#pragma unroll
    for (int p = 0; p < 4; p++) {
      int mlo = m0 + m8 + 2 * p;
      float sc0 = gam[mlo] * rs, cb0 = biasb[mlo], be0 = bet[mlo];
      float sc1 = gam[mlo + 1] * rs, cb1v = biasb[mlo + 1], be1v = bet[mlo + 1];
#pragma unroll
      for (int j = 0; j < 8; j++) {
        int pix = n0 + n8 + j;
        int b = pix >> logHW;
        int pos = pix & HWm1;
        float2 v = unp(acc[p][j]);
        float r0 = fmaxf((v.x + cb0) * sc0 + be0, 0.f);
        float r1 = fmaxf((v.y + cb1v) * sc1 + be1v, 0.f);
        Cb[(((long long)b * M + mlo) << logHW) + pos] = r0;
        Cb[(((long long)b * M + mlo + 1) << logHW) + pos] = r1;
      }
    }
  }
#endif
}

// =================== dense GEMM 128x64x16, f32x2 (small N only) ===============
#define DBM 128
#define DBN 64
#define DBK 16

__global__ __launch_bounds__(256) void gemm_f2(
    const float* __restrict__ A, const float* __restrict__ B,
    const float* __restrict__ bias, float* __restrict__ C,
    int M, int N, int K, int relu) {
  const int n0 = blockIdx.x * DBN;
  const int m0 = blockIdx.y * DBM;

  __shared__ float As[DBK][DBM + 2];
  __shared__ float Bs[DBK][DBN + 4];

  u64 acc[4][4];
#pragma unroll
  for (int p = 0; p < 4; p++)
#pragma unroll
    for (int j = 0; j < 4; j++) acc[p][j] = 0ull;

  const int tid = threadIdx.x;
  const int tx = tid & 15, ty = tid >> 4;

  int rowA[2], kqA[2];
  size_t abase[2];
#pragma unroll
  for (int i = 0; i < 2; i++) {
    int v = tid + i * 256;
    rowA[i] = v >> 2;
    kqA[i] = v & 3;
    abase[i] = (size_t)(m0 + rowA[i]) * K + kqA[i] * 4;
  }
  const int kb = tid >> 4, nb = (tid & 15) * 4;

  for (int k0 = 0; k0 < K; k0 += DBK) {
#pragma unroll
    for (int i = 0; i < 2; i++) {
      float4 a4 = *(const float4*)&A[abase[i] + k0];
      int kk = kqA[i] * 4;
      As[kk + 0][rowA[i]] = a4.x;
      As[kk + 1][rowA[i]] = a4.y;
      As[kk + 2][rowA[i]] = a4.z;
      As[kk + 3][rowA[i]] = a4.w;
    }
    {
      float4 b4;
      size_t bo = (size_t)(k0 + kb) * N + n0 + nb;
      if (n0 + nb + 3 < N) {
        b4 = *(const float4*)&B[bo];
      } else {
        b4.x = (n0 + nb + 0 < N) ? B[bo + 0] : 0.f;
        b4.y = (n0 + nb + 1 < N) ? B[bo + 1] : 0.f;
        b4.z = (n0 + nb + 2 < N) ? B[bo + 2] : 0.f;
        b4.w = (n0 + nb + 3 < N) ? B[bo + 3] : 0.f;
      }
      *(float4*)&Bs[kb][nb] = b4;
    }
    __syncthreads();
#pragma unroll
    for (int kk = 0; kk < DBK; kk++) {
      const u64* arow = (const u64*)&As[kk][0];
      u64 a0 = arow[ty * 4 + 0], a1 = arow[ty * 4 + 1];
      u64 a2 = arow[ty * 4 + 2], a3 = arow[ty * 4 + 3];
      float4 b4 = *(const float4*)&Bs[kk][tx * 4];
      u64 b0 = dupf(b4.x), b1 = dupf(b4.y), b2 = dupf(b4.z), b3 = dupf(b4.w);
      fma2(acc[0][0], a0, b0); fma2(acc[0][1], a0, b1);
      fma2(acc[0][2], a0, b2); fma2(acc[0][3], a0, b3);
      fma2(acc[1][0], a1, b0); fma2(acc[1][1], a1, b1);
      fma2(acc[1][2], a1, b2); fma2(acc[1][3], a1, b3);
      fma2(acc[2][0], a2, b0); fma2(acc[2][1], a2, b1);
      fma2(acc[2][2], a2, b2); fma2(acc[2][3], a2, b3);
      fma2(acc[3][0], a3, b0); fma2(acc[3][1], a3, b1);
      fma2(acc[3][2], a3, b2); fma2(acc[3][3], a3, b3);
    }
    __syncthreads();
  }

#pragma unroll
  for (int p = 0; p < 4; p++) {
    int mlo = m0 + ty * 8 + 2 * p;
#pragma unroll
    for (int j = 0; j < 4; j++) {
      int n = n0 + tx * 4 + j;
      if (n >= N) continue;
      float2 v = unp(acc[p][j]);
      float bsv = bias[n];
      if (mlo < M) {
        float r = v.x + bsv;
        if (relu) r = fmaxf(r, 0.f);
        C[(size_t)mlo * N + n] = r;
      }
      if (mlo + 1 < M) {
        float r = v.y + bsv;
        if (relu) r = fmaxf(r, 0.f);
        C[(size_t)(mlo + 1) * N + n] = r;
      }
    }
  }
}

// ============ implicit-im2col conv 64x128x16 + bias/BN/ReLU (conv1) ===========
#define CBM 64
#define CBN 128
#define CBK 16

__global__ __launch_bounds__(256) void conv_f2(
    const float* __restrict__ in, const float* __restrict__ w,
    const float* __restrict__ cb, const float* __restrict__ gam,
    const float* __restrict__ bet, float* __restrict__ out,
    int Cin, int Cout, int H, int logW, int logHW) {
  const int HW = 1 << logHW;
  const int W = 1 << logW;
  const int Ktot = Cin * 9;
  const int n0 = blockIdx.x * CBN;
  const int m0 = blockIdx.y * CBM;

  __shared__ float As[CBK][CBM + 2];
  __shared__ float Bs[CBK][CBN + 4];

  u64 acc[4][4];
#pragma unroll
  for (int p = 0; p < 4; p++)
#pragma unroll
    for (int j = 0; j < 4; j++) acc[p][j] = 0ull;

  const int tid = threadIdx.x;
  const int tx = tid & 31, ty = tid >> 5;
  const int kB = tid >> 4, nb8 = (tid & 15) * 8;

  for (int k0 = 0; k0 < Ktot; k0 += CBK) {
#pragma unroll
    for (int i = 0; i < 4; i++) {
      int l = tid + i * 256;
      int k = l & 15, m = l >> 4;
      int gk = k0 + k;
      As[k][m] = (gk < Ktot) ? w[(m0 + m) * Ktot + gk] : 0.f;
    }
    {
      int gk = k0 + kB;
      int ci = 0, ky = 0, kx = 0;
      bool kvalid = gk < Ktot;
      if (kvalid) {
        ci = gk / 9;
        int r = gk - ci * 9;
        ky = r / 3;
        kx = r - ky * 3;
      }
      const float* inp = in + (size_t)ci * HW;
#pragma unroll
      for (int jj = 0; jj < 8; jj++) {
        int gn = n0 + nb8 + jj;
        float v = 0.f;
        if (kvalid) {
          int b = gn >> logHW;
          int pos = gn & (HW - 1);
          int y = pos >> logW, x = pos & (W - 1);
          int iy = y + ky - 1, ix = x + kx - 1;
          if ((unsigned)iy < (unsigned)H && (unsigned)ix < (unsigned)H)
            v = inp[((size_t)b * Cin << logHW) + (iy << logW) + ix];
        }
        Bs[kB][nb8 + jj] = v;
      }
    }
    __syncthreads();
#pragma unroll
    for (int kk = 0; kk < CBK; kk++) {
      const u64* arow = (const u64*)&As[kk][0];
      u64 a0 = arow[ty * 4 + 0], a1 = arow[ty * 4 + 1];
      u64 a2 = arow[ty * 4 + 2], a3 = arow[ty * 4 + 3];
      float4 b4 = *(const float4*)&Bs[kk][tx * 4];
      u64 b0 = dupf(b4.x), b1 = dupf(b4.y), b2 = dupf(b4.z), b3 = dupf(b4.w);
      fma2(acc[0][0], a0, b0); fma2(acc[0][1], a0, b1);
      fma2(acc[0][2], a0, b2); fma2(acc[0][3], a0, b3);
      fma2(acc[1][0], a1, b0); fma2(acc[1][1], a1, b1);
      fma2(acc[1][2], a1, b2); fma2(acc[1][3], a1, b3);
      fma2(acc[2][0], a2, b0); fma2(acc[2][1], a2, b1);
      fma2(acc[2][2], a2, b2); fma2(acc[2][3], a2, b3);
      fma2(acc[3][0], a3, b0); fma2(acc[3][1], a3, b1);
      fma2(acc[3][2], a3, b2); fma2(acc[3][3], a3, b3);
    }
    __syncthreads();
  }

  const float rs = rsqrtf(1.00001f);
#pragma unroll
  for (int p = 0; p < 4; p++) {
    int mlo = m0 + ty * 8 + 2 * p;
    float sc0 = gam[mlo] * rs, cb0 = cb[mlo], be0 = bet[mlo];
    float sc1 = gam[mlo + 1] * rs, cb1v = cb[mlo + 1], be1v = bet[mlo + 1];
#pragma unroll
    for (int j = 0; j < 4; j++) {
      int gn = n0 + tx * 4 + j;
      int b = gn >> logHW;
      int pos = gn & (HW - 1);
      float2 v = unp(acc[p][j]);
      float r0 = fmaxf((v.x + cb0) * sc0 + be0, 0.f);
      float r1 = fmaxf((v.y + cb1v) * sc1 + be1v, 0.f);
      out[((size_t)(b * Cout + mlo) << logHW) + pos] = r0;
      out[((size_t)(b * Cout + mlo + 1) << logHW) + pos] = r1;
    }
  }
}

// ---------------- 2x2 max pool (stride 2) ----------------
__global__ void pool_kernel(const float* __restrict__ in, float* __restrict__ out,
                            int C, int H) {
  int Hp = H >> 1;
  int total = BATCH * C * Hp * Hp;
  int idx = blockIdx.x * blockDim.x + threadIdx.x;
  if (idx >= total) return;
  int px = idx % Hp;
  int t = idx / Hp;
  int py = t % Hp; t /= Hp;
  int c = t % C;
  int b = t / C;
  const float* p = in + ((size_t)(b * C + c) * H + py * 2) * H + px * 2;
  out[idx] = fmaxf(fmaxf(p[0], p[1]), fmaxf(p[H], p[H + 1]));
}

// ---------------- noisy top-k gating (per row) ----------------
__global__ void gating_kernel(const float* __restrict__ clean,
                              const float* __restrict__ rawstd,
                              const float* __restrict__ noise,
                              float* __restrict__ gates, float* __restrict__ prob) {
  int b = blockIdx.x * blockDim.x + threadIdx.x;
  if (b >= BATCH) return;
  float c[NEXP], sd[NEXP], nz[NEXP];
#pragma unroll
  for (int e = 0; e < NEXP; e++) {
    c[e] = clean[b * NEXP + e];
    float rsv = rawstd[b * NEXP + e];
    float sp = (rsv > 20.f) ? rsv : log1pf(expf(rsv));
    sd[e] = sp + 0.01f;
    nz[e] = c[e] + noise[b * NEXP + e] * sd[e];
  }
  int i0 = 0; float v0 = nz[0];
#pragma unroll
  for (int e = 1; e < NEXP; e++) if (nz[e] > v0) { v0 = nz[e]; i0 = e; }
  int i1 = -1; float v1 = -1e30f;
#pragma unroll
  for (int e = 0; e < NEXP; e++) if (e != i0 && nz[e] > v1) { v1 = nz[e]; i1 = e; }
  float v2 = -1e30f;
#pragma unroll
  for (int e = 0; e < NEXP; e++) if (e != i0 && e != i1 && nz[e] > v2) v2 = nz[e];

  float e1 = expf(v1 - v0);
  float inv = 1.f / (1.f + e1);
  const float kInvSqrt2 = 0.70710678118654752440f;
#pragma unroll
  for (int e = 0; e < NEXP; e++) {
    float g = (e == i0) ? inv : ((e == i1) ? e1 * inv : 0.f);
    gates[b * NEXP + e] = g;
    float th = (nz[e] > v2) ? v2 : v1;
    float zz = (c[e] - th) / sd[e];
    prob[b * NEXP + e] = 0.5f * (1.f + erff(zz * kInvSqrt2));
  }
}

// -------- deterministic dispatch build (1 block, warp per expert) --------
__global__ void build_dispatch(const float* __restrict__ gates,
                               int* __restrict__ rowlist, int* __restrict__ cnt,
                               int* __restrict__ rowslot,
                               float* __restrict__ slotgate) {
  int w = threadIdx.x >> 5;
  int lane = threadIdx.x & 31;
  int c = 0;
  for (int base = 0; base < BATCH; base += 32) {
    int b = base + lane;
    float g = gates[b * NEXP + w];
    unsigned mask = __ballot_sync(0xffffffffu, g > 0.f);
    if (g > 0.f) {
      int pos = c + __popc(mask & ((1u << lane) - 1u));
      int slot = w * BATCH + pos;
      rowlist[slot] = b;
      slotgate[slot] = g;
      int m8 = 0;
#pragma unroll
      for (int e = 0; e < NEXP; e++) m8 |= (gates[b * NEXP + e] > 0.f) ? (1 << e) : 0;
      int j = __popc(m8 & ((1 << w) - 1));
      rowslot[b * 2 + j] = slot;
    }
    c += __popc(mask);
  }
  if (lane == 0) cnt[w] = c;
}

// ---------------- deterministic per-expert reductions ----------------
__global__ void moe_reduce_kernel(const float* __restrict__ gates,
                                  const float* __restrict__ prob,
                                  float* __restrict__ imp, float* __restrict__ loadv) {
  int e = blockIdx.x;
  int t = threadIdx.x;
  __shared__ float s1[256], s2[256];
  float a = 0.f, b = 0.f;
  for (int i = t; i < BATCH; i += 256) {
    a += gates[i * NEXP + e];
    b += prob[i * NEXP + e];
  }
  s1[t] = a; s2[t] = b;
  __syncthreads();
  for (int s = 128; s > 0; s >>= 1) {
    if (t < s) { s1[t] += s1[t + s]; s2[t] += s2[t + s]; }
    __syncthreads();
  }
  if (t == 0) { imp[e] = s1[0]; loadv[e] = s2[0]; }
}

__global__ void loss_kernel(const float* __restrict__ imp,
                            const float* __restrict__ loadv,
                            float* __restrict__ out) {
  float m1 = 0.f, m2 = 0.f;
  for (int e = 0; e < NEXP; e++) { m1 += imp[e]; m2 += loadv[e]; }
  m1 *= 0.125f; m2 *= 0.125f;
  float v1 = 0.f, v2 = 0.f;
  for (int e = 0; e < NEXP; e++) {
    float d1 = imp[e] - m1; v1 += d1 * d1;
    float d2 = loadv[e] - m2; v2 += d2 * d2;
  }
  v1 /= 7.f; v2 /= 7.f;
  out[0] = v1 / (m1 * m1 + 1e-10f) + v2 / (m2 * m2 + 1e-10f);
}

// ------------- slot-based combine: y[b,c] = g0*eo[s0,c]+g1*eo[s1,c] ----------
__global__ void combine2_kernel(const int* __restrict__ rowslot,
                                const float* __restrict__ slotgate,
                                const float* __restrict__ eo,
                                float* __restrict__ y) {
  int idx = blockIdx.x * blockDim.x + threadIdx.x;
  if (idx >= BATCH * NCLS) return;
  int b = idx / NCLS;
  int c = idx - b * NCLS;
  int s0 = rowslot[b * 2 + 0], s1 = rowslot[b * 2 + 1];
  y[idx] = slotgate[s0] * eo[(size_t)s0 * NCLS + c] +
           slotgate[s1] * eo[(size_t)s1 * NCLS + c];
}

// ================================ launch ======================================
extern "C" void kernel_launch(void* const* d_in, const int* in_sizes, int n_in,
                              void* d_out, int out_size) {
  const float* x    = (const float*)d_in[0];
  const float* noise= (const float*)d_in[1];
  const float* cw1 = (const float*)d_in[2],  *cb1 = (const float*)d_in[3];
  const float* g1  = (const float*)d_in[4],  *be1 = (const float*)d_in[5];
  const float* cw2 = (const float*)d_in[6],  *cb2 = (const float*)d_in[7];
  const float* g2  = (const float*)d_in[8],  *be2 = (const float*)d_in[9];
  const float* cw3 = (const float*)d_in[10], *cb3 = (const float*)d_in[11];
  const float* g3  = (const float*)d_in[12], *be3 = (const float*)d_in[13];
  const float* cw4 = (const float*)d_in[14], *cb4 = (const float*)d_in[15];
  const float* g4  = (const float*)d_in[16], *be4 = (const float*)d_in[17];
  const float* wg1 = (const float*)d_in[18], *wg1b= (const float*)d_in[19];
  const float* wg2 = (const float*)d_in[20], *wg2b= (const float*)d_in[21];
  const float* wn1 = (const float*)d_in[22], *wn1b= (const float*)d_in[23];
  const float* wn2 = (const float*)d_in[24], *wn2b= (const float*)d_in[25];
  const float* eW1 = (const float*)d_in[26], *eb1 = (const float*)d_in[27];
  const float* eW2 = (const float*)d_in[28], *eb2 = (const float*)d_in[29];
  const float* eW3 = (const float*)d_in[30], *eb3 = (const float*)d_in[31];

  float *convout, *poolA, *poolB, *hid, *clean, *rawstd, *gates, *prob;
  float *eh, *eh2, *eo, *imp, *loadv, *slotgate;
  int *rowlist, *cnt, *rowslot;
  cudaGetSymbolAddress((void**)&convout, g_convout);
  cudaGetSymbolAddress((void**)&poolA, g_poolA);
  cudaGetSymbolAddress((void**)&poolB, g_poolB);
  cudaGetSymbolAddress((void**)&hid, g_hid);
  cudaGetSymbolAddress((void**)&clean, g_clean);
  cudaGetSymbolAddress((void**)&rawstd, g_rawstd);
  cudaGetSymbolAddress((void**)&gates, g_gates);
  cudaGetSymbolAddress((void**)&prob, g_prob);
  cudaGetSymbolAddress((void**)&eh, g_eh);
  cudaGetSymbolAddress((void**)&eh2, g_eh2);
  cudaGetSymbolAddress((void**)&eo, g_eo);
  cudaGetSymbolAddress((void**)&imp, g_imp);
  cudaGetSymbolAddress((void**)&loadv, g_load);
  cudaGetSymbolAddress((void**)&rowlist, g_rowlist);
  cudaGetSymbolAddress((void**)&cnt, g_cnt);
  cudaGetSymbolAddress((void**)&rowslot, g_rowslot);
  cudaGetSymbolAddress((void**)&slotgate, g_slotgate);

  float* out = (float*)d_out;

  cudaFuncSetAttribute(tc_gemm, cudaFuncAttributeMaxDynamicSharedMemorySize, SMEM_TC);

  // ---- conv1 (scalar) + pool ----
  conv_f2<<<dim3(BATCH * 1024 / CBN, 1), 256>>>(x, cw1, cb1, g1, be1, convout, 3, 64, 32, 5, 10);
  pool_kernel<<<(BATCH * 64 * 256 + 255) / 256, 256>>>(convout, poolA, 64, 32);

  // ---- conv2-4 (tc_gemm bf16x3) + pools ----
  tc_gemm<<<dim3(BATCH * 256 / TCN, 1, 1), 256, SMEM_TC>>>(
      cw2, poolA, cb2, convout, 128, BATCH * 256, 576, 1,
      0, 0, 0, 0, 0, 0, 1, 64, 16, 4, 8, g2, be2);
  pool_kernel<<<(BATCH * 128 * 64 + 255) / 256, 256>>>(convout, poolB, 128, 16);

  tc_gemm<<<dim3(BATCH * 64 / TCN, 2, 1), 256, SMEM_TC>>>(
      cw3, poolB, cb3, convout, 256, BATCH * 64, 1152, 1,
      0, 0, 0, 0, 0, 0, 1, 128, 8, 3, 6, g3, be3);
  pool_kernel<<<(BATCH * 256 * 16 + 255) / 256, 256>>>(convout, poolA, 256, 8);

  tc_gemm<<<dim3(BATCH * 16 / TCN, 4, 1), 256, SMEM_TC>>>(
      cw4, poolA, cb4, convout, 512, BATCH * 16, 2304, 1,
      0, 0, 0, 0, 0, 0, 1, 256, 4, 2, 4, g4, be4);
  pool_kernel<<<(BATCH * 512 * 4 + 255) / 256, 256>>>(convout, poolB, 512, 4);

  const float* f = poolB;  // [2048, 2048]

  // ---- gating nets (big GEMMs via tc_gemm, tiny N=8 scalar) ----
  tc_gemm<<<dim3(GATEH / TCN, BATCH / TCM, 1), 256, SMEM_TC>>>(
      f, wg1, wg1b, hid, BATCH, GATEH, FEAT, 1,
      0, 0, 0, 0, 0, 0, 0, 0, 0, 0, 0, 0, 0);
  gemm_f2<<<dim3(1, BATCH / DBM, 1), 256>>>(hid, wg2, wg2b, clean, BATCH, NEXP, GATEH, 0);
  tc_gemm<<<dim3(GATEH / TCN, BATCH / TCM, 1), 256, SMEM_TC>>>(
      f, wn1, wn1b, hid, BATCH, GATEH, FEAT, 1,
      0, 0, 0, 0, 0, 0, 0, 0, 0, 0, 0, 0, 0);
  gemm_f2<<<dim3(1, BATCH / DBM, 1), 256>>>(hid, wn2, wn2b, rawstd, BATCH, NEXP, GATEH, 0);

  gating_kernel<<<BATCH / 256, 256>>>(clean, rawstd, noise, gates, prob);
  build_dispatch<<<1, 256>>>(gates, rowlist, cnt, rowslot, slotgate);
  moe_reduce_kernel<<<NEXP, 256>>>(gates, prob, imp, loadv);

  // ---- sparse experts (capacity grid + early-exit) ----
  tc_gemm<<<dim3(HID / TCN, BATCH / TCM, NEXP), 256, SMEM_TC>>>(
      f, eW1, eb1, eh, BATCH, HID, FEAT, 1,
      0, (long long)FEAT * HID, HID, (long long)BATCH * HID,
      rowlist, cnt, 0, 0, 0, 0, 0, 0, 0);
  tc_gemm<<<dim3((HID / 2) / TCN, BATCH / TCM, NEXP), 256, SMEM_TC>>>(
      eh, eW2, eb2, eh2, BATCH, HID / 2, HID, 1,
      (long long)BATCH * HID, (long long)HID * (HID / 2), HID / 2,
      (long long)BATCH * (HID / 2), 0, cnt, 0, 0, 0, 0, 0, 0, 0);
  tc_gemm<<<dim3(1, BATCH / TCM, NEXP), 256, SMEM_TC>>>(
      eh2, eW3, eb3, eo, BATCH, NCLS, HID / 2, 0,
      (long long)BATCH * (HID / 2), (long long)(HID / 2) * NCLS, NCLS,
      (long long)BATCH * NCLS, 0, cnt, 0, 0, 0, 0, 0, 0, 0);

  // ---- outputs ----
  combine2_kernel<<<(BATCH * NCLS + 255) / 256, 256>>>(rowslot, slotgate, eo, out);
  if (out_size >= BATCH * NCLS + 1)
    loss_kernel<<<1, 1>>>(imp, loadv, out + BATCH * NCLS);
}

// round 7
// speedup vs baseline: 1.8568x; 1.1800x over previous
#include <cuda_runtime.h>
#include <cuda_bf16.h>
#include <math.h>
#include <stdint.h>

#define BATCH 2048
#define NEXP 8
#define NCLS 100
#define HID 1024
#define GATEH 2048
#define FEAT 2048

typedef unsigned long long u64;

#if defined(__CUDA_ARCH_FEAT_SM103_ALL) || defined(__CUDA_ARCH_FEAT_SM100_ALL) || \
    defined(__CUDA_ARCH_FEAT_SM101_ALL) ||                                        \
    (defined(__CUDA_ARCH_SPECIFIC__) && (__CUDA_ARCH_SPECIFIC__ > 0))
#define HAS_TC 1
#else
#define HAS_TC 0
#endif

// ---------------- scratch (device globals; no allocation allowed) -------------
__device__ float g_convout[134217728];
__device__ float g_poolA[33554432];
__device__ float g_poolB[16777216];
__device__ float g_hid[BATCH * GATEH];
__device__ float g_clean[BATCH * NEXP];
__device__ float g_rawstd[BATCH * NEXP];
__device__ float g_gates[BATCH * NEXP];
__device__ float g_prob[BATCH * NEXP];
__device__ float g_eh[(size_t)NEXP * BATCH * HID];
__device__ float g_eh2[(size_t)NEXP * BATCH * (HID / 2)];
__device__ float g_eo[(size_t)NEXP * BATCH * NCLS];
__device__ float g_imp[NEXP];
__device__ float g_load[NEXP];
__device__ int   g_rowlist[NEXP * BATCH];
__device__ int   g_cnt[NEXP];
__device__ int   g_rowslot[BATCH * 2];
__device__ float g_slotgate[NEXP * BATCH];

// ========================== common helpers ====================================
__device__ __forceinline__ uint32_t smem_u32(const void* p) {
  uint32_t a;
  asm("{ .reg .u64 t; cvta.to.shared.u64 t, %1; cvt.u32.u64 %0, t; }"
      : "=r"(a) : "l"(p));
  return a;
}

#define SW128(o) ((o) ^ (((o) >> 3) & 0x70))

__device__ __forceinline__ u64 dupf(float v) {
  u64 r; asm("mov.b64 %0, {%1, %1};" : "=l"(r) : "f"(v)); return r;
}
__device__ __forceinline__ void fma2(u64& d, u64 a, u64 b) {
  asm("fma.rn.f32x2 %0, %1, %2, %0;" : "+l"(d) : "l"(a), "l"(b));
}
__device__ __forceinline__ float2 unp(u64 v) {
  float2 f; asm("mov.b64 {%0, %1}, %2;" : "=f"(f.x), "=f"(f.y) : "l"(v)); return f;
}

// bf16 2-way split of two consecutive k values, packed into u32
__device__ __forceinline__ void bsplit2(float x0, float x1, uint32_t& hi, uint32_t& lo) {
  __nv_bfloat16 h0 = __float2bfloat16_rn(x0);
  __nv_bfloat16 h1 = __float2bfloat16_rn(x1);
  __nv_bfloat16 l0 = __float2bfloat16_rn(x0 - __bfloat162float(h0));
  __nv_bfloat16 l1 = __float2bfloat16_rn(x1 - __bfloat162float(h1));
  __nv_bfloat162 H; H.x = h0; H.y = h1;
  __nv_bfloat162 L; L.x = l0; L.y = l1;
  hi = *(uint32_t*)&H;
  lo = *(uint32_t*)&L;
}

#if HAS_TC
#define TC_ALLOC(sa, n) \
  asm volatile("tcgen05.alloc.cta_group::1.sync.aligned.shared::cta.b32 [%0], %1;" \
               :: "r"(sa), "r"(n) : "memory")
#define TC_DEALLOC(t, n) \
  asm volatile("tcgen05.dealloc.cta_group::1.sync.aligned.b32 %0, %1;" :: "r"(t), "r"(n))
#define TC_RELINQ() \
  asm volatile("tcgen05.relinquish_alloc_permit.cta_group::1.sync.aligned;")
#define TC_COMMIT(mb) \
  asm volatile("tcgen05.commit.cta_group::1.mbarrier::arrive::one.shared::cluster.b64 [%0];" \
               :: "r"(mb) : "memory")
#define TC_FENCE_AFTER()  asm volatile("tcgen05.fence::after_thread_sync;" ::: "memory")
#define TC_FENCE_BEFORE() asm volatile("tcgen05.fence::before_thread_sync;" ::: "memory")
#define TC_WAIT_LD()      asm volatile("tcgen05.wait::ld.sync.aligned;" ::: "memory")
#define FENCE_ASYNC()     asm volatile("fence.proxy.async.shared::cta;" ::: "memory")
#define MB_INIT(mb, n) \
  asm volatile("mbarrier.init.shared.b64 [%0], %1;" :: "r"(mb), "r"(n) : "memory")

#define MB_WAIT(mbar_addr, ph) do { \
  uint32_t _mb = (uint32_t)(mbar_addr); \
  uint32_t _p = (uint32_t)(ph); \
  asm volatile( \
      "{\n\t.reg .pred P1;\n\t" \
      "WAIT_LOOP_%=:\n\t" \
      "mbarrier.try_wait.parity.acquire.cta.shared::cta.b64 P1, [%0], %1, 0x989680;\n\t" \
      "@P1 bra.uni WAIT_DONE_%=;\n\t" \
      "bra.uni WAIT_LOOP_%=;\n\t" \
      "WAIT_DONE_%=:\n\t}" \
      :: "r"(_mb), "r"(_p) : "memory"); \
} while (0)

#define TC_LD_X32(r, ta) \
  asm volatile( \
      "tcgen05.ld.sync.aligned.32x32b.x32.b32 " \
      "{%0, %1, %2, %3, %4, %5, %6, %7, " \
      " %8, %9, %10, %11, %12, %13, %14, %15, " \
      " %16, %17, %18, %19, %20, %21, %22, %23, " \
      " %24, %25, %26, %27, %28, %29, %30, %31}, [%32];" \
      : "=r"((r)[0]),  "=r"((r)[1]),  "=r"((r)[2]),  "=r"((r)[3]), \
        "=r"((r)[4]),  "=r"((r)[5]),  "=r"((r)[6]),  "=r"((r)[7]), \
        "=r"((r)[8]),  "=r"((r)[9]),  "=r"((r)[10]), "=r"((r)[11]), \
        "=r"((r)[12]), "=r"((r)[13]), "=r"((r)[14]), "=r"((r)[15]), \
        "=r"((r)[16]), "=r"((r)[17]), "=r"((r)[18]), "=r"((r)[19]), \
        "=r"((r)[20]), "=r"((r)[21]), "=r"((r)[22]), "=r"((r)[23]), \
        "=r"((r)[24]), "=r"((r)[25]), "=r"((r)[26]), "=r"((r)[27]), \
        "=r"((r)[28]), "=r"((r)[29]), "=r"((r)[30]), "=r"((r)[31]) \
      : "r"(ta))

__device__ __forceinline__ uint64_t mkdesc(uint32_t addr) {
  return ((uint64_t)2 << 61) | ((uint64_t)1 << 46) | ((uint64_t)64 << 32) |
         ((uint64_t)1 << 16) | ((addr >> 4) & 0x3FFF);
}

__device__ __forceinline__ void mma_bf16(uint32_t d, uint64_t ad, uint64_t bd,
                                         uint32_t idesc, uint32_t en) {
  asm volatile(
      "{\n\t.reg .pred p;\n\tsetp.ne.u32 p, %5, 0;\n\t"
      "tcgen05.mma.cta_group::1.kind::f16 [%0], %1, %2, %3, {%4, %4, %4, %4}, p;\n\t}"
      :: "r"(d), "l"(ad), "l"(bd), "r"(idesc), "r"(0u), "r"(en) : "memory");
}
#endif  // HAS_TC

__device__ __forceinline__ void sts128u(uint32_t addr, uint32_t a, uint32_t b,
                                        uint32_t c, uint32_t d) {
  asm volatile("st.shared.v4.b32 [%0], {%1, %2, %3, %4};"
               :: "r"(addr), "r"(a), "r"(b), "r"(c), "r"(d) : "memory");
}
__device__ __forceinline__ void sts32u(uint32_t addr, uint32_t v) {
  asm volatile("st.shared.b32 [%0], %1;" :: "r"(addr), "r"(v) : "memory");
}
__device__ __forceinline__ float lds32f(uint32_t addr) {
  float v;
  asm volatile("ld.shared.b32 %0, [%1];" : "=f"(v) : "r"(addr));
  return v;
}

// ================= unified GEMM (128x128 tile, bf16x3, Kc=64) =================
// conv_mode=1 additionally fuses bias+BN+ReLU and 2x2 maxpool into the epilogue
// (output written POOLED, NCHW).
#define TCM 128
#define TCN 128
#define TCK 64
#define TC_TILE 16384
#define TC_STAGE (4 * TC_TILE)
#define SOFF_MBAR 16
#define SOFF_TILES 1024
#define SMEM_TC (SOFF_TILES + 2 * TC_STAGE)

__global__ void __launch_bounds__(256, 1) tc_gemm(
    const float* __restrict__ A, const float* __restrict__ Bm,
    const float* __restrict__ bias, float* __restrict__ C,
    int M, int N, int K, int relu,
    long long sA, long long sB, long long sBias, long long sC,
    const int* __restrict__ rowlist, const int* __restrict__ cnt,
    int conv_mode, int Cin, int Himg, int logW, int logHW,
    const float* __restrict__ gam, const float* __restrict__ bet) {
  extern __shared__ char smem[];
  const int z = blockIdx.z;
  const int Mz = cnt ? cnt[z] : M;
  const int m0 = blockIdx.y * TCM;
  if (m0 >= Mz) return;
  const int n0 = blockIdx.x * TCN;

  const float* Ab = A + (long long)z * sA;
  const float* Bb = Bm + (long long)z * sB;
  const float* biasb = bias + (long long)z * sBias;
  float* Cb = C + (long long)z * sC;
  const int* rl = rowlist ? rowlist + z * BATCH : (const int*)0;

  const int tid = threadIdx.x;
  const int wid = tid >> 5, lane = tid & 31;

  // A staging: thread -> (row, 32-k half)
  const int arow = tid >> 1;
  const int ahalf = (tid & 1) * 32;
  long long aidx;
  {
    int gm = m0 + arow;
    int r_ = (gm < Mz) ? gm : 0;
    if (rl) r_ = (gm < Mz) ? rl[gm] : 0;
    aidx = (long long)r_ * K + ahalf;
  }

  // conv pixel coords (B staging: thread -> (pixel, 32-k half))
  int pb = 0, py = 0, px = 0;
  if (conv_mode) {
    int gn = n0 + (tid >> 1);
    pb = gn >> logHW;
    int pos = gn & ((1 << logHW) - 1);
    py = pos >> logW;
    px = pos & ((1 << logW) - 1);
  }

#if HAS_TC
  // ======================= tcgen05 bf16x3 path ================================
  const uint32_t sbase = smem_u32(smem);
  if (wid == 0) TC_ALLOC(sbase, 128);
  if (tid == 0) { MB_INIT(sbase + SOFF_MBAR, 1); MB_INIT(sbase + SOFF_MBAR + 8, 1); }
  __syncthreads();
  uint32_t tmem;
  asm volatile("ld.shared.b32 %0, [%1];" : "=r"(tmem) : "r"(sbase));

  const int nchunks = K / TCK;
  int phase0 = 0, phase1 = 0;
  const uint32_t idesc =
      (1u << 4) | (1u << 7) | (1u << 10) | ((TCN / 8) << 17) | ((TCM / 16) << 24);

  for (int c = 0; c < nchunks; c++) {
    const int s = c & 1;
    const uint32_t stg = sbase + SOFF_TILES + s * TC_STAGE;
    const uint32_t sAhi = stg, sAlo = stg + TC_TILE;
    const uint32_t sBhi = stg + 2 * TC_TILE, sBlo = stg + 3 * TC_TILE;
    if (c >= 2) {
      if (s == 0) { MB_WAIT(sbase + SOFF_MBAR, phase0); phase0 ^= 1; }
      else        { MB_WAIT(sbase + SOFF_MBAR + 8, phase1); phase1 ^= 1; }
    }
    const int k0 = c * TCK;

    // ---- stage A (128 x 64 k): bf16 hi/lo, SW128 K-major ----
    {
      const float* ap = Ab + aidx + k0;
      uint32_t ha[16], la[16];
#pragma unroll
      for (int q = 0; q < 8; q++) {
        float4 t = *(const float4*)(ap + q * 4);
        bsplit2(t.x, t.y, ha[q * 2 + 0], la[q * 2 + 0]);
        bsplit2(t.z, t.w, ha[q * 2 + 1], la[q * 2 + 1]);
      }
      const uint32_t ro = arow * 128 + ahalf * 2;
#pragma unroll
      for (int q = 0; q < 4; q++) {
        uint32_t off = SW128(ro + q * 16);
        sts128u(sAhi + off, ha[q * 4], ha[q * 4 + 1], ha[q * 4 + 2], ha[q * 4 + 3]);
        sts128u(sAlo + off, la[q * 4], la[q * 4 + 1], la[q * 4 + 2], la[q * 4 + 3]);
      }
    }

    // ---- stage B (128 n x 64 k), row-wise (conflict-free) ----
    if (!conv_mode) {
      // dense weights [K][N]: thread -> (n-row, 32-k half); k-strided coalesced loads
      const int nrow = tid >> 1;
      const int khalf = (tid & 1) * 32;
      const int nr = (n0 + nrow < N) ? nrow : 0;  // clamp (cols >= N discarded later)
      const float* bp = Bb + (long long)(k0 + khalf) * N + n0 + nr;
      uint32_t hb[16], lb[16];
#pragma unroll
      for (int i = 0; i < 32; i += 2) {
        float v0 = bp[(long long)i * N];
        float v1 = bp[(long long)(i + 1) * N];
        bsplit2(v0, v1, hb[i / 2], lb[i / 2]);
      }
      const uint32_t ro = nrow * 128 + khalf * 2;
#pragma unroll
      for (int q = 0; q < 4; q++) {
        uint32_t off = SW128(ro + q * 16);
        sts128u(sBhi + off, hb[q * 4], hb[q * 4 + 1], hb[q * 4 + 2], hb[q * 4 + 3]);
        sts128u(sBlo + off, lb[q * 4], lb[q * 4 + 1], lb[q * 4 + 2], lb[q * 4 + 3]);
      }
    } else {
      // im2col gather: row = pixel, 32 k per thread
      const int khalf = (tid & 1) * 32;
      const int nl = tid >> 1;
      uint32_t hb[16], lb[16];
#pragma unroll
      for (int i = 0; i < 32; i += 2) {
        float v[2];
#pragma unroll
        for (int d = 0; d < 2; d++) {
          int k = k0 + khalf + i + d;
          int ci = k / 9;
          int rr = k - ci * 9;
          int ky = rr / 3;
          int kx = rr - ky * 3;
          int iy = py + ky - 1, ix = px + kx - 1;
          v[d] = 0.f;
          if ((unsigned)iy < (unsigned)Himg && (unsigned)ix < (unsigned)Himg)
            v[d] = Bb[(((long long)pb * Cin + ci) << logHW) + (iy << logW) + ix];
        }
        bsplit2(v[0], v[1], hb[i / 2], lb[i / 2]);
      }
      const uint32_t ro = nl * 128 + khalf * 2;
#pragma unroll
      for (int q = 0; q < 4; q++) {
        uint32_t off = SW128(ro + q * 16);
        sts128u(sBhi + off, hb[q * 4], hb[q * 4 + 1], hb[q * 4 + 2], hb[q * 4 + 3]);
        sts128u(sBlo + off, lb[q * 4], lb[q * 4 + 1], lb[q * 4 + 2], lb[q * 4 + 3]);
      }
    }

    FENCE_ASYNC();
    __syncthreads();

    if (tid == 0) {
      uint64_t dAh = mkdesc(sAhi), dAl = mkdesc(sAlo);
      uint64_t dBh = mkdesc(sBhi), dBl = mkdesc(sBlo);
#pragma unroll
      for (int i = 0; i < 4; i++)
        mma_bf16(tmem, dAh + 2 * i, dBh + 2 * i, idesc, (c > 0) | (i > 0));
#pragma unroll
      for (int i = 0; i < 4; i++)
        mma_bf16(tmem, dAh + 2 * i, dBl + 2 * i, idesc, 1u);
#pragma unroll
      for (int i = 0; i < 4; i++)
        mma_bf16(tmem, dAl + 2 * i, dBh + 2 * i, idesc, 1u);
      TC_COMMIT(sbase + SOFF_MBAR + 8 * s);
    }
  }

  MB_WAIT(sbase + SOFF_MBAR, phase0);
  if (nchunks > 1) MB_WAIT(sbase + SOFF_MBAR + 8, phase1);
  TC_FENCE_AFTER();

  // ---- epilogue with smem transpose (coalesced global stores) ----
  if (wid < 4) {
    const int m_loc = wid * 32 + lane;
    const int m = m0 + m_loc;
    float sc = 0.f, cbv = 0.f, bev = 0.f;
    if (conv_mode) { sc = gam[m] * rsqrtf(1.00001f); cbv = biasb[m]; bev = bet[m]; }
    const uint32_t Tbase = sbase + SOFF_TILES;
    // 4 groups of 32 cols -> separate T buffers (128 x 33 floats each)
#pragma unroll 1
    for (int g = 0; g < 4; g++) {
      uint32_t r[32];
      TC_LD_X32(r, tmem + g * 32);
      TC_WAIT_LD();
      uint32_t Tg = Tbase + (uint32_t)g * (128 * 33 * 4);
#pragma unroll
      for (int j = 0; j < 32; j++) {
        float v = __uint_as_float(r[j]);
        if (conv_mode) v = fmaxf((v + cbv) * sc + bev, 0.f);
        sts32u(Tg + (uint32_t)(m_loc * 33 + j) * 4, __float_as_uint(v));
      }
    }
    TC_FENCE_BEFORE();
    asm volatile("bar.sync 1, 128;" ::: "memory");

    if (!conv_mode) {
#pragma unroll 1
      for (int g = 0; g < 4; g++) {
        uint32_t Tg = Tbase + (uint32_t)g * (128 * 33 * 4);
        int n = n0 + g * 32 + lane;
        float bn = (n < N) ? biasb[n] : 0.f;
        bool nok = (n < N);
#pragma unroll 4
        for (int rr = 0; rr < 32; rr++) {
          int mm = m0 + wid * 32 + rr;
          float v = lds32f(Tg + (uint32_t)((wid * 32 + rr) * 33 + lane) * 4);
          v += bn;
          if (relu) v = fmaxf(v, 0.f);
          if (nok && mm < Mz) Cb[(long long)mm * N + n] = v;
        }
      }
    } else {
      // fused 2x2 maxpool; output written pooled NCHW
      const int HWm1 = (1 << logHW) - 1;
      const int W = 1 << logW;
#pragma unroll 1
      for (int g = 0; g < 4; g++) {
        uint32_t Tg = Tbase + (uint32_t)g * (128 * 33 * 4);
        int pix = n0 + g * 32 + lane;
        int b = pix >> logHW;
        int pos = pix & HWm1;
        bool wsel = ((pos & 1) == 0) && (((pos >> logW) & 1) == 0);
        int poff = ((pos >> (logW + 1)) << (logW - 1)) + ((pos & (W - 1)) >> 1);
        long long obase = ((long long)b * M) << (logHW - 2);
#pragma unroll 4
        for (int rr = 0; rr < 32; rr++) {
          int mm = m0 + wid * 32 + rr;
          float v = lds32f(Tg + (uint32_t)((wid * 32 + rr) * 33 + lane) * 4);
          float vx = fmaxf(v, __shfl_xor_sync(0xffffffffu, v, 1));
          float vy = fmaxf(vx, __shfl_xor_sync(0xffffffffu, vx, W));
          if (wsel)
            Cb[obase + (((long long)mm) << (logHW - 2)) + poff] = vy;
        }
      }
    }
  }
  __syncthreads();
  if (wid == 0) { TC_RELINQ(); TC_DEALLOC(tmem, 128); }

#else
  // ================== fallback: f32x2 scalar GEMM (same semantics) ===========
  float* Af = (float*)(smem + SOFF_TILES);     // [64][130]
  float* Bf = Af + 64 * 130;                   // [64][132]

  u64 acc[4][8];
#pragma unroll
  for (int p = 0; p < 4; p++)
#pragma unroll
    for (int j = 0; j < 8; j++) acc[p][j] = 0ull;

  const int tx = tid & 15, ty = tid >> 4;
  const int m8 = ty * 8, n8 = tx * 8;

  for (int k0 = 0; k0 < K; k0 += TCK) {
    {
      const float* ap = Ab + aidx + k0;
#pragma unroll
      for (int q = 0; q < 8; q++) {
        float4 t = *(const float4*)(ap + q * 4);
        Af[(ahalf + q * 4 + 0) * 130 + arow] = t.x;
        Af[(ahalf + q * 4 + 1) * 130 + arow] = t.y;
        Af[(ahalf + q * 4 + 2) * 130 + arow] = t.z;
        Af[(ahalf + q * 4 + 3) * 130 + arow] = t.w;
      }
    }
    if (!conv_mode) {
      const int nrow = tid >> 1;
      const int khalf = (tid & 1) * 32;
      const int nr = (n0 + nrow < N) ? nrow : 0;
      const float* bp = Bb + (long long)(k0 + khalf) * N + n0 + nr;
      bool nok = (n0 + nrow < N);
#pragma unroll
      for (int i = 0; i < 32; i++)
        Bf[(khalf + i) * 132 + nrow] = nok ? bp[(long long)i * N] : 0.f;
    } else {
      const int khalf = (tid & 1) * 32;
      const int nl = tid >> 1;
#pragma unroll
      for (int i = 0; i < 32; i++) {
        int k = k0 + khalf + i;
        int ci = k / 9;
        int rr = k - ci * 9;
        int ky = rr / 3;
        int kx = rr - ky * 3;
        int iy = py + ky - 1, ix = px + kx - 1;
        float v = 0.f;
        if ((unsigned)iy < (unsigned)Himg && (unsigned)ix < (unsigned)Himg)
          v = Bb[(((long long)pb * Cin + ci) << logHW) + (iy << logW) + ix];
        Bf[(khalf + i) * 132 + nl] = v;
      }
    }
    __syncthreads();
#pragma unroll 4
    for (int kk = 0; kk < TCK; kk++) {
      const u64* ar = (const u64*)&Af[kk * 130 + m8];
      u64 a0 = ar[0], a1 = ar[1], a2 = ar[2], a3 = ar[3];
      float4 b40 = *(const float4*)&Bf[kk * 132 + n8];
      float4 b41 = *(const float4*)&Bf[kk * 132 + n8 + 4];
      u64 b[8];
      b[0] = dupf(b40.x); b[1] = dupf(b40.y); b[2] = dupf(b40.z); b[3] = dupf(b40.w);
      b[4] = dupf(b41.x); b[5] = dupf(b41.y); b[6] = dupf(b41.z); b[7] = dupf(b41.w);
#pragma unroll
      for (int j = 0; j < 8; j++) {
        fma2(acc[0][j], a0, b[j]);
        fma2(acc[1][j], a1, b[j]);
        fma2(acc[2][j], a2, b[j]);
        fma2(acc[3][j], a3, b[j]);
      }
    }
    __syncthreads();
  }

  if (!conv_mode) {
#pragma unroll
    for (int p = 0; p < 4; p++) {
      int mlo = m0 + m8 + 2 * p;
#pragma unroll
      for (int j = 0; j < 8; j++) {
        int n = n0 + n8 + j;
        if (n >= N) continue;
        float2 v = unp(acc[p][j]);
        float bsv = biasb[n];
        if (mlo < Mz) {
          float r = v.x + bsv;
          if (relu) r = fmaxf(r, 0.f);
          Cb[(long long)mlo * N + n] = r;
        }
        if (mlo + 1 < Mz) {
          float r = v.y + bsv;
          if (relu) r = fmaxf(r, 0.f);
          Cb[(long long)(mlo + 1) * N + n] = r;
        }
      }
    }
  } else {
    // conv fallback: BN+ReLU -> smem transpose -> fused 2x2 maxpool
    float* T = (float*)(smem + SOFF_TILES);   // [128][132]
    const float rs = rsqrtf(1.00001f);
#pragma unroll
    for (int p = 0; p < 4; p++) {
      int mlo = m8 + 2 * p;
      int gm = m0 + mlo;
      float sc0 = gam[gm] * rs, cb0 = biasb[gm], be0 = bet[gm];
      float sc1 = gam[gm + 1] * rs, cb1v = biasb[gm + 1], be1v = bet[gm + 1];
#pragma unroll
      for (int j = 0; j < 8; j++) {
        float2 v = unp(acc[p][j]);
        T[mlo * 132 + n8 + j] = fmaxf((v.x + cb0) * sc0 + be0, 0.f);
        T[(mlo + 1) * 132 + n8 + j] = fmaxf((v.y + cb1v) * sc1 + be1v, 0.f);
      }
    }
    __syncthreads();
    const int HWm1 = (1 << logHW) - 1;
    const int W = 1 << logW;
    for (int g = 0; g < 4; g++) {
      int pix = n0 + g * 32 + lane;
      int b = pix >> logHW;
      int pos = pix & HWm1;
      bool wsel = ((pos & 1) == 0) && (((pos >> logW) & 1) == 0);
      int poff = ((pos >> (logW + 1)) << (logW - 1)) + ((pos & (W - 1)) >> 1);
      long long obase = ((long long)b * M) << (logHW - 2);
      for (int rr = 0; rr < 16; rr++) {
        int mloc = wid * 16 + rr;
        float v = T[mloc * 132 + g * 32 + lane];
        float vx = fmaxf(v, __shfl_xor_sync(0xffffffffu, v, 1));
        float vy = fmaxf(vx, __shfl_xor_sync(0xffffffffu, vx, W));
        if (wsel)
          Cb[obase + (((long long)(m0 + mloc)) << (logHW - 2)) + poff] = vy;
      }
    }
  }
#endif
}

// =================== dense GEMM 128x64x16, f32x2 (small N only) ===============
#define DBM 128
#define DBN 64
#define DBK 16

__global__ __launch_bounds__(256) void gemm_f2(
    const float* __restrict__ A, const float* __restrict__ B,
    const float* __restrict__ bias, float* __restrict__ C,
    int M, int N, int K, int relu) {
  const int n0 = blockIdx.x * DBN;
  const int m0 = blockIdx.y * DBM;

  __shared__ float As[DBK][DBM + 2];
  __shared__ float Bs[DBK][DBN + 4];

  u64 acc[4][4];
#pragma unroll
  for (int p = 0; p < 4; p++)
#pragma unroll
    for (int j = 0; j < 4; j++) acc[p][j] = 0ull;

  const int tid = threadIdx.x;
  const int tx = tid & 15, ty = tid >> 4;

  int rowA[2], kqA[2];
  size_t abase[2];
#pragma unroll
  for (int i = 0; i < 2; i++) {
    int v = tid + i * 256;
    rowA[i] = v >> 2;
    kqA[i] = v & 3;
    abase[i] = (size_t)(m0 + rowA[i]) * K + kqA[i] * 4;
  }
  const int kb = tid >> 4, nb = (tid & 15) * 4;

  for (int k0 = 0; k0 < K; k0 += DBK) {
#pragma unroll
    for (int i = 0; i < 2; i++) {
      float4 a4 = *(const float4*)&A[abase[i] + k0];
      int kk = kqA[i] * 4;
      As[kk + 0][rowA[i]] = a4.x;
      As[kk + 1][rowA[i]] = a4.y;
      As[kk + 2][rowA[i]] = a4.z;
      As[kk + 3][rowA[i]] = a4.w;
    }
    {
      float4 b4;
      size_t bo = (size_t)(k0 + kb) * N + n0 + nb;
      if (n0 + nb + 3 < N) {
        b4 = *(const float4*)&B[bo];
      } else {
        b4.x = (n0 + nb + 0 < N) ? B[bo + 0] : 0.f;
        b4.y = (n0 + nb + 1 < N) ? B[bo + 1] : 0.f;
        b4.z = (n0 + nb + 2 < N) ? B[bo + 2] : 0.f;
        b4.w = (n0 + nb + 3 < N) ? B[bo + 3] : 0.f;
      }
      *(float4*)&Bs[kb][nb] = b4;
    }
    __syncthreads();
#pragma unroll
    for (int kk = 0; kk < DBK; kk++) {
      const u64* arow = (const u64*)&As[kk][0];
      u64 a0 = arow[ty * 4 + 0], a1 = arow[ty * 4 + 1];
      u64 a2 = arow[ty * 4 + 2], a3 = arow[ty * 4 + 3];
      float4 b4 = *(const float4*)&Bs[kk][tx * 4];
      u64 b0 = dupf(b4.x), b1 = dupf(b4.y), b2 = dupf(b4.z), b3 = dupf(b4.w);
      fma2(acc[0][0], a0, b0); fma2(acc[0][1], a0, b1);
      fma2(acc[0][2], a0, b2); fma2(acc[0][3], a0, b3);
      fma2(acc[1][0], a1, b0); fma2(acc[1][1], a1, b1);
      fma2(acc[1][2], a1, b2); fma2(acc[1][3], a1, b3);
      fma2(acc[2][0], a2, b0); fma2(acc[2][1], a2, b1);
      fma2(acc[2][2], a2, b2); fma2(acc[2][3], a2, b3);
      fma2(acc[3][0], a3, b0); fma2(acc[3][1], a3, b1);
      fma2(acc[3][2], a3, b2); fma2(acc[3][3], a3, b3);
    }
    __syncthreads();
  }

#pragma unroll
  for (int p = 0; p < 4; p++) {
    int mlo = m0 + ty * 8 + 2 * p;
#pragma unroll
    for (int j = 0; j < 4; j++) {
      int n = n0 + tx * 4 + j;
      if (n >= N) continue;
      float2 v = unp(acc[p][j]);
      float bsv = bias[n];
      if (mlo < M) {
        float r = v.x + bsv;
        if (relu) r = fmaxf(r, 0.f);
        C[(size_t)mlo * N + n] = r;
      }
      if (mlo + 1 < M) {
        float r = v.y + bsv;
        if (relu) r = fmaxf(r, 0.f);
        C[(size_t)(mlo + 1) * N + n] = r;
      }
    }
  }
}

// ============ implicit-im2col conv 64x128x16 + bias/BN/ReLU (conv1) ===========
#define CBM 64
#define CBN 128
#define CBK 16

__global__ __launch_bounds__(256) void conv_f2(
    const float* __restrict__ in, const float* __restrict__ w,
    const float* __restrict__ cb, const float* __restrict__ gam,
    const float* __restrict__ bet, float* __restrict__ out,
    int Cin, int Cout, int H, int logW, int logHW) {
  const int HW = 1 << logHW;
  const int W = 1 << logW;
  const int Ktot = Cin * 9;
  const int n0 = blockIdx.x * CBN;
  const int m0 = blockIdx.y * CBM;

  __shared__ float As[CBK][CBM + 2];
  __shared__ float Bs[CBK][CBN + 4];

  u64 acc[4][4];
#pragma unroll
  for (int p = 0; p < 4; p++)
#pragma unroll
    for (int j = 0; j < 4; j++) acc[p][j] = 0ull;

  const int tid = threadIdx.x;
  const int tx = tid & 31, ty = tid >> 5;
  const int kB = tid >> 4, nb8 = (tid & 15) * 8;

  for (int k0 = 0; k0 < Ktot; k0 += CBK) {
#pragma unroll
    for (int i = 0; i < 4; i++) {
      int l = tid + i * 256;
      int k = l & 15, m = l >> 4;
      int gk = k0 + k;
      As[k][m] = (gk < Ktot) ? w[(m0 + m) * Ktot + gk] : 0.f;
    }
    {
      int gk = k0 + kB;
      int ci = 0, ky = 0, kx = 0;
      bool kvalid = gk < Ktot;
      if (kvalid) {
        ci = gk / 9;
        int r = gk - ci * 9;
        ky = r / 3;
        kx = r - ky * 3;
      }
      const float* inp = in + (size_t)ci * HW;
#pragma unroll
      for (int jj = 0; jj < 8; jj++) {
        int gn = n0 + nb8 + jj;
        float v = 0.f;
        if (kvalid) {
          int b = gn >> logHW;
          int pos = gn & (HW - 1);
          int y = pos >> logW, x = pos & (W - 1);
          int iy = y + ky - 1, ix = x + kx - 1;
          if ((unsigned)iy < (unsigned)H && (unsigned)ix < (unsigned)H)
            v = inp[((size_t)b * Cin << logHW) + (iy << logW) + ix];
        }
        Bs[kB][nb8 + jj] = v;
      }
    }
    __syncthreads();
#pragma unroll
    for (int kk = 0; kk < CBK; kk++) {
      const u64* arow = (const u64*)&As[kk][0];
      u64 a0 = arow[ty * 4 + 0], a1 = arow[ty * 4 + 1];
      u64 a2 = arow[ty * 4 + 2], a3 = arow[ty * 4 + 3];
      float4 b4 = *(const float4*)&Bs[kk][tx * 4];
      u64 b0 = dupf(b4.x), b1 = dupf(b4.y), b2 = dupf(b4.z), b3 = dupf(b4.w);
      fma2(acc[0][0], a0, b0); fma2(acc[0][1], a0, b1);
      fma2(acc[0][2], a0, b2); fma2(acc[0][3], a0, b3);
      fma2(acc[1][0], a1, b0); fma2(acc[1][1], a1, b1);
      fma2(acc[1][2], a1, b2); fma2(acc[1][3], a1, b3);
      fma2(acc[2][0], a2, b0); fma2(acc[2][1], a2, b1);
      fma2(acc[2][2], a2, b2); fma2(acc[2][3], a2, b3);
      fma2(acc[3][0], a3, b0); fma2(acc[3][1], a3, b1);
      fma2(acc[3][2], a3, b2); fma2(acc[3][3], a3, b3);
    }
    __syncthreads();
  }

  const float rs = rsqrtf(1.00001f);
#pragma unroll
  for (int p = 0; p < 4; p++) {
    int mlo = m0 + ty * 8 + 2 * p;
    float sc0 = gam[mlo] * rs, cb0 = cb[mlo], be0 = bet[mlo];
    float sc1 = gam[mlo + 1] * rs, cb1v = cb[mlo + 1], be1v = bet[mlo + 1];
#pragma unroll
    for (int j = 0; j < 4; j++) {
      int gn = n0 + tx * 4 + j;
      int b = gn >> logHW;
      int pos = gn & (HW - 1);
      float2 v = unp(acc[p][j]);
      float r0 = fmaxf((v.x + cb0) * sc0 + be0, 0.f);
      float r1 = fmaxf((v.y + cb1v) * sc1 + be1v, 0.f);
      out[((size_t)(b * Cout + mlo) << logHW) + pos] = r0;
      out[((size_t)(b * Cout + mlo + 1) << logHW) + pos] = r1;
    }
  }
}

// ---------------- 2x2 max pool (stride 2) -- conv1 only ----------------
__global__ void pool_kernel(const float* __restrict__ in, float* __restrict__ out,
                            int C, int H) {
  int Hp = H >> 1;
  int total = BATCH * C * Hp * Hp;
  int idx = blockIdx.x * blockDim.x + threadIdx.x;
  if (idx >= total) return;
  int px = idx % Hp;
  int t = idx / Hp;
  int py = t % Hp; t /= Hp;
  int c = t % C;
  int b = t / C;
  const float* p = in + ((size_t)(b * C + c) * H + py * 2) * H + px * 2;
  out[idx] = fmaxf(fmaxf(p[0], p[1]), fmaxf(p[H], p[H + 1]));
}

// ---------------- noisy top-k gating (per row) ----------------
__global__ void gating_kernel(const float* __restrict__ clean,
                              const float* __restrict__ rawstd,
                              const float* __restrict__ noise,
                              float* __restrict__ gates, float* __restrict__ prob) {
  int b = blockIdx.x * blockDim.x + threadIdx.x;
  if (b >= BATCH) return;
  float c[NEXP], sd[NEXP], nz[NEXP];
#pragma unroll
  for (int e = 0; e < NEXP; e++) {
    c[e] = clean[b * NEXP + e];
    float rsv = rawstd[b * NEXP + e];
    float sp = (rsv > 20.f) ? rsv : log1pf(expf(rsv));
    sd[e] = sp + 0.01f;
    nz[e] = c[e] + noise[b * NEXP + e] * sd[e];
  }
  int i0 = 0; float v0 = nz[0];
#pragma unroll
  for (int e = 1; e < NEXP; e++) if (nz[e] > v0) { v0 = nz[e]; i0 = e; }
  int i1 = -1; float v1 = -1e30f;
#pragma unroll
  for (int e = 0; e < NEXP; e++) if (e != i0 && nz[e] > v1) { v1 = nz[e]; i1 = e; }
  float v2 = -1e30f;
#pragma unroll
  for (int e = 0; e < NEXP; e++) if (e != i0 && e != i1 && nz[e] > v2) v2 = nz[e];

  float e1 = expf(v1 - v0);
  float inv = 1.f / (1.f + e1);
  const float kInvSqrt2 = 0.70710678118654752440f;
#pragma unroll
  for (int e = 0; e < NEXP; e++) {
    float g = (e == i0) ? inv : ((e == i1) ? e1 * inv : 0.f);
    gates[b * NEXP + e] = g;
    float th = (nz[e] > v2) ? v2 : v1;
    float zz = (c[e] - th) / sd[e];
    prob[b * NEXP + e] = 0.5f * (1.f + erff(zz * kInvSqrt2));
  }
}

// -------- deterministic dispatch build (1 block, warp per expert) --------
__global__ void build_dispatch(const float* __restrict__ gates,
                               int* __restrict__ rowlist, int* __restrict__ cnt,
                               int* __restrict__ rowslot,
                               float* __restrict__ slotgate) {
  int w = threadIdx.x >> 5;
  int lane = threadIdx.x & 31;
  int c = 0;
  for (int base = 0; base < BATCH; base += 32) {
    int b = base + lane;
    float g = gates[b * NEXP + w];
    unsigned mask = __ballot_sync(0xffffffffu, g > 0.f);
    if (g > 0.f) {
      int pos = c + __popc(mask & ((1u << lane) - 1u));
      int slot = w * BATCH + pos;
      rowlist[slot] = b;
      slotgate[slot] = g;
      int m8 = 0;
#pragma unroll
      for (int e = 0; e < NEXP; e++) m8 |= (gates[b * NEXP + e] > 0.f) ? (1 << e) : 0;
      int j = __popc(m8 & ((1 << w) - 1));
      rowslot[b * 2 + j] = slot;
    }
    c += __popc(mask);
  }
  if (lane == 0) cnt[w] = c;
}

// ---------------- deterministic per-expert reductions ----------------
__global__ void moe_reduce_kernel(const float* __restrict__ gates,
                                  const float* __restrict__ prob,
                                  float* __restrict__ imp, float* __restrict__ loadv) {
  int e = blockIdx.x;
  int t = threadIdx.x;
  __shared__ float s1[256], s2[256];
  float a = 0.f, b = 0.f;
  for (int i = t; i < BATCH; i += 256) {
    a += gates[i * NEXP + e];
    b += prob[i * NEXP + e];
  }
  s1[t] = a; s2[t] = b;
  __syncthreads();
  for (int s = 128; s > 0; s >>= 1) {
    if (t < s) { s1[t] += s1[t + s]; s2[t] += s2[t + s]; }
    __syncthreads();
  }
  if (t == 0) { imp[e] = s1[0]; loadv[e] = s2[0]; }
}

__global__ void loss_kernel(const float* __restrict__ imp,
                            const float* __restrict__ loadv,
                            float* __restrict__ out) {
  float m1 = 0.f, m2 = 0.f;
  for (int e = 0; e < NEXP; e++) { m1 += imp[e]; m2 += loadv[e]; }
  m1 *= 0.125f; m2 *= 0.125f;
  float v1 = 0.f, v2 = 0.f;
  for (int e = 0; e < NEXP; e++) {
    float d1 = imp[e] - m1; v1 += d1 * d1;
    float d2 = loadv[e] - m2; v2 += d2 * d2;
  }
  v1 /= 7.f; v2 /= 7.f;
  out[0] = v1 / (m1 * m1 + 1e-10f) + v2 / (m2 * m2 + 1e-10f);
}

// ------------- slot-based combine: y[b,c] = g0*eo[s0,c]+g1*eo[s1,c] ----------
__global__ void combine2_kernel(const int* __restrict__ rowslot,
                                const float* __restrict__ slotgate,
                                const float* __restrict__ eo,
                                float* __restrict__ y) {
  int idx = blockIdx.x * blockDim.x + threadIdx.x;
  if (idx >= BATCH * NCLS) return;
  int b = idx / NCLS;
  int c = idx - b * NCLS;
  int s0 = rowslot[b * 2 + 0], s1 = rowslot[b * 2 + 1];
  y[idx] = slotgate[s0] * eo[(size_t)s0 * NCLS + c] +
           slotgate[s1] * eo[(size_t)s1 * NCLS + c];
}

// ================================ launch ======================================
extern "C" void kernel_launch(void* const* d_in, const int* in_sizes, int n_in,
                              void* d_out, int out_size) {
  const float* x    = (const float*)d_in[0];
  const float* noise= (const float*)d_in[1];
  const float* cw1 = (const float*)d_in[2],  *cb1 = (const float*)d_in[3];
  const float* g1  = (const float*)d_in[4],  *be1 = (const float*)d_in[5];
  const float* cw2 = (const float*)d_in[6],  *cb2 = (const float*)d_in[7];
  const float* g2  = (const float*)d_in[8],  *be2 = (const float*)d_in[9];
  const float* cw3 = (const float*)d_in[10], *cb3 = (const float*)d_in[11];
  const float* g3  = (const float*)d_in[12], *be3 = (const float*)d_in[13];
  const float* cw4 = (const float*)d_in[14], *cb4 = (const float*)d_in[15];
  const float* g4  = (const float*)d_in[16], *be4 = (const float*)d_in[17];
  const float* wg1 = (const float*)d_in[18], *wg1b= (const float*)d_in[19];
  const float* wg2 = (const float*)d_in[20], *wg2b= (const float*)d_in[21];
  const float* wn1 = (const float*)d_in[22], *wn1b= (const float*)d_in[23];
  const float* wn2 = (const float*)d_in[24], *wn2b= (const float*)d_in[25];
  const float* eW1 = (const float*)d_in[26], *eb1 = (const float*)d_in[27];
  const float* eW2 = (const float*)d_in[28], *eb2 = (const float*)d_in[29];
  const float* eW3 = (const float*)d_in[30], *eb3 = (const float*)d_in[31];

  float *convout, *poolA, *poolB, *hid, *clean, *rawstd, *gates, *prob;
  float *eh, *eh2, *eo, *imp, *loadv, *slotgate;
  int *rowlist, *cnt, *rowslot;
  cudaGetSymbolAddress((void**)&convout, g_convout);
  cudaGetSymbolAddress((void**)&poolA, g_poolA);
  cudaGetSymbolAddress((void**)&poolB, g_poolB);
  cudaGetSymbolAddress((void**)&hid, g_hid);
  cudaGetSymbolAddress((void**)&clean, g_clean);
  cudaGetSymbolAddress((void**)&rawstd, g_rawstd);
  cudaGetSymbolAddress((void**)&gates, g_gates);
  cudaGetSymbolAddress((void**)&prob, g_prob);
  cudaGetSymbolAddress((void**)&eh, g_eh);
  cudaGetSymbolAddress((void**)&eh2, g_eh2);
  cudaGetSymbolAddress((void**)&eo, g_eo);
  cudaGetSymbolAddress((void**)&imp, g_imp);
  cudaGetSymbolAddress((void**)&loadv, g_load);
  cudaGetSymbolAddress((void**)&rowlist, g_rowlist);
  cudaGetSymbolAddress((void**)&cnt, g_cnt);
  cudaGetSymbolAddress((void**)&rowslot, g_rowslot);
  cudaGetSymbolAddress((void**)&slotgate, g_slotgate);

  float* out = (float*)d_out;

  cudaFuncSetAttribute(tc_gemm, cudaFuncAttributeMaxDynamicSharedMemorySize, SMEM_TC);

  // ---- conv1 (scalar) + pool1 ----
  conv_f2<<<dim3(BATCH * 1024 / CBN, 1), 256>>>(x, cw1, cb1, g1, be1, convout, 3, 64, 32, 5, 10);
  pool_kernel<<<(BATCH * 64 * 256 + 255) / 256, 256>>>(convout, poolA, 64, 32);

  // ---- conv2-4 (tc_gemm bf16x3, pool fused into epilogue) ----
  tc_gemm<<<dim3(BATCH * 256 / TCN, 1, 1), 256, SMEM_TC>>>(
      cw2, poolA, cb2, poolB, 128, BATCH * 256, 576, 1,
      0, 0, 0, 0, 0, 0, 1, 64, 16, 4, 8, g2, be2);

  tc_gemm<<<dim3(BATCH * 64 / TCN, 2, 1), 256, SMEM_TC>>>(
      cw3, poolB, cb3, poolA, 256, BATCH * 64, 1152, 1,
      0, 0, 0, 0, 0, 0, 1, 128, 8, 3, 6, g3, be3);

  tc_gemm<<<dim3(BATCH * 16 / TCN, 4, 1), 256, SMEM_TC>>>(
      cw4, poolA, cb4, poolB, 512, BATCH * 16, 2304, 1,
      0, 0, 0, 0, 0, 0, 1, 256, 4, 2, 4, g4, be4);

  const float* f = poolB;  // [2048, 2048]

  // ---- gating nets (big GEMMs via tc_gemm, tiny N=8 scalar) ----
  tc_gemm<<<dim3(GATEH / TCN, BATCH / TCM, 1), 256, SMEM_TC>>>(
      f, wg1, wg1b, hid, BATCH, GATEH, FEAT, 1,
      0, 0, 0, 0, 0, 0, 0, 0, 0, 0, 0, 0, 0);
  gemm_f2<<<dim3(1, BATCH / DBM, 1), 256>>>(hid, wg2, wg2b, clean, BATCH, NEXP, GATEH, 0);
  tc_gemm<<<dim3(GATEH / TCN, BATCH / TCM, 1), 256, SMEM_TC>>>(
      f, wn1, wn1b, hid, BATCH, GATEH, FEAT, 1,
      0, 0, 0, 0, 0, 0, 0, 0, 0, 0, 0, 0, 0);
  gemm_f2<<<dim3(1, BATCH / DBM, 1), 256>>>(hid, wn2, wn2b, rawstd, BATCH, NEXP, GATEH, 0);

  gating_kernel<<<BATCH / 256, 256>>>(clean, rawstd, noise, gates, prob);
  build_dispatch<<<1, 256>>>(gates, rowlist, cnt, rowslot, slotgate);
  moe_reduce_kernel<<<NEXP, 256>>>(gates, prob, imp, loadv);

  // ---- sparse experts (capacity grid + early-exit) ----
  tc_gemm<<<dim3(HID / TCN, BATCH / TCM, NEXP), 256, SMEM_TC>>>(
      f, eW1, eb1, eh, BATCH, HID, FEAT, 1,
      0, (long long)FEAT * HID, HID, (long long)BATCH * HID,
      rowlist, cnt, 0, 0, 0, 0, 0, 0, 0);
  tc_gemm<<<dim3((HID / 2) / TCN, BATCH / TCM, NEXP), 256, SMEM_TC>>>(
      eh, eW2, eb2, eh2, BATCH, HID / 2, HID, 1,
      (long long)BATCH * HID, (long long)HID * (HID / 2), HID / 2,
      (long long)BATCH * (HID / 2), 0, cnt, 0, 0, 0, 0, 0, 0, 0);
  tc_gemm<<<dim3(1, BATCH / TCM, NEXP), 256, SMEM_TC>>>(
      eh2, eW3, eb3, eo, BATCH, NCLS, HID / 2, 0,
      (long long)BATCH * (HID / 2), (long long)(HID / 2) * NCLS, NCLS,
      (long long)BATCH * NCLS, 0, cnt, 0, 0, 0, 0, 0, 0, 0);

  // ---- outputs ----
  combine2_kernel<<<(BATCH * NCLS + 255) / 256, 256>>>(rowslot, slotgate, eo, out);
  if (out_size >= BATCH * NCLS + 1)
    loss_kernel<<<1, 1>>>(imp, loadv, out + BATCH * NCLS);
}

// round 8
// speedup vs baseline: 2.4933x; 1.3428x over previous
#include <cuda_runtime.h>
#include <cuda_bf16.h>
#include <math.h>
#include <stdint.h>

#define BATCH 2048
#define NEXP 8
#define NCLS 100
#define HID 1024
#define GATEH 2048
#define FEAT 2048

typedef unsigned long long u64;

#if defined(__CUDA_ARCH_FEAT_SM103_ALL) || defined(__CUDA_ARCH_FEAT_SM100_ALL) || \
    defined(__CUDA_ARCH_FEAT_SM101_ALL) ||                                        \
    (defined(__CUDA_ARCH_SPECIFIC__) && (__CUDA_ARCH_SPECIFIC__ > 0))
#define HAS_TC 1
#else
#define HAS_TC 0
#endif

// ---------------- scratch (device globals; no allocation allowed) -------------
__device__ float g_poolA[33554432];
__device__ float g_poolB[16777216];
__device__ float g_hid[BATCH * GATEH];
__device__ float g_clean[BATCH * NEXP];
__device__ float g_rawstd[BATCH * NEXP];
__device__ float g_gates[BATCH * NEXP];
__device__ float g_prob[BATCH * NEXP];
__device__ float g_eh[(size_t)NEXP * BATCH * HID];
__device__ float g_eh2[(size_t)NEXP * BATCH * (HID / 2)];
__device__ float g_eo[(size_t)NEXP * BATCH * NCLS];
__device__ float g_imp[NEXP];
__device__ float g_load[NEXP];
__device__ int   g_rowlist[NEXP * BATCH];
__device__ int   g_cnt[NEXP];
__device__ int   g_rowslot[BATCH * 2];
__device__ float g_slotgate[NEXP * BATCH];

// ========================== common helpers ====================================
__device__ __forceinline__ uint32_t smem_u32(const void* p) {
  uint32_t a;
  asm("{ .reg .u64 t; cvta.to.shared.u64 t, %1; cvt.u32.u64 %0, t; }"
      : "=r"(a) : "l"(p));
  return a;
}

#define SW128(o) ((o) ^ (((o) >> 3) & 0x70))

__device__ __forceinline__ u64 dupf(float v) {
  u64 r; asm("mov.b64 %0, {%1, %1};" : "=l"(r) : "f"(v)); return r;
}
__device__ __forceinline__ void fma2(u64& d, u64 a, u64 b) {
  asm("fma.rn.f32x2 %0, %1, %2, %0;" : "+l"(d) : "l"(a), "l"(b));
}
__device__ __forceinline__ float2 unp(u64 v) {
  float2 f; asm("mov.b64 {%0, %1}, %2;" : "=f"(f.x), "=f"(f.y) : "l"(v)); return f;
}

__device__ __forceinline__ void bsplit2(float x0, float x1, uint32_t& hi, uint32_t& lo) {
  __nv_bfloat16 h0 = __float2bfloat16_rn(x0);
  __nv_bfloat16 h1 = __float2bfloat16_rn(x1);
  __nv_bfloat16 l0 = __float2bfloat16_rn(x0 - __bfloat162float(h0));
  __nv_bfloat16 l1 = __float2bfloat16_rn(x1 - __bfloat162float(h1));
  __nv_bfloat162 H; H.x = h0; H.y = h1;
  __nv_bfloat162 L; L.x = l0; L.y = l1;
  hi = *(uint32_t*)&H;
  lo = *(uint32_t*)&L;
}

#if HAS_TC
#define TC_ALLOC(sa, n) \
  asm volatile("tcgen05.alloc.cta_group::1.sync.aligned.shared::cta.b32 [%0], %1;" \
               :: "r"(sa), "r"(n) : "memory")
#define TC_DEALLOC(t, n) \
  asm volatile("tcgen05.dealloc.cta_group::1.sync.aligned.b32 %0, %1;" :: "r"(t), "r"(n))
#define TC_RELINQ() \
  asm volatile("tcgen05.relinquish_alloc_permit.cta_group::1.sync.aligned;")
#define TC_COMMIT(mb) \
  asm volatile("tcgen05.commit.cta_group::1.mbarrier::arrive::one.shared::cluster.b64 [%0];" \
               :: "r"(mb) : "memory")
#define TC_FENCE_AFTER()  asm volatile("tcgen05.fence::after_thread_sync;" ::: "memory")
#define TC_FENCE_BEFORE() asm volatile("tcgen05.fence::before_thread_sync;" ::: "memory")
#define TC_WAIT_LD()      asm volatile("tcgen05.wait::ld.sync.aligned;" ::: "memory")
#define FENCE_ASYNC()     asm volatile("fence.proxy.async.shared::cta;" ::: "memory")
#define MB_INIT(mb, n) \
  asm volatile("mbarrier.init.shared.b64 [%0], %1;" :: "r"(mb), "r"(n) : "memory")

#define MB_WAIT(mbar_addr, ph) do { \
  uint32_t _mb = (uint32_t)(mbar_addr); \
  uint32_t _p = (uint32_t)(ph); \
  asm volatile( \
      "{\n\t.reg .pred P1;\n\t" \
      "WAIT_LOOP_%=:\n\t" \
      "mbarrier.try_wait.parity.acquire.cta.shared::cta.b64 P1, [%0], %1, 0x989680;\n\t" \
      "@P1 bra.uni WAIT_DONE_%=;\n\t" \
      "bra.uni WAIT_LOOP_%=;\n\t" \
      "WAIT_DONE_%=:\n\t}" \
      :: "r"(_mb), "r"(_p) : "memory"); \
} while (0)

#define TC_LD_X32(r, ta) \
  asm volatile( \
      "tcgen05.ld.sync.aligned.32x32b.x32.b32 " \
      "{%0, %1, %2, %3, %4, %5, %6, %7, " \
      " %8, %9, %10, %11, %12, %13, %14, %15, " \
      " %16, %17, %18, %19, %20, %21, %22, %23, " \
      " %24, %25, %26, %27, %28, %29, %30, %31}, [%32];" \
      : "=r"((r)[0]),  "=r"((r)[1]),  "=r"((r)[2]),  "=r"((r)[3]), \
        "=r"((r)[4]),  "=r"((r)[5]),  "=r"((r)[6]),  "=r"((r)[7]), \
        "=r"((r)[8]),  "=r"((r)[9]),  "=r"((r)[10]), "=r"((r)[11]), \
        "=r"((r)[12]), "=r"((r)[13]), "=r"((r)[14]), "=r"((r)[15]), \
        "=r"((r)[16]), "=r"((r)[17]), "=r"((r)[18]), "=r"((r)[19]), \
        "=r"((r)[20]), "=r"((r)[21]), "=r"((r)[22]), "=r"((r)[23]), \
        "=r"((r)[24]), "=r"((r)[25]), "=r"((r)[26]), "=r"((r)[27]), \
        "=r"((r)[28]), "=r"((r)[29]), "=r"((r)[30]), "=r"((r)[31]) \
      : "r"(ta))

__device__ __forceinline__ uint64_t mkdesc(uint32_t addr) {
  return ((uint64_t)2 << 61) | ((uint64_t)1 << 46) | ((uint64_t)64 << 32) |
         ((uint64_t)1 << 16) | ((addr >> 4) & 0x3FFF);
}

__device__ __forceinline__ void mma_bf16(uint32_t d, uint64_t ad, uint64_t bd,
                                         uint32_t idesc, uint32_t en) {
  asm volatile(
      "{\n\t.reg .pred p;\n\tsetp.ne.u32 p, %5, 0;\n\t"
      "tcgen05.mma.cta_group::1.kind::f16 [%0], %1, %2, %3, {%4, %4, %4, %4}, p;\n\t}"
      :: "r"(d), "l"(ad), "l"(bd), "r"(idesc), "r"(0u), "r"(en) : "memory");
}
#endif  // HAS_TC

__device__ __forceinline__ void sts128u(uint32_t addr, uint32_t a, uint32_t b,
                                        uint32_t c, uint32_t d) {
  asm volatile("st.shared.v4.b32 [%0], {%1, %2, %3, %4};"
               :: "r"(addr), "r"(a), "r"(b), "r"(c), "r"(d) : "memory");
}
__device__ __forceinline__ void sts32u(uint32_t addr, uint32_t v) {
  asm volatile("st.shared.b32 [%0], %1;" :: "r"(addr), "r"(v) : "memory");
}
__device__ __forceinline__ float lds32f(uint32_t addr) {
  float v;
  asm volatile("ld.shared.b32 %0, [%1];" : "=f"(v) : "r"(addr));
  return v;
}

// ================= unified GEMM (128x128 tile, bf16x3, Kc=64, 512 thr) ========
#define TCM 128
#define TCN 128
#define TCK 64
#define TC_TILE 16384
#define TC_STAGE (4 * TC_TILE)
#define SOFF_MBAR 16
#define SOFF_TILES 1024
#define SMEM_TC (SOFF_TILES + 2 * TC_STAGE)
#define TCTHREADS 512

__global__ void __launch_bounds__(TCTHREADS, 1) tc_gemm(
    const float* __restrict__ A, const float* __restrict__ Bm,
    const float* __restrict__ bias, float* __restrict__ C,
    int M, int N, int K, int relu,
    long long sA, long long sB, long long sBias, long long sC,
    const int* __restrict__ rowlist, const int* __restrict__ cnt,
    int conv_mode, int Cin, int Himg, int logW, int logHW,
    const float* __restrict__ gam, const float* __restrict__ bet) {
  extern __shared__ char smem[];
  const int z = blockIdx.z;
  const int Mz = cnt ? cnt[z] : M;
  const int m0 = blockIdx.y * TCM;
  if (m0 >= Mz) return;
  const int n0 = blockIdx.x * TCN;

  const float* Ab = A + (long long)z * sA;
  const float* Bb = Bm + (long long)z * sB;
  const float* biasb = bias + (long long)z * sBias;
  float* Cb = C + (long long)z * sC;
  const int* rl = rowlist ? rowlist + z * BATCH : (const int*)0;

  const int tid = threadIdx.x;
  const int wid = tid >> 5, lane = tid & 31;

  // staging: thread -> (row = tid&127, 16-k quarter = tid>>7)
  const int srow = tid & 127;
  const int skq = (tid >> 7) * 16;
  long long aidx;
  {
    int gm = m0 + srow;
    int r_ = (gm < Mz) ? gm : 0;
    if (rl) r_ = (gm < Mz) ? rl[gm] : 0;
    aidx = (long long)r_ * K + skq;
  }

  // conv pixel coords for B staging
  int pb = 0, py = 0, px = 0;
  if (conv_mode) {
    int gn = n0 + srow;
    pb = gn >> logHW;
    int pos = gn & ((1 << logHW) - 1);
    py = pos >> logW;
    px = pos & ((1 << logW) - 1);
  }

#if HAS_TC
  // ======================= tcgen05 bf16x3 path ================================
  const uint32_t sbase = smem_u32(smem);
  if (wid == 0) TC_ALLOC(sbase, 128);
  if (tid == 0) { MB_INIT(sbase + SOFF_MBAR, 1); MB_INIT(sbase + SOFF_MBAR + 8, 1); }
  __syncthreads();
  uint32_t tmem;
  asm volatile("ld.shared.b32 %0, [%1];" : "=r"(tmem) : "r"(sbase));

  const int nchunks = K / TCK;
  int phase0 = 0, phase1 = 0;
  const uint32_t idesc =
      (1u << 4) | (1u << 7) | (1u << 10) | ((TCN / 8) << 17) | ((TCM / 16) << 24);

  for (int c = 0; c < nchunks; c++) {
    const int s = c & 1;
    const uint32_t stg = sbase + SOFF_TILES + s * TC_STAGE;
    const uint32_t sAhi = stg, sAlo = stg + TC_TILE;
    const uint32_t sBhi = stg + 2 * TC_TILE, sBlo = stg + 3 * TC_TILE;
    if (c >= 2) {
      if (s == 0) { MB_WAIT(sbase + SOFF_MBAR, phase0); phase0 ^= 1; }
      else        { MB_WAIT(sbase + SOFF_MBAR + 8, phase1); phase1 ^= 1; }
    }
    const int k0 = c * TCK;

    // ---- stage A (row srow, k [skq, skq+16)) ----
    {
      const float* ap = Ab + aidx + k0;
      uint32_t ha[8], la[8];
#pragma unroll
      for (int q = 0; q < 4; q++) {
        float4 t = *(const float4*)(ap + q * 4);
        bsplit2(t.x, t.y, ha[q * 2 + 0], la[q * 2 + 0]);
        bsplit2(t.z, t.w, ha[q * 2 + 1], la[q * 2 + 1]);
      }
      const uint32_t ro = srow * 128 + skq * 2;
      uint32_t o0 = SW128(ro), o1 = SW128(ro + 16);
      sts128u(sAhi + o0, ha[0], ha[1], ha[2], ha[3]);
      sts128u(sAhi + o1, ha[4], ha[5], ha[6], ha[7]);
      sts128u(sAlo + o0, la[0], la[1], la[2], la[3]);
      sts128u(sAlo + o1, la[4], la[5], la[6], la[7]);
    }

    // ---- stage B (row srow = n or pixel, k [skq, skq+16)) ----
    {
      uint32_t hb[8], lb[8];
      if (!conv_mode) {
        const int nr = (n0 + srow < N) ? srow : 0;
        const float* bp = Bb + (long long)(k0 + skq) * N + n0 + nr;
#pragma unroll
        for (int i = 0; i < 16; i += 2) {
          float v0 = bp[(long long)i * N];
          float v1 = bp[(long long)(i + 1) * N];
          bsplit2(v0, v1, hb[i / 2], lb[i / 2]);
        }
      } else {
#pragma unroll
        for (int i = 0; i < 16; i += 2) {
          float v[2];
#pragma unroll
          for (int d = 0; d < 2; d++) {
            int k = k0 + skq + i + d;
            int ci = k / 9;
            int rr = k - ci * 9;
            int ky = rr / 3;
            int kx = rr - ky * 3;
            int iy = py + ky - 1, ix = px + kx - 1;
            v[d] = 0.f;
            if ((unsigned)iy < (unsigned)Himg && (unsigned)ix < (unsigned)Himg)
              v[d] = Bb[(((long long)pb * Cin + ci) << logHW) + (iy << logW) + ix];
          }
          bsplit2(v[0], v[1], hb[i / 2], lb[i / 2]);
        }
      }
      const uint32_t ro = srow * 128 + skq * 2;
      uint32_t o0 = SW128(ro), o1 = SW128(ro + 16);
      sts128u(sBhi + o0, hb[0], hb[1], hb[2], hb[3]);
      sts128u(sBhi + o1, hb[4], hb[5], hb[6], hb[7]);
      sts128u(sBlo + o0, lb[0], lb[1], lb[2], lb[3]);
      sts128u(sBlo + o1, lb[4], lb[5], lb[6], lb[7]);
    }

    FENCE_ASYNC();
    __syncthreads();

    if (tid == 0) {
      uint64_t dAh = mkdesc(sAhi), dAl = mkdesc(sAlo);
      uint64_t dBh = mkdesc(sBhi), dBl = mkdesc(sBlo);
#pragma unroll
      for (int i = 0; i < 4; i++)
        mma_bf16(tmem, dAh + 2 * i, dBh + 2 * i, idesc, (c > 0) | (i > 0));
#pragma unroll
      for (int i = 0; i < 4; i++)
        mma_bf16(tmem, dAh + 2 * i, dBl + 2 * i, idesc, 1u);
#pragma unroll
      for (int i = 0; i < 4; i++)
        mma_bf16(tmem, dAl + 2 * i, dBh + 2 * i, idesc, 1u);
      TC_COMMIT(sbase + SOFF_MBAR + 8 * s);
    }
  }

  MB_WAIT(sbase + SOFF_MBAR, phase0);
  if (nchunks > 1) MB_WAIT(sbase + SOFF_MBAR + 8, phase1);
  TC_FENCE_AFTER();

  // ---- epilogue: warps 0-3 LDTM+transpose (with conv BN/ReLU), then all 16
  //      warps cooperate on coalesced stores ----
  const uint32_t Tbase = sbase + SOFF_TILES;
  if (tid < 128) {
    const int m_loc = tid;
    const int m = m0 + m_loc;
    float sc = 0.f, cbv = 0.f, bev = 0.f;
    if (conv_mode) { sc = gam[m] * rsqrtf(1.00001f); cbv = biasb[m]; bev = bet[m]; }
#pragma unroll 1
    for (int g = 0; g < 4; g++) {
      uint32_t r[32];
      TC_LD_X32(r, tmem + g * 32);
      TC_WAIT_LD();
      uint32_t Tg = Tbase + (uint32_t)g * (128 * 33 * 4);
#pragma unroll
      for (int j = 0; j < 32; j++) {
        float v = __uint_as_float(r[j]);
        if (conv_mode) v = fmaxf((v + cbv) * sc + bev, 0.f);
        sts32u(Tg + (uint32_t)(m_loc * 33 + j) * 4, __float_as_uint(v));
      }
    }
    TC_FENCE_BEFORE();
  }
  __syncthreads();

  {
    const int g = wid & 3;
    const int mb = wid >> 2;
    const uint32_t Tg = Tbase + (uint32_t)g * (128 * 33 * 4);
    if (!conv_mode) {
      int n = n0 + g * 32 + lane;
      bool nok = (n < N);
      float bn = nok ? biasb[n] : 0.f;
#pragma unroll 4
      for (int rr = 0; rr < 32; rr++) {
        int mloc = mb * 32 + rr;
        int mm = m0 + mloc;
        float v = lds32f(Tg + (uint32_t)(mloc * 33 + lane) * 4);
        v += bn;
        if (relu) v = fmaxf(v, 0.f);
        if (nok && mm < Mz) Cb[(long long)mm * N + n] = v;
      }
    } else {
      const int HWm1 = (1 << logHW) - 1;
      const int W = 1 << logW;
      int pix = n0 + g * 32 + lane;
      int b = pix >> logHW;
      int pos = pix & HWm1;
      bool wsel = ((pos & 1) == 0) && (((pos >> logW) & 1) == 0);
      int poff = ((pos >> (logW + 1)) << (logW - 1)) + ((pos & (W - 1)) >> 1);
      long long obase = ((long long)b * M) << (logHW - 2);
#pragma unroll 4
      for (int rr = 0; rr < 32; rr++) {
        int mloc = mb * 32 + rr;
        int mm = m0 + mloc;
        float v = lds32f(Tg + (uint32_t)(mloc * 33 + lane) * 4);
        float vx = fmaxf(v, __shfl_xor_sync(0xffffffffu, v, 1));
        float vy = fmaxf(vx, __shfl_xor_sync(0xffffffffu, vx, W));
        if (wsel)
          Cb[obase + (((long long)mm) << (logHW - 2)) + poff] = vy;
      }
    }
  }
  __syncthreads();
  if (wid == 0) { TC_RELINQ(); TC_DEALLOC(tmem, 128); }

#else
  // ================== fallback: f32x2 scalar GEMM (same semantics) ===========
  float* Af = (float*)(smem + SOFF_TILES);     // [64][130]
  float* Bf = Af + 64 * 130;                   // [64][132]

  u64 acc[2][8];
#pragma unroll
  for (int p = 0; p < 2; p++)
#pragma unroll
    for (int j = 0; j < 8; j++) acc[p][j] = 0ull;

  const int tx = tid & 15, ty = tid >> 4;      // ty 0..31
  const int m4 = ty * 4, n8 = tx * 8;

  for (int k0 = 0; k0 < K; k0 += TCK) {
    {
      const float* ap = Ab + aidx + k0;
#pragma unroll
      for (int q = 0; q < 4; q++) {
        float4 t = *(const float4*)(ap + q * 4);
        Af[(skq + q * 4 + 0) * 130 + srow] = t.x;
        Af[(skq + q * 4 + 1) * 130 + srow] = t.y;
        Af[(skq + q * 4 + 2) * 130 + srow] = t.z;
        Af[(skq + q * 4 + 3) * 130 + srow] = t.w;
      }
    }
    if (!conv_mode) {
      const int nr = (n0 + srow < N) ? srow : 0;
      const float* bp = Bb + (long long)(k0 + skq) * N + n0 + nr;
      bool nok = (n0 + srow < N);
#pragma unroll
      for (int i = 0; i < 16; i++)
        Bf[(skq + i) * 132 + srow] = nok ? bp[(long long)i * N] : 0.f;
    } else {
#pragma unroll
      for (int i = 0; i < 16; i++) {
        int k = k0 + skq + i;
        int ci = k / 9;
        int rr = k - ci * 9;
        int ky = rr / 3;
        int kx = rr - ky * 3;
        int iy = py + ky - 1, ix = px + kx - 1;
        float v = 0.f;
        if ((unsigned)iy < (unsigned)Himg && (unsigned)ix < (unsigned)Himg)
          v = Bb[(((long long)pb * Cin + ci) << logHW) + (iy << logW) + ix];
        Bf[(skq + i) * 132 + srow] = v;
      }
    }
    __syncthreads();
#pragma unroll 4
    for (int kk = 0; kk < TCK; kk++) {
      const u64* ar = (const u64*)&Af[kk * 130 + m4];
      u64 a0 = ar[0], a1 = ar[1];
      float4 b40 = *(const float4*)&Bf[kk * 132 + n8];
      float4 b41 = *(const float4*)&Bf[kk * 132 + n8 + 4];
      u64 b[8];
      b[0] = dupf(b40.x); b[1] = dupf(b40.y); b[2] = dupf(b40.z); b[3] = dupf(b40.w);
      b[4] = dupf(b41.x); b[5] = dupf(b41.y); b[6] = dupf(b41.z); b[7] = dupf(b41.w);
#pragma unroll
      for (int j = 0; j < 8; j++) {
        fma2(acc[0][j], a0, b[j]);
        fma2(acc[1][j], a1, b[j]);
      }
    }
    __syncthreads();
  }

  if (!conv_mode) {
#pragma unroll
    for (int p = 0; p < 2; p++) {
      int mlo = m0 + m4 + 2 * p;
#pragma unroll
      for (int j = 0; j < 8; j++) {
        int n = n0 + n8 + j;
        if (n >= N) continue;
        float2 v = unp(acc[p][j]);
        float bsv = biasb[n];
        if (mlo < Mz) {
          float r = v.x + bsv;
          if (relu) r = fmaxf(r, 0.f);
          Cb[(long long)mlo * N + n] = r;
        }
        if (mlo + 1 < Mz) {
          float r = v.y + bsv;
          if (relu) r = fmaxf(r, 0.f);
          Cb[(long long)(mlo + 1) * N + n] = r;
        }
      }
    }
  } else {
    float* T = (float*)(smem + SOFF_TILES);   // [128][132]
    const float rs = rsqrtf(1.00001f);
#pragma unroll
    for (int p = 0; p < 2; p++) {
      int mlo = m4 + 2 * p;
      int gm = m0 + mlo;
      float sc0 = gam[gm] * rs, cb0 = biasb[gm], be0 = bet[gm];
      float sc1 = gam[gm + 1] * rs, cb1v = biasb[gm + 1], be1v = bet[gm + 1];
#pragma unroll
      for (int j = 0; j < 8; j++) {
        float2 v = unp(acc[p][j]);
        T[mlo * 132 + n8 + j] = fmaxf((v.x + cb0) * sc0 + be0, 0.f);
        T[(mlo + 1) * 132 + n8 + j] = fmaxf((v.y + cb1v) * sc1 + be1v, 0.f);
      }
    }
    __syncthreads();
    const int HWm1 = (1 << logHW) - 1;
    const int W = 1 << logW;
    const int g = wid & 3, mb = wid >> 2;
    int pix = n0 + g * 32 + lane;
    int b = pix >> logHW;
    int pos = pix & HWm1;
    bool wsel = ((pos & 1) == 0) && (((pos >> logW) & 1) == 0);
    int poff = ((pos >> (logW + 1)) << (logW - 1)) + ((pos & (W - 1)) >> 1);
    long long obase = ((long long)b * M) << (logHW - 2);
    for (int rr = 0; rr < 32; rr++) {
      int mloc = mb * 32 + rr;
      float v = T[mloc * 132 + g * 32 + lane];
      float vx = fmaxf(v, __shfl_xor_sync(0xffffffffu, v, 1));
      float vy = fmaxf(vx, __shfl_xor_sync(0xffffffffu, vx, W));
      if (wsel)
        Cb[obase + (((long long)(m0 + mloc)) << (logHW - 2)) + poff] = vy;
    }
  }
#endif
}

// =================== dense GEMM 128x64x16, f32x2 (small N only) ===============
#define DBM 128
#define DBN 64
#define DBK 16

__global__ __launch_bounds__(256) void gemm_f2(
    const float* __restrict__ A, const float* __restrict__ B,
    const float* __restrict__ bias, float* __restrict__ C,
    int M, int N, int K, int relu) {
  const int n0 = blockIdx.x * DBN;
  const int m0 = blockIdx.y * DBM;

  __shared__ float As[DBK][DBM + 2];
  __shared__ float Bs[DBK][DBN + 4];

  u64 acc[4][4];
#pragma unroll
  for (int p = 0; p < 4; p++)
#pragma unroll
    for (int j = 0; j < 4; j++) acc[p][j] = 0ull;

  const int tid = threadIdx.x;
  const int tx = tid & 15, ty = tid >> 4;

  int rowA[2], kqA[2];
  size_t abase[2];
#pragma unroll
  for (int i = 0; i < 2; i++) {
    int v = tid + i * 256;
    rowA[i] = v >> 2;
    kqA[i] = v & 3;
    abase[i] = (size_t)(m0 + rowA[i]) * K + kqA[i] * 4;
  }
  const int kb = tid >> 4, nb = (tid & 15) * 4;

  for (int k0 = 0; k0 < K; k0 += DBK) {
#pragma unroll
    for (int i = 0; i < 2; i++) {
      float4 a4 = *(const float4*)&A[abase[i] + k0];
      int kk = kqA[i] * 4;
      As[kk + 0][rowA[i]] = a4.x;
      As[kk + 1][rowA[i]] = a4.y;
      As[kk + 2][rowA[i]] = a4.z;
      As[kk + 3][rowA[i]] = a4.w;
    }
    {
      float4 b4;
      size_t bo = (size_t)(k0 + kb) * N + n0 + nb;
      if (n0 + nb + 3 < N) {
        b4 = *(const float4*)&B[bo];
      } else {
        b4.x = (n0 + nb + 0 < N) ? B[bo + 0] : 0.f;
        b4.y = (n0 + nb + 1 < N) ? B[bo + 1] : 0.f;
        b4.z = (n0 + nb + 2 < N) ? B[bo + 2] : 0.f;
        b4.w = (n0 + nb + 3 < N) ? B[bo + 3] : 0.f;
      }
      *(float4*)&Bs[kb][nb] = b4;
    }
    __syncthreads();
#pragma unroll
    for (int kk = 0; kk < DBK; kk++) {
      const u64* arow = (const u64*)&As[kk][0];
      u64 a0 = arow[ty * 4 + 0], a1 = arow[ty * 4 + 1];
      u64 a2 = arow[ty * 4 + 2], a3 = arow[ty * 4 + 3];
      float4 b4 = *(const float4*)&Bs[kk][tx * 4];
      u64 b0 = dupf(b4.x), b1 = dupf(b4.y), b2 = dupf(b4.z), b3 = dupf(b4.w);
      fma2(acc[0][0], a0, b0); fma2(acc[0][1], a0, b1);
      fma2(acc[0][2], a0, b2); fma2(acc[0][3], a0, b3);
      fma2(acc[1][0], a1, b0); fma2(acc[1][1], a1, b1);
      fma2(acc[1][2], a1, b2); fma2(acc[1][3], a1, b3);
      fma2(acc[2][0], a2, b0); fma2(acc[2][1], a2, b1);
      fma2(acc[2][2], a2, b2); fma2(acc[2][3], a2, b3);
      fma2(acc[3][0], a3, b0); fma2(acc[3][1], a3, b1);
      fma2(acc[3][2], a3, b2); fma2(acc[3][3], a3, b3);
    }
    __syncthreads();
  }

#pragma unroll
  for (int p = 0; p < 4; p++) {
    int mlo = m0 + ty * 8 + 2 * p;
#pragma unroll
    for (int j = 0; j < 4; j++) {
      int n = n0 + tx * 4 + j;
      if (n >= N) continue;
      float2 v = unp(acc[p][j]);
      float bsv = bias[n];
      if (mlo < M) {
        float r = v.x + bsv;
        if (relu) r = fmaxf(r, 0.f);
        C[(size_t)mlo * N + n] = r;
      }
      if (mlo + 1 < M) {
        float r = v.y + bsv;
        if (relu) r = fmaxf(r, 0.f);
        C[(size_t)(mlo + 1) * N + n] = r;
      }
    }
  }
}

// ==== implicit-im2col conv1 + bias/BN/ReLU + FUSED 2x2 maxpool (scalar) =======
#define CBM 64
#define CBN 128
#define CBK 16

__global__ __launch_bounds__(256) void conv_f2(
    const float* __restrict__ in, const float* __restrict__ w,
    const float* __restrict__ cb, const float* __restrict__ gam,
    const float* __restrict__ bet, float* __restrict__ out,
    int Cin, int Cout, int H, int logW, int logHW) {
  const int HW = 1 << logHW;
  const int W = 1 << logW;
  const int Ktot = Cin * 9;
  const int n0 = blockIdx.x * CBN;
  const int m0 = blockIdx.y * CBM;

  __shared__ float As[CBK][CBM + 2];
  __shared__ float Bs[CBK][CBN + 4];

  u64 acc[4][4];
#pragma unroll
  for (int p = 0; p < 4; p++)
#pragma unroll
    for (int j = 0; j < 4; j++) acc[p][j] = 0ull;

  const int tid = threadIdx.x;
  const int tx = tid & 31, ty = tid >> 5;
  const int kB = tid >> 4, nb8 = (tid & 15) * 8;

  for (int k0 = 0; k0 < Ktot; k0 += CBK) {
#pragma unroll
    for (int i = 0; i < 4; i++) {
      int l = tid + i * 256;
      int k = l & 15, m = l >> 4;
      int gk = k0 + k;
      As[k][m] = (gk < Ktot) ? w[(m0 + m) * Ktot + gk] : 0.f;
    }
    {
      int gk = k0 + kB;
      int ci = 0, ky = 0, kx = 0;
      bool kvalid = gk < Ktot;
      if (kvalid) {
        ci = gk / 9;
        int r = gk - ci * 9;
        ky = r / 3;
        kx = r - ky * 3;
      }
      const float* inp = in + (size_t)ci * HW;
#pragma unroll
      for (int jj = 0; jj < 8; jj++) {
        int gn = n0 + nb8 + jj;
        float v = 0.f;
        if (kvalid) {
          int b = gn >> logHW;
          int pos = gn & (HW - 1);
          int y = pos >> logW, x = pos & (W - 1);
          int iy = y + ky - 1, ix = x + kx - 1;
          if ((unsigned)iy < (unsigned)H && (unsigned)ix < (unsigned)H)
            v = inp[((size_t)b * Cin << logHW) + (iy << logW) + ix];
        }
        Bs[kB][nb8 + jj] = v;
      }
    }
    __syncthreads();
#pragma unroll
    for (int kk = 0; kk < CBK; kk++) {
      const u64* arow = (const u64*)&As[kk][0];
      u64 a0 = arow[ty * 4 + 0], a1 = arow[ty * 4 + 1];
      u64 a2 = arow[ty * 4 + 2], a3 = arow[ty * 4 + 3];
      float4 b4 = *(const float4*)&Bs[kk][tx * 4];
      u64 b0 = dupf(b4.x), b1 = dupf(b4.y), b2 = dupf(b4.z), b3 = dupf(b4.w);
      fma2(acc[0][0], a0, b0); fma2(acc[0][1], a0, b1);
      fma2(acc[0][2], a0, b2); fma2(acc[0][3], a0, b3);
      fma2(acc[1][0], a1, b0); fma2(acc[1][1], a1, b1);
      fma2(acc[1][2], a1, b2); fma2(acc[1][3], a1, b3);
      fma2(acc[2][0], a2, b0); fma2(acc[2][1], a2, b1);
      fma2(acc[2][2], a2, b2); fma2(acc[2][3], a2, b3);
      fma2(acc[3][0], a3, b0); fma2(acc[3][1], a3, b1);
      fma2(acc[3][2], a3, b2); fma2(acc[3][3], a3, b3);
    }
    __syncthreads();
  }

  // ---- epilogue: BN+ReLU then fused 2x2 maxpool; output POOLED NCHW ----
  const float rs = rsqrtf(1.00001f);
  const int W2 = W >> 1;
  const int xsh = W >> 2;  // shfl distance for y-pair
  int gn0 = n0 + tx * 4;
  int b = gn0 >> logHW;
  int pos = gn0 & (HW - 1);
  int yg = pos >> logW;
  bool wsel = (yg & 1) == 0;
  int py = yg >> 1;
  int px0 = (pos & (W - 1)) >> 1;
  long long obase = ((long long)b * Cout) << (logHW - 2);
#pragma unroll
  for (int p = 0; p < 4; p++) {
    int mlo = m0 + ty * 8 + 2 * p;
    float sc0 = gam[mlo] * rs, cb0 = cb[mlo], be0 = bet[mlo];
    float sc1 = gam[mlo + 1] * rs, cb1v = cb[mlo + 1], be1v = bet[mlo + 1];
    float r0[4], r1[4];
#pragma unroll
    for (int j = 0; j < 4; j++) {
      float2 v = unp(acc[p][j]);
      r0[j] = fmaxf((v.x + cb0) * sc0 + be0, 0.f);
      r1[j] = fmaxf((v.y + cb1v) * sc1 + be1v, 0.f);
    }
    float a00 = fmaxf(r0[0], r0[1]), a01 = fmaxf(r0[2], r0[3]);
    float a10 = fmaxf(r1[0], r1[1]), a11 = fmaxf(r1[2], r1[3]);
    a00 = fmaxf(a00, __shfl_xor_sync(0xffffffffu, a00, xsh));
    a01 = fmaxf(a01, __shfl_xor_sync(0xffffffffu, a01, xsh));
    a10 = fmaxf(a10, __shfl_xor_sync(0xffffffffu, a10, xsh));
    a11 = fmaxf(a11, __shfl_xor_sync(0xffffffffu, a11, xsh));
    if (wsel) {
      long long o0 = obase + (((long long)mlo) << (logHW - 2)) + py * W2 + px0;
      long long o1 = obase + (((long long)(mlo + 1)) << (logHW - 2)) + py * W2 + px0;
      out[o0] = a00;
      out[o0 + 1] = a01;
      out[o1] = a10;
      out[o1 + 1] = a11;
    }
  }
}

// ---------------- noisy top-k gating (per row) ----------------
__global__ void gating_kernel(const float* __restrict__ clean,
                              const float* __restrict__ rawstd,
                              const float* __restrict__ noise,
                              float* __restrict__ gates, float* __restrict__ prob) {
  int b = blockIdx.x * blockDim.x + threadIdx.x;
  if (b >= BATCH) return;
  float c[NEXP], sd[NEXP], nz[NEXP];
#pragma unroll
  for (int e = 0; e < NEXP; e++) {
    c[e] = clean[b * NEXP + e];
    float rsv = rawstd[b * NEXP + e];
    float sp = (rsv > 20.f) ? rsv : log1pf(expf(rsv));
    sd[e] = sp + 0.01f;
    nz[e] = c[e] + noise[b * NEXP + e] * sd[e];
  }
  int i0 = 0; float v0 = nz[0];
#pragma unroll
  for (int e = 1; e < NEXP; e++) if (nz[e] > v0) { v0 = nz[e]; i0 = e; }
  int i1 = -1; float v1 = -1e30f;
#pragma unroll
  for (int e = 0; e < NEXP; e++) if (e != i0 && nz[e] > v1) { v1 = nz[e]; i1 = e; }
  float v2 = -1e30f;
#pragma unroll
  for (int e = 0; e < NEXP; e++) if (e != i0 && e != i1 && nz[e] > v2) v2 = nz[e];

  float e1 = expf(v1 - v0);
  float inv = 1.f / (1.f + e1);
  const float kInvSqrt2 = 0.70710678118654752440f;
#pragma unroll
  for (int e = 0; e < NEXP; e++) {
    float g = (e == i0) ? inv : ((e == i1) ? e1 * inv : 0.f);
    gates[b * NEXP + e] = g;
    float th = (nz[e] > v2) ? v2 : v1;
    float zz = (c[e] - th) / sd[e];
    prob[b * NEXP + e] = 0.5f * (1.f + erff(zz * kInvSqrt2));
  }
}

// -------- deterministic dispatch build (1 block, warp per expert) --------
__global__ void build_dispatch(const float* __restrict__ gates,
                               int* __restrict__ rowlist, int* __restrict__ cnt,
                               int* __restrict__ rowslot,
                               float* __restrict__ slotgate) {
  int w = threadIdx.x >> 5;
  int lane = threadIdx.x & 31;
  int c = 0;
  for (int base = 0; base < BATCH; base += 32) {
    int b = base + lane;
    float g = gates[b * NEXP + w];
    unsigned mask = __ballot_sync(0xffffffffu, g > 0.f);
    if (g > 0.f) {
      int pos = c + __popc(mask & ((1u << lane) - 1u));
      int slot = w * BATCH + pos;
      rowlist[slot] = b;
      slotgate[slot] = g;
      int m8 = 0;
#pragma unroll
      for (int e = 0; e < NEXP; e++) m8 |= (gates[b * NEXP + e] > 0.f) ? (1 << e) : 0;
      int j = __popc(m8 & ((1 << w) - 1));
      rowslot[b * 2 + j] = slot;
    }
    c += __popc(mask);
  }
  if (lane == 0) cnt[w] = c;
}

// ---------------- deterministic per-expert reductions ----------------
__global__ void moe_reduce_kernel(const float* __restrict__ gates,
                                  const float* __restrict__ prob,
                                  float* __restrict__ imp, float* __restrict__ loadv) {
  int e = blockIdx.x;
  int t = threadIdx.x;
  __shared__ float s1[256], s2[256];
  float a = 0.f, b = 0.f;
  for (int i = t; i < BATCH; i += 256) {
    a += gates[i * NEXP + e];
    b += prob[i * NEXP + e];
  }
  s1[t] = a; s2[t] = b;
  __syncthreads();
  for (int s = 128; s > 0; s >>= 1) {
    if (t < s) { s1[t] += s1[t + s]; s2[t] += s2[t + s]; }
    __syncthreads();
  }
  if (t == 0) { imp[e] = s1[0]; loadv[e] = s2[0]; }
}

__global__ void loss_kernel(const float* __restrict__ imp,
                            const float* __restrict__ loadv,
                            float* __restrict__ out) {
  float m1 = 0.f, m2 = 0.f;
  for (int e = 0; e < NEXP; e++) { m1 += imp[e]; m2 += loadv[e]; }
  m1 *= 0.125f; m2 *= 0.125f;
  float v1 = 0.f, v2 = 0.f;
  for (int e = 0; e < NEXP; e++) {
    float d1 = imp[e] - m1; v1 += d1 * d1;
    float d2 = loadv[e] - m2; v2 += d2 * d2;
  }
  v1 /= 7.f; v2 /= 7.f;
  out[0] = v1 / (m1 * m1 + 1e-10f) + v2 / (m2 * m2 + 1e-10f);
}

// ------------- slot-based combine: y[b,c] = g0*eo[s0,c]+g1*eo[s1,c] ----------
__global__ void combine2_kernel(const int* __restrict__ rowslot,
                                const float* __restrict__ slotgate,
                                const float* __restrict__ eo,
                                float* __restrict__ y) {
  int idx = blockIdx.x * blockDim.x + threadIdx.x;
  if (idx >= BATCH * NCLS) return;
  int b = idx / NCLS;
  int c = idx - b * NCLS;
  int s0 = rowslot[b * 2 + 0], s1 = rowslot[b * 2 + 1];
  y[idx] = slotgate[s0] * eo[(size_t)s0 * NCLS + c] +
           slotgate[s1] * eo[(size_t)s1 * NCLS + c];
}

// ================================ launch ======================================
extern "C" void kernel_launch(void* const* d_in, const int* in_sizes, int n_in,
                              void* d_out, int out_size) {
  const float* x    = (const float*)d_in[0];
  const float* noise= (const float*)d_in[1];
  const float* cw1 = (const float*)d_in[2],  *cb1 = (const float*)d_in[3];
  const float* g1  = (const float*)d_in[4],  *be1 = (const float*)d_in[5];
  const float* cw2 = (const float*)d_in[6],  *cb2 = (const float*)d_in[7];
  const float* g2  = (const float*)d_in[8],  *be2 = (const float*)d_in[9];
  const float* cw3 = (const float*)d_in[10], *cb3 = (const float*)d_in[11];
  const float* g3  = (const float*)d_in[12], *be3 = (const float*)d_in[13];
  const float* cw4 = (const float*)d_in[14], *cb4 = (const float*)d_in[15];
  const float* g4  = (const float*)d_in[16], *be4 = (const float*)d_in[17];
  const float* wg1 = (const float*)d_in[18], *wg1b= (const float*)d_in[19];
  const float* wg2 = (const float*)d_in[20], *wg2b= (const float*)d_in[21];
  const float* wn1 = (const float*)d_in[22], *wn1b= (const float*)d_in[23];
  const float* wn2 = (const float*)d_in[24], *wn2b= (const float*)d_in[25];
  const float* eW1 = (const float*)d_in[26], *eb1 = (const float*)d_in[27];
  const float* eW2 = (const float*)d_in[28], *eb2 = (const float*)d_in[29];
  const float* eW3 = (const float*)d_in[30], *eb3 = (const float*)d_in[31];

  float *poolA, *poolB, *hid, *clean, *rawstd, *gates, *prob;
  float *eh, *eh2, *eo, *imp, *loadv, *slotgate;
  int *rowlist, *cnt, *rowslot;
  cudaGetSymbolAddress((void**)&poolA, g_poolA);
  cudaGetSymbolAddress((void**)&poolB, g_poolB);
  cudaGetSymbolAddress((void**)&hid, g_hid);
  cudaGetSymbolAddress((void**)&clean, g_clean);
  cudaGetSymbolAddress((void**)&rawstd, g_rawstd);
  cudaGetSymbolAddress((void**)&gates, g_gates);
  cudaGetSymbolAddress((void**)&prob, g_prob);
  cudaGetSymbolAddress((void**)&eh, g_eh);
  cudaGetSymbolAddress((void**)&eh2, g_eh2);
  cudaGetSymbolAddress((void**)&eo, g_eo);
  cudaGetSymbolAddress((void**)&imp, g_imp);
  cudaGetSymbolAddress((void**)&loadv, g_load);
  cudaGetSymbolAddress((void**)&rowlist, g_rowlist);
  cudaGetSymbolAddress((void**)&cnt, g_cnt);
  cudaGetSymbolAddress((void**)&rowslot, g_rowslot);
  cudaGetSymbolAddress((void**)&slotgate, g_slotgate);

  float* out = (float*)d_out;

  cudaFuncSetAttribute(tc_gemm, cudaFuncAttributeMaxDynamicSharedMemorySize, SMEM_TC);

  // ---- conv1 (scalar, pool fused) -> poolA [2048,64,16,16] ----
  conv_f2<<<dim3(BATCH * 1024 / CBN, 1), 256>>>(x, cw1, cb1, g1, be1, poolA, 3, 64, 32, 5, 10);

  // ---- conv2-4 (tc_gemm bf16x3, pool fused) ----
  tc_gemm<<<dim3(BATCH * 256 / TCN, 1, 1), TCTHREADS, SMEM_TC>>>(
      cw2, poolA, cb2, poolB, 128, BATCH * 256, 576, 1,
      0, 0, 0, 0, 0, 0, 1, 64, 16, 4, 8, g2, be2);

  tc_gemm<<<dim3(BATCH * 64 / TCN, 2, 1), TCTHREADS, SMEM_TC>>>(
      cw3, poolB, cb3, poolA, 256, BATCH * 64, 1152, 1,
      0, 0, 0, 0, 0, 0, 1, 128, 8, 3, 6, g3, be3);

  tc_gemm<<<dim3(BATCH * 16 / TCN, 4, 1), TCTHREADS, SMEM_TC>>>(
      cw4, poolA, cb4, poolB, 512, BATCH * 16, 2304, 1,
      0, 0, 0, 0, 0, 0, 1, 256, 4, 2, 4, g4, be4);

  const float* f = poolB;  // [2048, 2048]

  // ---- gating nets ----
  tc_gemm<<<dim3(GATEH / TCN, BATCH / TCM, 1), TCTHREADS, SMEM_TC>>>(
      f, wg1, wg1b, hid, BATCH, GATEH, FEAT, 1,
      0, 0, 0, 0, 0, 0, 0, 0, 0, 0, 0, 0, 0);
  gemm_f2<<<dim3(1, BATCH / DBM, 1), 256>>>(hid, wg2, wg2b, clean, BATCH, NEXP, GATEH, 0);
  tc_gemm<<<dim3(GATEH / TCN, BATCH / TCM, 1), TCTHREADS, SMEM_TC>>>(
      f, wn1, wn1b, hid, BATCH, GATEH, FEAT, 1,
      0, 0, 0, 0, 0, 0, 0, 0, 0, 0, 0, 0, 0);
  gemm_f2<<<dim3(1, BATCH / DBM, 1), 256>>>(hid, wn2, wn2b, rawstd, BATCH, NEXP, GATEH, 0);

  gating_kernel<<<BATCH / 256, 256>>>(clean, rawstd, noise, gates, prob);
  build_dispatch<<<1, 256>>>(gates, rowlist, cnt, rowslot, slotgate);
  moe_reduce_kernel<<<NEXP, 256>>>(gates, prob, imp, loadv);

  // ---- sparse experts ----
  tc_gemm<<<dim3(HID / TCN, BATCH / TCM, NEXP), TCTHREADS, SMEM_TC>>>(
      f, eW1, eb1, eh, BATCH, HID, FEAT, 1,
      0, (long long)FEAT * HID, HID, (long long)BATCH * HID,
      rowlist, cnt, 0, 0, 0, 0, 0, 0, 0);
  tc_gemm<<<dim3((HID / 2) / TCN, BATCH / TCM, NEXP), TCTHREADS, SMEM_TC>>>(
      eh, eW2, eb2, eh2, BATCH, HID / 2, HID, 1,
      (long long)BATCH * HID, (long long)HID * (HID / 2), HID / 2,
      (long long)BATCH * (HID / 2), 0, cnt, 0, 0, 0, 0, 0, 0, 0);
  tc_gemm<<<dim3(1, BATCH / TCM, NEXP), TCTHREADS, SMEM_TC>>>(
      eh2, eW3, eb3, eo, BATCH, NCLS, HID / 2, 0,
      (long long)BATCH * (HID / 2), (long long)(HID / 2) * NCLS, NCLS,
      (long long)BATCH * NCLS, 0, cnt, 0, 0, 0, 0, 0, 0, 0);

  // ---- outputs ----
  combine2_kernel<<<(BATCH * NCLS + 255) / 256, 256>>>(rowslot, slotgate, eo, out);
  if (out_size >= BATCH * NCLS + 1)
    loss_kernel<<<1, 1>>>(imp, loadv, out + BATCH * NCLS);
}

// round 9
// speedup vs baseline: 2.7667x; 1.1097x over previous
#include <cuda_runtime.h>
#include <cuda_bf16.h>
#include <math.h>
#include <stdint.h>

#define BATCH 2048
#define NEXP 8
#define NCLS 100
#define HID 1024
#define GATEH 2048
#define FEAT 2048

typedef unsigned long long u64;

#if defined(__CUDA_ARCH_FEAT_SM103_ALL) || defined(__CUDA_ARCH_FEAT_SM100_ALL) || \
    defined(__CUDA_ARCH_FEAT_SM101_ALL) ||                                        \
    (defined(__CUDA_ARCH_SPECIFIC__) && (__CUDA_ARCH_SPECIFIC__ > 0))
#define HAS_TC 1
#else
#define HAS_TC 0
#endif

// ---------------- scratch (device globals; no allocation allowed) -------------
__device__ float g_poolA[33554432];
__device__ float g_poolB[16777216];
__device__ float g_hid[BATCH * GATEH];
__device__ float g_clean[BATCH * NEXP];
__device__ float g_rawstd[BATCH * NEXP];
__device__ float g_gates[BATCH * NEXP];
__device__ float g_prob[BATCH * NEXP];
__device__ float g_eh[(size_t)NEXP * BATCH * HID];
__device__ float g_eh2[(size_t)NEXP * BATCH * (HID / 2)];
__device__ float g_eo[(size_t)NEXP * BATCH * NCLS];
__device__ float g_imp[NEXP];
__device__ float g_load[NEXP];
__device__ int   g_rowlist[NEXP * BATCH];
__device__ int   g_cnt[NEXP];
__device__ int   g_rowslot[BATCH * 2];
__device__ float g_slotgate[NEXP * BATCH];

// ========================== common helpers ====================================
__device__ __forceinline__ uint32_t smem_u32(const void* p) {
  uint32_t a;
  asm("{ .reg .u64 t; cvta.to.shared.u64 t, %1; cvt.u32.u64 %0, t; }"
      : "=r"(a) : "l"(p));
  return a;
}

#define SW128(o) ((o) ^ (((o) >> 3) & 0x70))

__device__ __forceinline__ u64 dupf(float v) {
  u64 r; asm("mov.b64 %0, {%1, %1};" : "=l"(r) : "f"(v)); return r;
}
__device__ __forceinline__ void fma2(u64& d, u64 a, u64 b) {
  asm("fma.rn.f32x2 %0, %1, %2, %0;" : "+l"(d) : "l"(a), "l"(b));
}
__device__ __forceinline__ float2 unp(u64 v) {
  float2 f; asm("mov.b64 {%0, %1}, %2;" : "=f"(f.x), "=f"(f.y) : "l"(v)); return f;
}

__device__ __forceinline__ void bsplit2(float x0, float x1, uint32_t& hi, uint32_t& lo) {
  __nv_bfloat16 h0 = __float2bfloat16_rn(x0);
  __nv_bfloat16 h1 = __float2bfloat16_rn(x1);
  __nv_bfloat16 l0 = __float2bfloat16_rn(x0 - __bfloat162float(h0));
  __nv_bfloat16 l1 = __float2bfloat16_rn(x1 - __bfloat162float(h1));
  __nv_bfloat162 H; H.x = h0; H.y = h1;
  __nv_bfloat162 L; L.x = l0; L.y = l1;
  hi = *(uint32_t*)&H;
  lo = *(uint32_t*)&L;
}

#if HAS_TC
#define TC_ALLOC(sa, n) \
  asm volatile("tcgen05.alloc.cta_group::1.sync.aligned.shared::cta.b32 [%0], %1;" \
               :: "r"(sa), "r"(n) : "memory")
#define TC_DEALLOC(t, n) \
  asm volatile("tcgen05.dealloc.cta_group::1.sync.aligned.b32 %0, %1;" :: "r"(t), "r"(n))
#define TC_RELINQ() \
  asm volatile("tcgen05.relinquish_alloc_permit.cta_group::1.sync.aligned;")
#define TC_COMMIT(mb) \
  asm volatile("tcgen05.commit.cta_group::1.mbarrier::arrive::one.shared::cluster.b64 [%0];" \
               :: "r"(mb) : "memory")
#define TC_FENCE_AFTER()  asm volatile("tcgen05.fence::after_thread_sync;" ::: "memory")
#define TC_FENCE_BEFORE() asm volatile("tcgen05.fence::before_thread_sync;" ::: "memory")
#define TC_WAIT_LD()      asm volatile("tcgen05.wait::ld.sync.aligned;" ::: "memory")
#define FENCE_ASYNC()     asm volatile("fence.proxy.async.shared::cta;" ::: "memory")
#define MB_INIT(mb, n) \
  asm volatile("mbarrier.init.shared.b64 [%0], %1;" :: "r"(mb), "r"(n) : "memory")

#define MB_WAIT(mbar_addr, ph) do { \
  uint32_t _mb = (uint32_t)(mbar_addr); \
  uint32_t _p = (uint32_t)(ph); \
  asm volatile( \
      "{\n\t.reg .pred P1;\n\t" \
      "WAIT_LOOP_%=:\n\t" \
      "mbarrier.try_wait.parity.acquire.cta.shared::cta.b64 P1, [%0], %1, 0x989680;\n\t" \
      "@P1 bra.uni WAIT_DONE_%=;\n\t" \
      "bra.uni WAIT_LOOP_%=;\n\t" \
      "WAIT_DONE_%=:\n\t}" \
      :: "r"(_mb), "r"(_p) : "memory"); \
} while (0)

#define TC_LD_X16(r, ta) \
  asm volatile( \
      "tcgen05.ld.sync.aligned.32x32b.x16.b32 " \
      "{%0, %1, %2, %3, %4, %5, %6, %7, " \
      " %8, %9, %10, %11, %12, %13, %14, %15}, [%16];" \
      : "=r"((r)[0]),  "=r"((r)[1]),  "=r"((r)[2]),  "=r"((r)[3]), \
        "=r"((r)[4]),  "=r"((r)[5]),  "=r"((r)[6]),  "=r"((r)[7]), \
        "=r"((r)[8]),  "=r"((r)[9]),  "=r"((r)[10]), "=r"((r)[11]), \
        "=r"((r)[12]), "=r"((r)[13]), "=r"((r)[14]), "=r"((r)[15]) \
      : "r"(ta))

__device__ __forceinline__ uint64_t mkdesc(uint32_t addr) {
  return ((uint64_t)2 << 61) | ((uint64_t)1 << 46) | ((uint64_t)64 << 32) |
         ((uint64_t)1 << 16) | ((addr >> 4) & 0x3FFF);
}

__device__ __forceinline__ void mma_bf16(uint32_t d, uint64_t ad, uint64_t bd,
                                         uint32_t idesc, uint32_t en) {
  asm volatile(
      "{\n\t.reg .pred p;\n\tsetp.ne.u32 p, %5, 0;\n\t"
      "tcgen05.mma.cta_group::1.kind::f16 [%0], %1, %2, %3, {%4, %4, %4, %4}, p;\n\t}"
      :: "r"(d), "l"(ad), "l"(bd), "r"(idesc), "r"(0u), "r"(en) : "memory");
}
#endif  // HAS_TC

__device__ __forceinline__ void sts128u(uint32_t addr, uint32_t a, uint32_t b,
                                        uint32_t c, uint32_t d) {
  asm volatile("st.shared.v4.b32 [%0], {%1, %2, %3, %4};"
               :: "r"(addr), "r"(a), "r"(b), "r"(c), "r"(d) : "memory");
}
__device__ __forceinline__ void sts32u(uint32_t addr, uint32_t v) {
  asm volatile("st.shared.b32 [%0], %1;" :: "r"(addr), "r"(v) : "memory");
}
__device__ __forceinline__ float lds32f(uint32_t addr) {
  float v;
  asm volatile("ld.shared.b32 %0, [%1];" : "=f"(v) : "r"(addr));
  return v;
}
__device__ __forceinline__ uint32_t lds32u(uint32_t addr) {
  uint32_t v;
  asm volatile("ld.shared.b32 %0, [%1];" : "=r"(v) : "r"(addr));
  return v;
}

// ================= unified GEMM (128x128 tile, bf16x3, Kc=64, 1024 thr) =======
#define TCM 128
#define TCN 128
#define TCK 64
#define TC_TILE 16384
#define TC_STAGE (4 * TC_TILE)
#define SOFF_MBAR 16
#define SOFF_TAB 64            // im2col table, up to 2304 u32 (ends 9280)
#define SOFF_TILES 10240       // 1024-aligned
#define SMEM_TC (SOFF_TILES + 2 * TC_STAGE)
#define TCTHREADS 1024

__global__ void __launch_bounds__(TCTHREADS, 1) tc_gemm(
    const float* __restrict__ A, const float* __restrict__ Bm,
    const float* __restrict__ bias, float* __restrict__ C,
    int M, int N, int K, int relu,
    long long sA, long long sB, long long sBias, long long sC,
    const int* __restrict__ rowlist, const int* __restrict__ cnt,
    int conv_mode, int Cin, int Himg, int logW, int logHW,
    const float* __restrict__ gam, const float* __restrict__ bet) {
  extern __shared__ char smem[];
  const int z = blockIdx.z;
  const int Mz = cnt ? cnt[z] : M;
  const int m0 = blockIdx.y * TCM;
  if (m0 >= Mz) return;
  const int n0 = blockIdx.x * TCN;

  const float* Ab = A + (long long)z * sA;
  const float* Bb = Bm + (long long)z * sB;
  const float* biasb = bias + (long long)z * sBias;
  float* Cb = C + (long long)z * sC;
  const int* rl = rowlist ? rowlist + z * BATCH : (const int*)0;

  const int tid = threadIdx.x;
  const int wid = tid >> 5, lane = tid & 31;
  const uint32_t sbase = smem_u32(smem);

  // staging: thread -> (row = tid&127, 8-k eighth = (tid>>7)*8)
  const int srow = tid & 127;
  const int skq = (tid >> 7) * 8;
  long long aidx;
  {
    int gm = m0 + srow;
    int r_ = (gm < Mz) ? gm : 0;
    if (rl) r_ = (gm < Mz) ? rl[gm] : 0;
    aidx = (long long)r_ * K + skq;
  }

  // conv pixel coords for B staging
  int py = 0, px = 0;
  long long convbase = 0;
  if (conv_mode) {
    int gn = n0 + srow;
    int pb = gn >> logHW;
    int pos = gn & ((1 << logHW) - 1);
    py = pos >> logW;
    px = pos & ((1 << logW) - 1);
    convbase = ((long long)pb * Cin) << logHW;
  }

#if HAS_TC
  // ======================= tcgen05 bf16x3 path ================================
  if (wid == 0) TC_ALLOC(sbase, 128);
  if (tid == 0) { MB_INIT(sbase + SOFF_MBAR, 1); MB_INIT(sbase + SOFF_MBAR + 8, 1); }
  // im2col table: tab[k] = (ci << 4) | (ky << 2) | kx
  if (conv_mode) {
    for (int k = tid; k < K; k += TCTHREADS) {
      int ci = k / 9;
      int rr = k - ci * 9;
      int ky = rr / 3;
      int kx = rr - ky * 3;
      sts32u(sbase + SOFF_TAB + k * 4, ((uint32_t)ci << 4) | (ky << 2) | kx);
    }
  }
  __syncthreads();
  uint32_t tmem;
  asm volatile("ld.shared.b32 %0, [%1];" : "=r"(tmem) : "r"(sbase));

  const int nchunks = K / TCK;
  int phase0 = 0, phase1 = 0;
  const uint32_t idesc =
      (1u << 4) | (1u << 7) | (1u << 10) | ((TCN / 8) << 17) | ((TCM / 16) << 24);

  for (int c = 0; c < nchunks; c++) {
    const int s = c & 1;
    const uint32_t stg = sbase + SOFF_TILES + s * TC_STAGE;
    const uint32_t sAhi = stg, sAlo = stg + TC_TILE;
    const uint32_t sBhi = stg + 2 * TC_TILE, sBlo = stg + 3 * TC_TILE;
    if (c >= 2) {
      if (s == 0) { MB_WAIT(sbase + SOFF_MBAR, phase0); phase0 ^= 1; }
      else        { MB_WAIT(sbase + SOFF_MBAR + 8, phase1); phase1 ^= 1; }
    }
    const int k0 = c * TCK;

    // ---- stage A (row srow, k [skq, skq+8)) ----
    {
      const float* ap = Ab + aidx + k0;
      float4 t0 = *(const float4*)(ap);
      float4 t1 = *(const float4*)(ap + 4);
      uint32_t ha[4], la[4];
      bsplit2(t0.x, t0.y, ha[0], la[0]);
      bsplit2(t0.z, t0.w, ha[1], la[1]);
      bsplit2(t1.x, t1.y, ha[2], la[2]);
      bsplit2(t1.z, t1.w, ha[3], la[3]);
      const uint32_t off = SW128((uint32_t)(srow * 128 + skq * 2));
      sts128u(sAhi + off, ha[0], ha[1], ha[2], ha[3]);
      sts128u(sAlo + off, la[0], la[1], la[2], la[3]);
    }

    // ---- stage B (row srow = n or pixel, k [skq, skq+8)) ----
    {
      uint32_t hb[4], lb[4];
      if (!conv_mode) {
        const int nr = (n0 + srow < N) ? srow : 0;
        const float* bp = Bb + (long long)(k0 + skq) * N + n0 + nr;
#pragma unroll
        for (int i = 0; i < 8; i += 2) {
          float v0 = bp[(long long)i * N];
          float v1 = bp[(long long)(i + 1) * N];
          bsplit2(v0, v1, hb[i / 2], lb[i / 2]);
        }
      } else {
        const uint32_t tadr = sbase + SOFF_TAB + (uint32_t)(k0 + skq) * 4;
#pragma unroll
        for (int i = 0; i < 8; i += 2) {
          float v[2];
#pragma unroll
          for (int d = 0; d < 2; d++) {
            uint32_t t = lds32u(tadr + (i + d) * 4);
            int ci = t >> 4;
            int iy = py + (int)((t >> 2) & 3) - 1;
            int ix = px + (int)(t & 3) - 1;
            v[d] = 0.f;
            if ((unsigned)iy < (unsigned)Himg && (unsigned)ix < (unsigned)Himg)
              v[d] = Bb[convbase + ((long long)ci << logHW) + (iy << logW) + ix];
          }
          bsplit2(v[0], v[1], hb[i / 2], lb[i / 2]);
        }
      }
      const uint32_t off = SW128((uint32_t)(srow * 128 + skq * 2));
      sts128u(sBhi + off, hb[0], hb[1], hb[2], hb[3]);
      sts128u(sBlo + off, lb[0], lb[1], lb[2], lb[3]);
    }

    FENCE_ASYNC();
    __syncthreads();

    if (tid == 0) {
      uint64_t dAh = mkdesc(sAhi), dAl = mkdesc(sAlo);
      uint64_t dBh = mkdesc(sBhi), dBl = mkdesc(sBlo);
#pragma unroll
      for (int i = 0; i < 4; i++)
        mma_bf16(tmem, dAh + 2 * i, dBh + 2 * i, idesc, (c > 0) | (i > 0));
#pragma unroll
      for (int i = 0; i < 4; i++)
        mma_bf16(tmem, dAh + 2 * i, dBl + 2 * i, idesc, 1u);
#pragma unroll
      for (int i = 0; i < 4; i++)
        mma_bf16(tmem, dAl + 2 * i, dBh + 2 * i, idesc, 1u);
      TC_COMMIT(sbase + SOFF_MBAR + 8 * s);
    }
  }

  MB_WAIT(sbase + SOFF_MBAR, phase0);
  if (nchunks > 1) MB_WAIT(sbase + SOFF_MBAR + 8, phase1);
  TC_FENCE_AFTER();

  // ---- epilogue: warps 0-3 LDTM(x16)+transpose, then 32 warps store ----
  const uint32_t Tbase = sbase + SOFF_TILES;
  if (tid < 128) {
    const int m_loc = tid;
    const int m = m0 + m_loc;
    float sc = 0.f, cbv = 0.f, bev = 0.f;
    if (conv_mode) { sc = gam[m] * rsqrtf(1.00001f); cbv = biasb[m]; bev = bet[m]; }
#pragma unroll 1
    for (int h = 0; h < 8; h++) {
      uint32_t r[16];
      TC_LD_X16(r, tmem + h * 16);
      TC_WAIT_LD();
      int g = h >> 1;
      uint32_t Tg = Tbase + (uint32_t)g * (128 * 33 * 4) +
                    (uint32_t)((h & 1) * 16) * 4;
#pragma unroll
      for (int j = 0; j < 16; j++) {
        float v = __uint_as_float(r[j]);
        if (conv_mode) v = fmaxf((v + cbv) * sc + bev, 0.f);
        sts32u(Tg + (uint32_t)(m_loc * 33 + j) * 4, __float_as_uint(v));
      }
    }
    TC_FENCE_BEFORE();
  }
  __syncthreads();

  {
    const int g = wid & 3;          // col group (32 cols)
    const int mb = wid >> 2;        // row block (16 rows)
    const uint32_t Tg = Tbase + (uint32_t)g * (128 * 33 * 4);
    if (!conv_mode) {
      int n = n0 + g * 32 + lane;
      bool nok = (n < N);
      float bn = nok ? biasb[n] : 0.f;
#pragma unroll 4
      for (int rr = 0; rr < 16; rr++) {
        int mloc = mb * 16 + rr;
        int mm = m0 + mloc;
        float v = lds32f(Tg + (uint32_t)(mloc * 33 + lane) * 4);
        v += bn;
        if (relu) v = fmaxf(v, 0.f);
        if (nok && mm < Mz) Cb[(long long)mm * N + n] = v;
      }
    } else {
      const int HWm1 = (1 << logHW) - 1;
      const int W = 1 << logW;
      int pix = n0 + g * 32 + lane;
      int b = pix >> logHW;
      int pos = pix & HWm1;
      bool wsel = ((pos & 1) == 0) && (((pos >> logW) & 1) == 0);
      int poff = ((pos >> (logW + 1)) << (logW - 1)) + ((pos & (W - 1)) >> 1);
      long long obase = ((long long)b * M) << (logHW - 2);
#pragma unroll 4
      for (int rr = 0; rr < 16; rr++) {
        int mloc = mb * 16 + rr;
        int mm = m0 + mloc;
        float v = lds32f(Tg + (uint32_t)(mloc * 33 + lane) * 4);
        float vx = fmaxf(v, __shfl_xor_sync(0xffffffffu, v, 1));
        float vy = fmaxf(vx, __shfl_xor_sync(0xffffffffu, vx, W));
        if (wsel)
          Cb[obase + (((long long)mm) << (logHW - 2)) + poff] = vy;
      }
    }
  }
  __syncthreads();
  if (wid == 0) { TC_RELINQ(); TC_DEALLOC(tmem, 128); }

#else
  // ================== fallback: f32x2 scalar GEMM (same semantics) ===========
  float* Af = (float*)(smem + SOFF_TILES);     // [64][130]
  float* Bf = Af + 64 * 130;                   // [64][132]

  u64 acc[8];
#pragma unroll
  for (int j = 0; j < 8; j++) acc[j] = 0ull;

  const int tx = tid & 15, ty = tid >> 4;      // ty 0..63
  const int m2 = ty * 2, n8 = tx * 8;

  for (int k0 = 0; k0 < K; k0 += TCK) {
    {
      const float* ap = Ab + aidx + k0;
      float4 t0 = *(const float4*)(ap);
      float4 t1 = *(const float4*)(ap + 4);
      Af[(skq + 0) * 130 + srow] = t0.x;
      Af[(skq + 1) * 130 + srow] = t0.y;
      Af[(skq + 2) * 130 + srow] = t0.z;
      Af[(skq + 3) * 130 + srow] = t0.w;
      Af[(skq + 4) * 130 + srow] = t1.x;
      Af[(skq + 5) * 130 + srow] = t1.y;
      Af[(skq + 6) * 130 + srow] = t1.z;
      Af[(skq + 7) * 130 + srow] = t1.w;
    }
    if (!conv_mode) {
      const int nr = (n0 + srow < N) ? srow : 0;
      const float* bp = Bb + (long long)(k0 + skq) * N + n0 + nr;
      bool nok = (n0 + srow < N);
#pragma unroll
      for (int i = 0; i < 8; i++)
        Bf[(skq + i) * 132 + srow] = nok ? bp[(long long)i * N] : 0.f;
    } else {
#pragma unroll
      for (int i = 0; i < 8; i++) {
        int k = k0 + skq + i;
        int ci = k / 9;
        int rr = k - ci * 9;
        int ky = rr / 3;
        int kx = rr - ky * 3;
        int iy = py + ky - 1, ix = px + kx - 1;
        float v = 0.f;
        if ((unsigned)iy < (unsigned)Himg && (unsigned)ix < (unsigned)Himg)
          v = Bb[convbase + ((long long)ci << logHW) + (iy << logW) + ix];
        Bf[(skq + i) * 132 + srow] = v;
      }
    }
    __syncthreads();
#pragma unroll 4
    for (int kk = 0; kk < TCK; kk++) {
      u64 a = *(const u64*)&Af[kk * 130 + m2];
      float4 b40 = *(const float4*)&Bf[kk * 132 + n8];
      float4 b41 = *(const float4*)&Bf[kk * 132 + n8 + 4];
      u64 b[8];
      b[0] = dupf(b40.x); b[1] = dupf(b40.y); b[2] = dupf(b40.z); b[3] = dupf(b40.w);
      b[4] = dupf(b41.x); b[5] = dupf(b41.y); b[6] = dupf(b41.z); b[7] = dupf(b41.w);
#pragma unroll
      for (int j = 0; j < 8; j++) fma2(acc[j], a, b[j]);
    }
    __syncthreads();
  }

  if (!conv_mode) {
    int mlo = m0 + m2;
#pragma unroll
    for (int j = 0; j < 8; j++) {
      int n = n0 + n8 + j;
      if (n >= N) continue;
      float2 v = unp(acc[j]);
      float bsv = biasb[n];
      if (mlo < Mz) {
        float r = v.x + bsv;
        if (relu) r = fmaxf(r, 0.f);
        Cb[(long long)mlo * N + n] = r;
      }
      if (mlo + 1 < Mz) {
        float r = v.y + bsv;
        if (relu) r = fmaxf(r, 0.f);
        Cb[(long long)(mlo + 1) * N + n] = r;
      }
    }
  } else {
    float* T = (float*)(smem + SOFF_TILES);   // [128][132]
    const float rs = rsqrtf(1.00001f);
    {
      int gm = m0 + m2;
      float sc0 = gam[gm] * rs, cb0 = biasb[gm], be0 = bet[gm];
      float sc1 = gam[gm + 1] * rs, cb1v = biasb[gm + 1], be1v = bet[gm + 1];
#pragma unroll
      for (int j = 0; j < 8; j++) {
        float2 v = unp(acc[j]);
        T[m2 * 132 + n8 + j] = fmaxf((v.x + cb0) * sc0 + be0, 0.f);
        T[(m2 + 1) * 132 + n8 + j] = fmaxf((v.y + cb1v) * sc1 + be1v, 0.f);
      }
    }
    __syncthreads();
    const int HWm1 = (1 << logHW) - 1;
    const int W = 1 << logW;
    const int g = wid & 3, mb = wid >> 2;
    int pix = n0 + g * 32 + lane;
    int b = pix >> logHW;
    int pos = pix & HWm1;
    bool wsel = ((pos & 1) == 0) && (((pos >> logW) & 1) == 0);
    int poff = ((pos >> (logW + 1)) << (logW - 1)) + ((pos & (W - 1)) >> 1);
    long long obase = ((long long)b * M) << (logHW - 2);
    for (int rr = 0; rr < 16; rr++) {
      int mloc = mb * 16 + rr;
      float v = T[mloc * 132 + g * 32 + lane];
      float vx = fmaxf(v, __shfl_xor_sync(0xffffffffu, v, 1));
      float vy = fmaxf(vx, __shfl_xor_sync(0xffffffffu, vx, W));
      if (wsel)
        Cb[obase + (((long long)(m0 + mloc)) << (logHW - 2)) + poff] = vy;
    }
  }
#endif
}

// =================== dense GEMM 128x64x16, f32x2 (small N only) ===============
#define DBM 128
#define DBN 64
#define DBK 16

__global__ __launch_bounds__(256) void gemm_f2(
    const float* __restrict__ A, const float* __restrict__ B,
    const float* __restrict__ bias, float* __restrict__ C,
    int M, int N, int K, int relu) {
  const int n0 = blockIdx.x * DBN;
  const int m0 = blockIdx.y * DBM;

  __shared__ float As[DBK][DBM + 2];
  __shared__ float Bs[DBK][DBN + 4];

  u64 acc[4][4];
#pragma unroll
  for (int p = 0; p < 4; p++)
#pragma unroll
    for (int j = 0; j < 4; j++) acc[p][j] = 0ull;

  const int tid = threadIdx.x;
  const int tx = tid & 15, ty = tid >> 4;

  int rowA[2], kqA[2];
  size_t abase[2];
#pragma unroll
  for (int i = 0; i < 2; i++) {
    int v = tid + i * 256;
    rowA[i] = v >> 2;
    kqA[i] = v & 3;
    abase[i] = (size_t)(m0 + rowA[i]) * K + kqA[i] * 4;
  }
  const int kb = tid >> 4, nb = (tid & 15) * 4;

  for (int k0 = 0; k0 < K; k0 += DBK) {
#pragma unroll
    for (int i = 0; i < 2; i++) {
      float4 a4 = *(const float4*)&A[abase[i] + k0];
      int kk = kqA[i] * 4;
      As[kk + 0][rowA[i]] = a4.x;
      As[kk + 1][rowA[i]] = a4.y;
      As[kk + 2][rowA[i]] = a4.z;
      As[kk + 3][rowA[i]] = a4.w;
    }
    {
      float4 b4;
      size_t bo = (size_t)(k0 + kb) * N + n0 + nb;
      if (n0 + nb + 3 < N) {
        b4 = *(const float4*)&B[bo];
      } else {
        b4.x = (n0 + nb + 0 < N) ? B[bo + 0] : 0.f;
        b4.y = (n0 + nb + 1 < N) ? B[bo + 1] : 0.f;
        b4.z = (n0 + nb + 2 < N) ? B[bo + 2] : 0.f;
        b4.w = (n0 + nb + 3 < N) ? B[bo + 3] : 0.f;
      }
      *(float4*)&Bs[kb][nb] = b4;
    }
    __syncthreads();
#pragma unroll
    for (int kk = 0; kk < DBK; kk++) {
      const u64* arow = (const u64*)&As[kk][0];
      u64 a0 = arow[ty * 4 + 0], a1 = arow[ty * 4 + 1];
      u64 a2 = arow[ty * 4 + 2], a3 = arow[ty * 4 + 3];
      float4 b4 = *(const float4*)&Bs[kk][tx * 4];
      u64 b0 = dupf(b4.x), b1 = dupf(b4.y), b2 = dupf(b4.z), b3 = dupf(b4.w);
      fma2(acc[0][0], a0, b0); fma2(acc[0][1], a0, b1);
      fma2(acc[0][2], a0, b2); fma2(acc[0][3], a0, b3);
      fma2(acc[1][0], a1, b0); fma2(acc[1][1], a1, b1);
      fma2(acc[1][2], a1, b2); fma2(acc[1][3], a1, b3);
      fma2(acc[2][0], a2, b0); fma2(acc[2][1], a2, b1);
      fma2(acc[2][2], a2, b2); fma2(acc[2][3], a2, b3);
      fma2(acc[3][0], a3, b0); fma2(acc[3][1], a3, b1);
      fma2(acc[3][2], a3, b2); fma2(acc[3][3], a3, b3);
    }
    __syncthreads();
  }

#pragma unroll
  for (int p = 0; p < 4; p++) {
    int mlo = m0 + ty * 8 + 2 * p;
#pragma unroll
    for (int j = 0; j < 4; j++) {
      int n = n0 + tx * 4 + j;
      if (n >= N) continue;
      float2 v = unp(acc[p][j]);
      float bsv = bias[n];
      if (mlo < M) {
        float r = v.x + bsv;
        if (relu) r = fmaxf(r, 0.f);
        C[(size_t)mlo * N + n] = r;
      }
      if (mlo + 1 < M) {
        float r = v.y + bsv;
        if (relu) r = fmaxf(r, 0.f);
        C[(size_t)(mlo + 1) * N + n] = r;
      }
    }
  }
}

// ==== implicit-im2col conv1 + bias/BN/ReLU + FUSED 2x2 maxpool (scalar) =======
#define CBM 64
#define CBN 128
#define CBK 16

__global__ __launch_bounds__(256) void conv_f2(
    const float* __restrict__ in, const float* __restrict__ w,
    const float* __restrict__ cb, const float* __restrict__ gam,
    const float* __restrict__ bet, float* __restrict__ out,
    int Cin, int Cout, int H, int logW, int logHW) {
  const int HW = 1 << logHW;
  const int W = 1 << logW;
  const int Ktot = Cin * 9;
  const int n0 = blockIdx.x * CBN;
  const int m0 = blockIdx.y * CBM;

  __shared__ float As[CBK][CBM + 2];
  __shared__ float Bs[CBK][CBN + 4];

  u64 acc[4][4];
#pragma unroll
  for (int p = 0; p < 4; p++)
#pragma unroll
    for (int j = 0; j < 4; j++) acc[p][j] = 0ull;

  const int tid = threadIdx.x;
  const int tx = tid & 31, ty = tid >> 5;
  const int kB = tid >> 4, nb8 = (tid & 15) * 8;

  for (int k0 = 0; k0 < Ktot; k0 += CBK) {
#pragma unroll
    for (int i = 0; i < 4; i++) {
      int l = tid + i * 256;
      int k = l & 15, m = l >> 4;
      int gk = k0 + k;
      As[k][m] = (gk < Ktot) ? w[(m0 + m) * Ktot + gk] : 0.f;
    }
    {
      int gk = k0 + kB;
      int ci = 0, ky = 0, kx = 0;
      bool kvalid = gk < Ktot;
      if (kvalid) {
        ci = gk / 9;
        int r = gk - ci * 9;
        ky = r / 3;
        kx = r - ky * 3;
      }
      const float* inp = in + (size_t)ci * HW;
#pragma unroll
      for (int jj = 0; jj < 8; jj++) {
        int gn = n0 + nb8 + jj;
        float v = 0.f;
        if (kvalid) {
          int b = gn >> logHW;
          int pos = gn & (HW - 1);
          int y = pos >> logW, x = pos & (W - 1);
          int iy = y + ky - 1, ix = x + kx - 1;
          if ((unsigned)iy < (unsigned)H && (unsigned)ix < (unsigned)H)
            v = inp[((size_t)b * Cin << logHW) + (iy << logW) + ix];
        }
        Bs[kB][nb8 + jj] = v;
      }
    }
    __syncthreads();
#pragma unroll
    for (int kk = 0; kk < CBK; kk++) {
      const u64* arow = (const u64*)&As[kk][0];
      u64 a0 = arow[ty * 4 + 0], a1 = arow[ty * 4 + 1];
      u64 a2 = arow[ty * 4 + 2], a3 = arow[ty * 4 + 3];
      float4 b4 = *(const float4*)&Bs[kk][tx * 4];
      u64 b0 = dupf(b4.x), b1 = dupf(b4.y), b2 = dupf(b4.z), b3 = dupf(b4.w);
      fma2(acc[0][0], a0, b0); fma2(acc[0][1], a0, b1);
      fma2(acc[0][2], a0, b2); fma2(acc[0][3], a0, b3);
      fma2(acc[1][0], a1, b0); fma2(acc[1][1], a1, b1);
      fma2(acc[1][2], a1, b2); fma2(acc[1][3], a1, b3);
      fma2(acc[2][0], a2, b0); fma2(acc[2][1], a2, b1);
      fma2(acc[2][2], a2, b2); fma2(acc[2][3], a2, b3);
      fma2(acc[3][0], a3, b0); fma2(acc[3][1], a3, b1);
      fma2(acc[3][2], a3, b2); fma2(acc[3][3], a3, b3);
    }
    __syncthreads();
  }

  // ---- epilogue: BN+ReLU then fused 2x2 maxpool; output POOLED NCHW ----
  const float rs = rsqrtf(1.00001f);
  const int W2 = W >> 1;
  const int xsh = W >> 2;  // shfl distance for y-pair
  int gn0 = n0 + tx * 4;
  int b = gn0 >> logHW;
  int pos = gn0 & (HW - 1);
  int yg = pos >> logW;
  bool wsel = (yg & 1) == 0;
  int py = yg >> 1;
  int px0 = (pos & (W - 1)) >> 1;
  long long obase = ((long long)b * Cout) << (logHW - 2);
#pragma unroll
  for (int p = 0; p < 4; p++) {
    int mlo = m0 + ty * 8 + 2 * p;
    float sc0 = gam[mlo] * rs, cb0 = cb[mlo], be0 = bet[mlo];
    float sc1 = gam[mlo + 1] * rs, cb1v = cb[mlo + 1], be1v = bet[mlo + 1];
    float r0[4], r1[4];
#pragma unroll
    for (int j = 0; j < 4; j++) {
      float2 v = unp(acc[p][j]);
      r0[j] = fmaxf((v.x + cb0) * sc0 + be0, 0.f);
      r1[j] = fmaxf((v.y + cb1v) * sc1 + be1v, 0.f);
    }
    float a00 = fmaxf(r0[0], r0[1]), a01 = fmaxf(r0[2], r0[3]);
    float a10 = fmaxf(r1[0], r1[1]), a11 = fmaxf(r1[2], r1[3]);
    a00 = fmaxf(a00, __shfl_xor_sync(0xffffffffu, a00, xsh));
    a01 = fmaxf(a01, __shfl_xor_sync(0xffffffffu, a01, xsh));
    a10 = fmaxf(a10, __shfl_xor_sync(0xffffffffu, a10, xsh));
    a11 = fmaxf(a11, __shfl_xor_sync(0xffffffffu, a11, xsh));
    if (wsel) {
      long long o0 = obase + (((long long)mlo) << (logHW - 2)) + py * W2 + px0;
      long long o1 = obase + (((long long)(mlo + 1)) << (logHW - 2)) + py * W2 + px0;
      out[o0] = a00;
      out[o0 + 1] = a01;
      out[o1] = a10;
      out[o1 + 1] = a11;
    }
  }
}

// ---------------- noisy top-k gating (per row) ----------------
__global__ void gating_kernel(const float* __restrict__ clean,
                              const float* __restrict__ rawstd,
                              const float* __restrict__ noise,
                              float* __restrict__ gates, float* __restrict__ prob) {
  int b = blockIdx.x * blockDim.x + threadIdx.x;
  if (b >= BATCH) return;
  float c[NEXP], sd[NEXP], nz[NEXP];
#pragma unroll
  for (int e = 0; e < NEXP; e++) {
    c[e] = clean[b * NEXP + e];
    float rsv = rawstd[b * NEXP + e];
    float sp = (rsv > 20.f) ? rsv : log1pf(expf(rsv));
    sd[e] = sp + 0.01f;
    nz[e] = c[e] + noise[b * NEXP + e] * sd[e];
  }
  int i0 = 0; float v0 = nz[0];
#pragma unroll
  for (int e = 1; e < NEXP; e++) if (nz[e] > v0) { v0 = nz[e]; i0 = e; }
  int i1 = -1; float v1 = -1e30f;
#pragma unroll
  for (int e = 0; e < NEXP; e++) if (e != i0 && nz[e] > v1) { v1 = nz[e]; i1 = e; }
  float v2 = -1e30f;
#pragma unroll
  for (int e = 0; e < NEXP; e++) if (e != i0 && e != i1 && nz[e] > v2) v2 = nz[e];

  float e1 = expf(v1 - v0);
  float inv = 1.f / (1.f + e1);
  const float kInvSqrt2 = 0.70710678118654752440f;
#pragma unroll
  for (int e = 0; e < NEXP; e++) {
    float g = (e == i0) ? inv : ((e == i1) ? e1 * inv : 0.f);
    gates[b * NEXP + e] = g;
    float th = (nz[e] > v2) ? v2 : v1;
    float zz = (c[e] - th) / sd[e];
    prob[b * NEXP + e] = 0.5f * (1.f + erff(zz * kInvSqrt2));
  }
}

// -------- deterministic dispatch build (1 block, warp per expert) --------
__global__ void build_dispatch(const float* __restrict__ gates,
                               int* __restrict__ rowlist, int* __restrict__ cnt,
                               int* __restrict__ rowslot,
                               float* __restrict__ slotgate) {
  int w = threadIdx.x >> 5;
  int lane = threadIdx.x & 31;
  int c = 0;
  for (int base = 0; base < BATCH; base += 32) {
    int b = base + lane;
    float g = gates[b * NEXP + w];
    unsigned mask = __ballot_sync(0xffffffffu, g > 0.f);
    if (g > 0.f) {
      int pos = c + __popc(mask & ((1u << lane) - 1u));
      int slot = w * BATCH + pos;
      rowlist[slot] = b;
      slotgate[slot] = g;
      int m8 = 0;
#pragma unroll
      for (int e = 0; e < NEXP; e++) m8 |= (gates[b * NEXP + e] > 0.f) ? (1 << e) : 0;
      int j = __popc(m8 & ((1 << w) - 1));
      rowslot[b * 2 + j] = slot;
    }
    c += __popc(mask);
  }
  if (lane == 0) cnt[w] = c;
}

// ---------------- deterministic per-expert reductions ----------------
__global__ void moe_reduce_kernel(const float* __restrict__ gates,
                                  const float* __restrict__ prob,
                                  float* __restrict__ imp, float* __restrict__ loadv) {
  int e = blockIdx.x;
  int t = threadIdx.x;
  __shared__ float s1[256], s2[256];
  float a = 0.f, b = 0.f;
  for (int i = t; i < BATCH; i += 256) {
    a += gates[i * NEXP + e];
    b += prob[i * NEXP + e];
  }
  s1[t] = a; s2[t] = b;
  __syncthreads();
  for (int s = 128; s > 0; s >>= 1) {
    if (t < s) { s1[t] += s1[t + s]; s2[t] += s2[t + s]; }
    __syncthreads();
  }
  if (t == 0) { imp[e] = s1[0]; loadv[e] = s2[0]; }
}

__global__ void loss_kernel(const float* __restrict__ imp,
                            const float* __restrict__ loadv,
                            float* __restrict__ out) {
  float m1 = 0.f, m2 = 0.f;
  for (int e = 0; e < NEXP; e++) { m1 += imp[e]; m2 += loadv[e]; }
  m1 *= 0.125f; m2 *= 0.125f;
  float v1 = 0.f, v2 = 0.f;
  for (int e = 0; e < NEXP; e++) {
    float d1 = imp[e] - m1; v1 += d1 * d1;
    float d2 = loadv[e] - m2; v2 += d2 * d2;
  }
  v1 /= 7.f; v2 /= 7.f;
  out[0] = v1 / (m1 * m1 + 1e-10f) + v2 / (m2 * m2 + 1e-10f);
}

// ------------- slot-based combine: y[b,c] = g0*eo[s0,c]+g1*eo[s1,c] ----------
__global__ void combine2_kernel(const int* __restrict__ rowslot,
                                const float* __restrict__ slotgate,
                                const float* __restrict__ eo,
                                float* __restrict__ y) {
  int idx = blockIdx.x * blockDim.x + threadIdx.x;
  if (idx >= BATCH * NCLS) return;
  int b = idx / NCLS;
  int c = idx - b * NCLS;
  int s0 = rowslot[b * 2 + 0], s1 = rowslot[b * 2 + 1];
  y[idx] = slotgate[s0] * eo[(size_t)s0 * NCLS + c] +
           slotgate[s1] * eo[(size_t)s1 * NCLS + c];
}

// ================================ launch ======================================
extern "C" void kernel_launch(void* const* d_in, const int* in_sizes, int n_in,
                              void* d_out, int out_size) {
  const float* x    = (const float*)d_in[0];
  const float* noise= (const float*)d_in[1];
  const float* cw1 = (const float*)d_in[2],  *cb1 = (const float*)d_in[3];
  const float* g1  = (const float*)d_in[4],  *be1 = (const float*)d_in[5];
  const float* cw2 = (const float*)d_in[6],  *cb2 = (const float*)d_in[7];
  const float* g2  = (const float*)d_in[8],  *be2 = (const float*)d_in[9];
  const float* cw3 = (const float*)d_in[10], *cb3 = (const float*)d_in[11];
  const float* g3  = (const float*)d_in[12], *be3 = (const float*)d_in[13];
  const float* cw4 = (const float*)d_in[14], *cb4 = (const float*)d_in[15];
  const float* g4  = (const float*)d_in[16], *be4 = (const float*)d_in[17];
  const float* wg1 = (const float*)d_in[18], *wg1b= (const float*)d_in[19];
  const float* wg2 = (const float*)d_in[20], *wg2b= (const float*)d_in[21];
  const float* wn1 = (const float*)d_in[22], *wn1b= (const float*)d_in[23];
  const float* wn2 = (const float*)d_in[24], *wn2b= (const float*)d_in[25];
  const float* eW1 = (const float*)d_in[26], *eb1 = (const float*)d_in[27];
  const float* eW2 = (const float*)d_in[28], *eb2 = (const float*)d_in[29];
  const float* eW3 = (const float*)d_in[30], *eb3 = (const float*)d_in[31];

  float *poolA, *poolB, *hid, *clean, *rawstd, *gates, *prob;
  float *eh, *eh2, *eo, *imp, *loadv, *slotgate;
  int *rowlist, *cnt, *rowslot;
  cudaGetSymbolAddress((void**)&poolA, g_poolA);
  cudaGetSymbolAddress((void**)&poolB, g_poolB);
  cudaGetSymbolAddress((void**)&hid, g_hid);
  cudaGetSymbolAddress((void**)&clean, g_clean);
  cudaGetSymbolAddress((void**)&rawstd, g_rawstd);
  cudaGetSymbolAddress((void**)&gates, g_gates);
  cudaGetSymbolAddress((void**)&prob, g_prob);
  cudaGetSymbolAddress((void**)&eh, g_eh);
  cudaGetSymbolAddress((void**)&eh2, g_eh2);
  cudaGetSymbolAddress((void**)&eo, g_eo);
  cudaGetSymbolAddress((void**)&imp, g_imp);
  cudaGetSymbolAddress((void**)&loadv, g_load);
  cudaGetSymbolAddress((void**)&rowlist, g_rowlist);
  cudaGetSymbolAddress((void**)&cnt, g_cnt);
  cudaGetSymbolAddress((void**)&rowslot, g_rowslot);
  cudaGetSymbolAddress((void**)&slotgate, g_slotgate);

  float* out = (float*)d_out;

  cudaFuncSetAttribute(tc_gemm, cudaFuncAttributeMaxDynamicSharedMemorySize, SMEM_TC);

  // ---- conv1 (scalar, pool fused) -> poolA [2048,64,16,16] ----
  conv_f2<<<dim3(BATCH * 1024 / CBN, 1), 256>>>(x, cw1, cb1, g1, be1, poolA, 3, 64, 32, 5, 10);

  // ---- conv2-4 (tc_gemm bf16x3, pool fused) ----
  tc_gemm<<<dim3(BATCH * 256 / TCN, 1, 1), TCTHREADS, SMEM_TC>>>(
      cw2, poolA, cb2, poolB, 128, BATCH * 256, 576, 1,
      0, 0, 0, 0, 0, 0, 1, 64, 16, 4, 8, g2, be2);

  tc_gemm<<<dim3(BATCH * 64 / TCN, 2, 1), TCTHREADS, SMEM_TC>>>(
      cw3, poolB, cb3, poolA, 256, BATCH * 64, 1152, 1,
      0, 0, 0, 0, 0, 0, 1, 128, 8, 3, 6, g3, be3);

  tc_gemm<<<dim3(BATCH * 16 / TCN, 4, 1), TCTHREADS, SMEM_TC>>>(
      cw4, poolA, cb4, poolB, 512, BATCH * 16, 2304, 1,
      0, 0, 0, 0, 0, 0, 1, 256, 4, 2, 4, g4, be4);

  const float* f = poolB;  // [2048, 2048]

  // ---- gating nets ----
  tc_gemm<<<dim3(GATEH / TCN, BATCH / TCM, 1), TCTHREADS, SMEM_TC>>>(
      f, wg1, wg1b, hid, BATCH, GATEH, FEAT, 1,
      0, 0, 0, 0, 0, 0, 0, 0, 0, 0, 0, 0, 0);
  gemm_f2<<<dim3(1, BATCH / DBM, 1), 256>>>(hid, wg2, wg2b, clean, BATCH, NEXP, GATEH, 0);
  tc_gemm<<<dim3(GATEH / TCN, BATCH / TCM, 1), TCTHREADS, SMEM_TC>>>(
      f, wn1, wn1b, hid, BATCH, GATEH, FEAT, 1,
      0, 0, 0, 0, 0, 0, 0, 0, 0, 0, 0, 0, 0);
  gemm_f2<<<dim3(1, BATCH / DBM, 1), 256>>>(hid, wn2, wn2b, rawstd, BATCH, NEXP, GATEH, 0);

  gating_kernel<<<BATCH / 256, 256>>>(clean, rawstd, noise, gates, prob);
  build_dispatch<<<1, 256>>>(gates, rowlist, cnt, rowslot, slotgate);
  moe_reduce_kernel<<<NEXP, 256>>>(gates, prob, imp, loadv);

  // ---- sparse experts ----
  tc_gemm<<<dim3(HID / TCN, BATCH / TCM, NEXP), TCTHREADS, SMEM_TC>>>(
      f, eW1, eb1, eh, BATCH, HID, FEAT, 1,
      0, (long long)FEAT * HID, HID, (long long)BATCH * HID,
      rowlist, cnt, 0, 0, 0, 0, 0, 0, 0);
  tc_gemm<<<dim3((HID / 2) / TCN, BATCH / TCM, NEXP), TCTHREADS, SMEM_TC>>>(
      eh, eW2, eb2, eh2, BATCH, HID / 2, HID, 1,
      (long long)BATCH * HID, (long long)HID * (HID / 2), HID / 2,
      (long long)BATCH * (HID / 2), 0, cnt, 0, 0, 0, 0, 0, 0, 0);
  tc_gemm<<<dim3(1, BATCH / TCM, NEXP), TCTHREADS, SMEM_TC>>>(
      eh2, eW3, eb3, eo, BATCH, NCLS, HID / 2, 0,
      (long long)BATCH * (HID / 2), (long long)(HID / 2) * NCLS, NCLS,
      (long long)BATCH * NCLS, 0, cnt, 0, 0, 0, 0, 0, 0, 0);

  // ---- outputs ----
  combine2_kernel<<<(BATCH * NCLS + 255) / 256, 256>>>(rowslot, slotgate, eo, out);
  if (out_size >= BATCH * NCLS + 1)
    loss_kernel<<<1, 1>>>(imp, loadv, out + BATCH * NCLS);
}